// round 1
// baseline (speedup 1.0000x reference)
#include <cuda_runtime.h>

// ---------------------------------------------------------------------------
// HGT forward, fp32. Node layout: stmt rows [0,100000), func rows [100000,150000).
// ---------------------------------------------------------------------------
constexpr int kNStmt = 100000;
constexpr int kNFunc = 50000;
constexpr int kNTot  = 150000;
constexpr int kC = 128;
constexpr int kH = 8;
constexpr int kD = 16;
constexpr int kE = 200000;
constexpr int kL = 2;
constexpr int kT = 16;

// Scratch (device globals: no allocation allowed)
__device__ float g_e  [(size_t)kNTot * kC];
__device__ float g_x  [(size_t)kNTot * kC];
__device__ float g_k  [(size_t)kNTot * kC];
__device__ float g_q  [(size_t)kNTot * kC];
__device__ float g_v  [(size_t)kNTot * kC];
__device__ float g_agg[(size_t)kNTot * kC];
__device__ float g_kr [(size_t)kNStmt * kC];
__device__ float g_vr [(size_t)kNStmt * kC];
__device__ float g_logit [(size_t)kE * kH];
__device__ float g_segmax[(size_t)kNStmt * kH];
__device__ float g_segsum[(size_t)kNStmt * kH];

// ---------------------------------------------------------------------------
// Embedding: e[n,c] = relu(mean_t emb[tok[n,t], c])
// ---------------------------------------------------------------------------
__global__ void embed_kernel(const int* __restrict__ tok_s, const int* __restrict__ tok_f,
                             const float* __restrict__ emb, float* __restrict__ out) {
    int n = blockIdx.x;
    int c = threadIdx.x;
    const int* tok = (n < kNStmt) ? (tok_s + (size_t)n * kT)
                                  : (tok_f + (size_t)(n - kNStmt) * kT);
    float acc = 0.f;
#pragma unroll
    for (int i = 0; i < kT; ++i) {
        int t = __ldg(&tok[i]);
        acc += __ldg(&emb[(size_t)t * kC + c]);
    }
    acc *= (1.f / 16.f);
    out[(size_t)n * kC + c] = fmaxf(acc, 0.f);
}

// ---------------------------------------------------------------------------
// GEMM: Out[n,j] = post( pre(A)[n,:] @ W[:,j] + bias[j] )
// PRE:  0=none, 1=tanh-gelu
// POST: 0=none, 1=relu, 2=skip blend: g*val + (1-g)*Xold, g = sigmoid(*skipp)
// 64-row tiles, 256 threads, packed f32x2 FMAs (full fp32 rate on B300).
// ---------------------------------------------------------------------------
constexpr int GEMM_SMEM = (128 * 130 + 64 * 129) * 4;

template<int PRE, int POST>
__global__ void __launch_bounds__(256) gemm128(
        const float* __restrict__ A, const float* __restrict__ W,
        const float* __restrict__ bias, const float* __restrict__ Xold,
        const float* __restrict__ skipp, float* __restrict__ Out, int N)
{
    extern __shared__ float sm[];
    float* Ws = sm;              // [128][130] padded
    float* As = sm + 128 * 130;  // [64][129] padded
    int tid = threadIdx.x;
    int rowBase = blockIdx.x * 64;

    for (int idx = tid; idx < 128 * 128; idx += 256)
        Ws[(idx >> 7) * 130 + (idx & 127)] = W[idx];
    for (int idx = tid; idx < 64 * 128; idx += 256) {
        int r = idx >> 7, c = idx & 127;
        int n = rowBase + r;
        float v = (n < N) ? A[(size_t)n * 128 + c] : 0.f;
        if (PRE == 1) {
            float u = v;
            v = 0.5f * u * (1.f + tanhf(0.7978845608028654f * (u + 0.044715f * u * u * u)));
        }
        As[r * 129 + c] = v;
    }
    __syncthreads();

    int tx = tid & 15, ty = tid >> 4;
    int j0 = tx * 8, r0 = ty * 4;
    unsigned long long acc[4][4];
#pragma unroll
    for (int a = 0; a < 4; ++a)
#pragma unroll
        for (int b = 0; b < 4; ++b) acc[a][b] = 0ull;

#pragma unroll 4
    for (int i = 0; i < 128; ++i) {
        unsigned long long w0 = *(const unsigned long long*)(Ws + i * 130 + j0);
        unsigned long long w1 = *(const unsigned long long*)(Ws + i * 130 + j0 + 2);
        unsigned long long w2 = *(const unsigned long long*)(Ws + i * 130 + j0 + 4);
        unsigned long long w3 = *(const unsigned long long*)(Ws + i * 130 + j0 + 6);
#pragma unroll
        for (int rr = 0; rr < 4; ++rr) {
            unsigned int ab = __float_as_uint(As[(r0 + rr) * 129 + i]);
            unsigned long long a2;
            asm("mov.b64 %0, {%1, %1};" : "=l"(a2) : "r"(ab));
            asm("fma.rn.f32x2 %0, %1, %2, %0;" : "+l"(acc[rr][0]) : "l"(a2), "l"(w0));
            asm("fma.rn.f32x2 %0, %1, %2, %0;" : "+l"(acc[rr][1]) : "l"(a2), "l"(w1));
            asm("fma.rn.f32x2 %0, %1, %2, %0;" : "+l"(acc[rr][2]) : "l"(a2), "l"(w2));
            asm("fma.rn.f32x2 %0, %1, %2, %0;" : "+l"(acc[rr][3]) : "l"(a2), "l"(w3));
        }
    }

    float gate = 1.f, og = 0.f;
    if (POST == 2) {
        float sv = __ldg(skipp);
        gate = 1.f / (1.f + expf(-sv));
        og = 1.f - gate;
    }
    float b8[8];
#pragma unroll
    for (int j = 0; j < 8; ++j) b8[j] = __ldg(&bias[j0 + j]);

#pragma unroll
    for (int rr = 0; rr < 4; ++rr) {
        int n = rowBase + r0 + rr;
        if (n >= N) continue;
        float o[8];
#pragma unroll
        for (int jj = 0; jj < 4; ++jj) {
            float lo, hi;
            asm("mov.b64 {%0, %1}, %2;" : "=f"(lo), "=f"(hi) : "l"(acc[rr][jj]));
            o[2 * jj]     = lo + b8[2 * jj];
            o[2 * jj + 1] = hi + b8[2 * jj + 1];
        }
        if (POST == 1) {
#pragma unroll
            for (int j = 0; j < 8; ++j) o[j] = fmaxf(o[j], 0.f);
        }
        if (POST == 2) {
            const float4* xo = (const float4*)(Xold + (size_t)n * 128 + j0);
            float4 x0 = __ldg(&xo[0]), x1 = __ldg(&xo[1]);
            o[0] = gate * o[0] + og * x0.x; o[1] = gate * o[1] + og * x0.y;
            o[2] = gate * o[2] + og * x0.z; o[3] = gate * o[3] + og * x0.w;
            o[4] = gate * o[4] + og * x1.x; o[5] = gate * o[5] + og * x1.y;
            o[6] = gate * o[6] + og * x1.z; o[7] = gate * o[7] + og * x1.w;
        }
        float4* op = (float4*)(Out + (size_t)n * 128 + j0);
        op[0] = make_float4(o[0], o[1], o[2], o[3]);
        op[1] = make_float4(o[4], o[5], o[6], o[7]);
    }
}

// ---------------------------------------------------------------------------
// Per-head relation transform: out[n, h*16+e] = sum_d in[n, h*16+d] * A[h,d,e]
// ---------------------------------------------------------------------------
__global__ void __launch_bounds__(256) rel_transform(
        const float* __restrict__ in, const float* __restrict__ A,
        float* __restrict__ out, int Nsrc)
{
    __shared__ float As[8 * 16 * 17];   // padded [h][d][e]
    __shared__ float row[2][128];
    int tid = threadIdx.x;
    for (int idx = tid; idx < 8 * 16 * 16; idx += 256) {
        int h = idx >> 8, d = (idx >> 4) & 15, e = idx & 15;
        As[h * 272 + d * 17 + e] = __ldg(&A[idx]);
    }
    __syncthreads();
    int base = blockIdx.x * 16;
    int half = tid >> 7;
    int c = tid & 127;
    int h = c >> 4, e = c & 15;
    for (int it = 0; it < 8; ++it) {
        int n = base + it * 2 + half;
        float v = 0.f;
        if (n < Nsrc) v = in[(size_t)n * kC + c];
        row[half][c] = v;
        __syncthreads();
        float acc = 0.f;
#pragma unroll
        for (int d = 0; d < 16; ++d)
            acc += row[half][h * 16 + d] * As[h * 272 + d * 17 + e];
        if (n < Nsrc) out[(size_t)n * kC + c] = acc;
        __syncthreads();
    }
}

// ---------------------------------------------------------------------------
// Edge-phase kernels
// ---------------------------------------------------------------------------
__global__ void seg_init(unsigned int* __restrict__ smax, float* __restrict__ ssum, int n) {
    int i = blockIdx.x * 256 + threadIdx.x;
    if (i < n) { smax[i] = 0xFF800000u; ssum[i] = 0.f; }   // -inf, 0
}

__global__ void zero_kernel(float4* __restrict__ p, int n4) {
    int i = blockIdx.x * 256 + threadIdx.x;
    if (i < n4) p[i] = make_float4(0.f, 0.f, 0.f, 0.f);
}

__device__ __forceinline__ void atomicMaxFloat(float* addr, float v) {
    unsigned int u = __float_as_uint(v);
    if (u >> 31) atomicMin((unsigned int*)addr, u);     // negative (incl. -0)
    else         atomicMax((int*)addr, (int)u);         // non-negative
}

__global__ void edge_logits(const int* __restrict__ src, const int* __restrict__ dst,
                            const float* __restrict__ q, const float* __restrict__ kr,
                            const float* __restrict__ prel, float* __restrict__ logit,
                            float* __restrict__ smax) {
    int idx = blockIdx.x * 256 + threadIdx.x;
    if (idx >= kE * kH) return;
    int e = idx >> 3, h = idx & 7;
    int s = __ldg(&src[e]), dn = __ldg(&dst[e]);
    const float4* qp = (const float4*)(q  + (size_t)dn * kC + h * kD);
    const float4* kp = (const float4*)(kr + (size_t)s  * kC + h * kD);
    float acc = 0.f;
#pragma unroll
    for (int i = 0; i < 4; ++i) {
        float4 a = __ldg(&qp[i]);
        float4 b = __ldg(&kp[i]);
        acc += a.x * b.x + a.y * b.y + a.z * b.z + a.w * b.w;
    }
    float lg = acc * __ldg(&prel[h]) * 0.25f;   // scale = 1/sqrt(16)
    logit[idx] = lg;
    atomicMaxFloat(&smax[(size_t)dn * kH + h], lg);
}

__global__ void edge_expsum(const int* __restrict__ dst, float* __restrict__ logit,
                            const float* __restrict__ smax, float* __restrict__ ssum) {
    int idx = blockIdx.x * 256 + threadIdx.x;
    if (idx >= kE * kH) return;
    int e = idx >> 3, h = idx & 7;
    int dn = __ldg(&dst[e]);
    float v = expf(logit[idx] - __ldg(&smax[(size_t)dn * kH + h]));
    logit[idx] = v;
    atomicAdd(&ssum[(size_t)dn * kH + h], v);
}

__global__ void edge_scatter(const int* __restrict__ src, const int* __restrict__ dst,
                             const float* __restrict__ vr, const float* __restrict__ ev,
                             const float* __restrict__ ssum, float* __restrict__ agg) {
    int idx = blockIdx.x * 256 + threadIdx.x;
    if (idx >= kE * 32) return;
    int e = idx >> 5, c4 = idx & 31;
    int h = c4 >> 2;
    int s = __ldg(&src[e]), dn = __ldg(&dst[e]);
    float alpha = __ldg(&ev[(size_t)e * kH + h]) /
                  (__ldg(&ssum[(size_t)dn * kH + h]) + 1e-16f);
    float4 v = __ldg((const float4*)(vr + (size_t)s * kC + c4 * 4));
    v.x *= alpha; v.y *= alpha; v.z *= alpha; v.w *= alpha;
    float* p = agg + (size_t)dn * kC + c4 * 4;
    asm volatile("red.global.add.v4.f32 [%0], {%1,%2,%3,%4};"
                 :: "l"(p), "f"(v.x), "f"(v.y), "f"(v.z), "f"(v.w) : "memory");
}

// ---------------------------------------------------------------------------
// Orchestration
// ---------------------------------------------------------------------------
extern "C" void kernel_launch(void* const* d_in, const int* in_sizes, int n_in,
                              void* d_out, int out_size) {
    const int* tok_s = (const int*)d_in[0];
    const int* tok_f = (const int*)d_in[1];
    const int* esrc[3] = {(const int*)d_in[2], (const int*)d_in[4], (const int*)d_in[6]};
    const int* edst[3] = {(const int*)d_in[3], (const int*)d_in[5], (const int*)d_in[7]};
    const float* emb   = (const float*)d_in[8];
    const float* lin_w = (const float*)d_in[9];
    const float* lin_b = (const float*)d_in[10];
    const float* kw = (const float*)d_in[11];
    const float* kb = (const float*)d_in[12];
    const float* qw = (const float*)d_in[13];
    const float* qb = (const float*)d_in[14];
    const float* vw = (const float*)d_in[15];
    const float* vb = (const float*)d_in[16];
    const float* aw = (const float*)d_in[17];
    const float* ab = (const float*)d_in[18];
    const float* skip  = (const float*)d_in[19];
    const float* a_rel = (const float*)d_in[20];
    const float* m_rel = (const float*)d_in[21];
    const float* p_rel = (const float*)d_in[22];
    float* out = (float*)d_out;

    float *pe, *px, *pk, *pq, *pv, *pagg, *pkr, *pvr, *plog, *psm, *pss;
    cudaGetSymbolAddress((void**)&pe,   g_e);
    cudaGetSymbolAddress((void**)&px,   g_x);
    cudaGetSymbolAddress((void**)&pk,   g_k);
    cudaGetSymbolAddress((void**)&pq,   g_q);
    cudaGetSymbolAddress((void**)&pv,   g_v);
    cudaGetSymbolAddress((void**)&pagg, g_agg);
    cudaGetSymbolAddress((void**)&pkr,  g_kr);
    cudaGetSymbolAddress((void**)&pvr,  g_vr);
    cudaGetSymbolAddress((void**)&plog, g_logit);
    cudaGetSymbolAddress((void**)&psm,  g_segmax);
    cudaGetSymbolAddress((void**)&pss,  g_segsum);

    cudaFuncSetAttribute(gemm128<0,0>, cudaFuncAttributeMaxDynamicSharedMemorySize, GEMM_SMEM);
    cudaFuncSetAttribute(gemm128<0,1>, cudaFuncAttributeMaxDynamicSharedMemorySize, GEMM_SMEM);
    cudaFuncSetAttribute(gemm128<1,2>, cudaFuncAttributeMaxDynamicSharedMemorySize, GEMM_SMEM);

    const int toff[2] = {0, kNStmt};
    const int tN[2]   = {kNStmt, kNFunc};
    const int st[3]  = {0, 0, 1};
    const int dtt[3] = {0, 1, 0};

    // Stage A: embedding + per-type input linear (relu)
    embed_kernel<<<kNTot, 128>>>(tok_s, tok_f, emb, pe);
    for (int t = 0; t < 2; ++t) {
        size_t xo = (size_t)toff[t] * kC;
        gemm128<0,1><<<(tN[t] + 63) / 64, 256, GEMM_SMEM>>>(
            pe + xo, lin_w + t * 16384, lin_b + t * 128, nullptr, nullptr, px + xo, tN[t]);
    }

    for (int l = 0; l < kL; ++l) {
        // k/q/v projections per type
        for (int t = 0; t < 2; ++t) {
            int woff = (l * 2 + t) * 16384, boff = (l * 2 + t) * 128;
            size_t xo = (size_t)toff[t] * kC;
            int grid = (tN[t] + 63) / 64;
            gemm128<0,0><<<grid, 256, GEMM_SMEM>>>(px + xo, kw + woff, kb + boff, nullptr, nullptr, pk + xo, tN[t]);
            gemm128<0,0><<<grid, 256, GEMM_SMEM>>>(px + xo, qw + woff, qb + boff, nullptr, nullptr, pq + xo, tN[t]);
            gemm128<0,0><<<grid, 256, GEMM_SMEM>>>(px + xo, vw + woff, vb + boff, nullptr, nullptr, pv + xo, tN[t]);
        }
        zero_kernel<<<(kNTot * 32 + 255) / 256, 256>>>((float4*)pagg, kNTot * 32);

        for (int r = 0; r < 3; ++r) {
            int s = st[r], d = dtt[r];
            int Nsrc = tN[s], Ndst = tN[d];
            size_t so = (size_t)toff[s] * kC, dofs = (size_t)toff[d] * kC;
            const float* Ar = a_rel + (size_t)(l * 3 + r) * 2048;
            const float* Mr = m_rel + (size_t)(l * 3 + r) * 2048;
            rel_transform<<<(Nsrc + 15) / 16, 256>>>(pk + so, Ar, pkr, Nsrc);
            rel_transform<<<(Nsrc + 15) / 16, 256>>>(pv + so, Mr, pvr, Nsrc);
            seg_init<<<(Ndst * kH + 255) / 256, 256>>>((unsigned int*)psm, pss, Ndst * kH);
            edge_logits<<<(kE * kH + 255) / 256, 256>>>(esrc[r], edst[r], pq + dofs, pkr,
                                                        p_rel + (l * 3 + r) * 8, plog, psm);
            edge_expsum<<<(kE * kH + 255) / 256, 256>>>(edst[r], plog, psm, pss);
            edge_scatter<<<(kE * 32 + 255) / 256, 256>>>(esrc[r], edst[r], pvr, plog, pss,
                                                         pagg + dofs);
        }

        // Output projection with gelu pre-activation + skip blend
        for (int t = 0; t < 2; ++t) {
            int woff = (l * 2 + t) * 16384, boff = (l * 2 + t) * 128;
            size_t xo = (size_t)toff[t] * kC;
            float* dst = (l == kL - 1) ? (out + xo) : (px + xo);
            gemm128<1,2><<<(tN[t] + 63) / 64, 256, GEMM_SMEM>>>(
                pagg + xo, aw + woff, ab + boff, px + xo, skip + (l * 2 + t), dst, tN[t]);
        }
    }
}

// round 3
// speedup vs baseline: 1.9582x; 1.9582x over previous
#include <cuda_runtime.h>
#include <cstdint>

// ---------------------------------------------------------------------------
// HGT forward. Node layout: stmt rows [0,100000), func rows [100000,150000).
// GEMMs: mma.sync tf32 (sm_80 path; tcgen05 unavailable — harness PTX targets
// sm_103 without the 'a' feature suffix). Everything else fp32.
// ---------------------------------------------------------------------------
constexpr int kNStmt = 100000;
constexpr int kNFunc = 50000;
constexpr int kNTot  = 150000;
constexpr int kC = 128;
constexpr int kH = 8;
constexpr int kD = 16;
constexpr int kE = 200000;
constexpr int kL = 2;
constexpr int kT = 16;

// Scratch (device globals: no allocation allowed)
__device__ float g_e  [(size_t)kNTot * kC];
__device__ float g_x  [(size_t)kNTot * kC];
__device__ float g_k  [(size_t)kNTot * kC];
__device__ float g_q  [(size_t)kNTot * kC];
__device__ float g_v  [(size_t)kNTot * kC];
__device__ float g_agg[(size_t)kNTot * kC];
__device__ float g_kr [(size_t)kNStmt * kC];
__device__ float g_vr [(size_t)kNStmt * kC];
__device__ float g_logit [(size_t)kE * kH];
__device__ float g_segmax[(size_t)kNStmt * kH];
__device__ float g_segsum[(size_t)kNStmt * kH];
__device__ float g_wt [(size_t)18 * 16384];   // 18 fragment-ordered tf32 weights

__device__ __forceinline__ float totf32(float x) {
    uint32_t r;
    asm("cvt.rna.tf32.f32 %0, %1;" : "=r"(r) : "f"(x));
    return __uint_as_float(r);
}
__device__ __forceinline__ float gelu_t(float u) {
    return 0.5f * u * (1.f + tanhf(0.7978845608028654f * (u + 0.044715f * u * u * u)));
}

#define MMA_TF32(c, a, bv0, bv1) \
    asm volatile("mma.sync.aligned.m16n8k8.row.col.f32.tf32.tf32.f32 " \
        "{%0,%1,%2,%3}, {%4,%5,%6,%7}, {%8,%9}, {%0,%1,%2,%3};" \
        : "+f"((c)[0]), "+f"((c)[1]), "+f"((c)[2]), "+f"((c)[3]) \
        : "r"((a)[0]), "r"((a)[1]), "r"((a)[2]), "r"((a)[3]), "r"(bv0), "r"(bv1))

// ---------------------------------------------------------------------------
// Weight prep: W[k][n] (row-major 128x128) -> fragment-ordered tf32 layout
// idx = ((nt*16 + ks)*32 + lane)*2 + reg ;  k = ks*8+(lane&3)+reg*4, n = nt*8+(lane>>2)
// ---------------------------------------------------------------------------
__global__ void __launch_bounds__(256) fragw(
        const float* __restrict__ lin_w, const float* __restrict__ kw,
        const float* __restrict__ qw, const float* __restrict__ vw,
        const float* __restrict__ aw, float* __restrict__ wt) {
    int m = blockIdx.x;
    const float* W = (m < 2)  ? lin_w + (size_t)m * 16384
                   : (m < 6)  ? kw + (size_t)(m - 2) * 16384
                   : (m < 10) ? qw + (size_t)(m - 6) * 16384
                   : (m < 14) ? vw + (size_t)(m - 10) * 16384
                              : aw + (size_t)(m - 14) * 16384;
    float* dst = wt + (size_t)m * 16384;
    for (int idx = threadIdx.x; idx < 16384; idx += 256) {
        int reg = idx & 1, lane = (idx >> 1) & 31, ks = (idx >> 6) & 15, nt = idx >> 10;
        int k = ks * 8 + (lane & 3) + reg * 4;
        int n = nt * 8 + (lane >> 2);
        dst[idx] = totf32(__ldg(&W[k * 128 + n]));
    }
}

// ---------------------------------------------------------------------------
// tf32 GEMM: Out_j[n,:] = post( pre(A)[n,:] @ W_j + bias_j )  for j < NB
// Tile M=128,N=128,K=128. 8 warps (4Mx2N), warp 32x64, m16n8k8 fragments.
// PRE: 0=none, 1=tanh-gelu.  POST: 0=none, 1=relu, 2=skip blend.
// ---------------------------------------------------------------------------
constexpr int TG_SMEM = (128 * 132 + 16384) * 4;   // A padded + B frags

template<int PRE, int POST, int NB>
__global__ void __launch_bounds__(256, 1) tgemm(
        const float* __restrict__ A,
        const float* __restrict__ Bf0, const float* __restrict__ Bf1,
        const float* __restrict__ Bf2,
        const float* __restrict__ b0, const float* __restrict__ b1,
        const float* __restrict__ b2,
        const float* __restrict__ Xold, const float* __restrict__ skipp,
        float* __restrict__ O0, float* __restrict__ O1, float* __restrict__ O2,
        int N)
{
    extern __shared__ float sm[];
    float* As = sm;                       // [128][132]
    float* Bs = sm + 128 * 132;           // 16384 frag-ordered
    uint32_t* Asu = (uint32_t*)As;

    int tid = threadIdx.x, wid = tid >> 5, lane = tid & 31;
    int warpM = wid & 3, warpN = wid >> 2;
    int rowBase = blockIdx.x * 128;

    // Stage A (PRE + tf32 rounding), row-major padded
#pragma unroll 4
    for (int p = 0; p < 16; ++p) {
        int idx = p * 256 + tid;
        int r = idx >> 5, c4 = idx & 31;
        int n = rowBase + r;
        float4 v = make_float4(0.f, 0.f, 0.f, 0.f);
        if (n < N) v = __ldg((const float4*)(A + (size_t)n * 128 + c4 * 4));
        if (PRE == 1) {
            v.x = gelu_t(v.x); v.y = gelu_t(v.y); v.z = gelu_t(v.z); v.w = gelu_t(v.w);
        }
        v.x = totf32(v.x); v.y = totf32(v.y); v.z = totf32(v.z); v.w = totf32(v.w);
        *(float4*)&As[r * 132 + c4 * 4] = v;
    }

    const float* Bfs[3] = {Bf0, Bf1, Bf2};
    const float* bss[3] = {b0, b1, b2};
    float* Os[3] = {O0, O1, O2};

    float gate = 1.f, og = 0.f;
    if (POST == 2) {
        float sv = __ldg(skipp);
        gate = 1.f / (1.f + expf(-sv));
        og = 1.f - gate;
    }

#pragma unroll
    for (int j = 0; j < NB; ++j) {
        __syncthreads();   // A ready / prior Bs fully consumed
#pragma unroll 4
        for (int p = 0; p < 16; ++p) {
            int idx = p * 256 + tid;
            ((float4*)Bs)[idx] = __ldg((const float4*)Bfs[j] + idx);
        }
        __syncthreads();

        float acc[2][8][4];
#pragma unroll
        for (int mt = 0; mt < 2; ++mt)
#pragma unroll
            for (int nt = 0; nt < 8; ++nt)
#pragma unroll
                for (int i = 0; i < 4; ++i) acc[mt][nt][i] = 0.f;

#pragma unroll
        for (int ks = 0; ks < 16; ++ks) {
            uint32_t a[2][4];
#pragma unroll
            for (int mt = 0; mt < 2; ++mt) {
                int rb = warpM * 32 + mt * 16 + (lane >> 2);
                int cb = ks * 8 + (lane & 3);
                a[mt][0] = Asu[rb * 132 + cb];
                a[mt][1] = Asu[(rb + 8) * 132 + cb];
                a[mt][2] = Asu[rb * 132 + cb + 4];
                a[mt][3] = Asu[(rb + 8) * 132 + cb + 4];
            }
#pragma unroll
            for (int nt = 0; nt < 8; ++nt) {
                int ntA = warpN * 8 + nt;
                uint2 bv = *(const uint2*)&Bs[((ntA * 16 + ks) * 32 + lane) * 2];
#pragma unroll
                for (int mt = 0; mt < 2; ++mt)
                    MMA_TF32(acc[mt][nt], a[mt], bv.x, bv.y);
            }
        }

        // Epilogue
        int g = lane >> 2, t2 = (lane & 3) * 2;
#pragma unroll
        for (int mt = 0; mt < 2; ++mt) {
            int r0 = rowBase + warpM * 32 + mt * 16 + g;
#pragma unroll
            for (int nt = 0; nt < 8; ++nt) {
                int col = warpN * 64 + nt * 8 + t2;
                float bb0 = __ldg(&bss[j][col]), bb1 = __ldg(&bss[j][col + 1]);
                float o0 = acc[mt][nt][0] + bb0, o1 = acc[mt][nt][1] + bb1;
                float o2 = acc[mt][nt][2] + bb0, o3 = acc[mt][nt][3] + bb1;
                if (POST == 1) {
                    o0 = fmaxf(o0, 0.f); o1 = fmaxf(o1, 0.f);
                    o2 = fmaxf(o2, 0.f); o3 = fmaxf(o3, 0.f);
                }
                if (POST == 2) {
                    if (r0 < N) {
                        float2 x = *(const float2*)(Xold + (size_t)r0 * 128 + col);
                        o0 = gate * o0 + og * x.x; o1 = gate * o1 + og * x.y;
                    }
                    if (r0 + 8 < N) {
                        float2 x = *(const float2*)(Xold + (size_t)(r0 + 8) * 128 + col);
                        o2 = gate * o2 + og * x.x; o3 = gate * o3 + og * x.y;
                    }
                }
                if (r0 < N)
                    *(float2*)(Os[j] + (size_t)r0 * 128 + col) = make_float2(o0, o1);
                if (r0 + 8 < N)
                    *(float2*)(Os[j] + (size_t)(r0 + 8) * 128 + col) = make_float2(o2, o3);
            }
        }
    }
}

// ---------------------------------------------------------------------------
// Embedding: e[n,c] = relu(mean_t emb[tok[n,t], c])
// ---------------------------------------------------------------------------
__global__ void embed_kernel(const int* __restrict__ tok_s, const int* __restrict__ tok_f,
                             const float* __restrict__ emb, float* __restrict__ out) {
    int n = blockIdx.x;
    int c = threadIdx.x;
    const int* tok = (n < kNStmt) ? (tok_s + (size_t)n * kT)
                                  : (tok_f + (size_t)(n - kNStmt) * kT);
    float acc = 0.f;
#pragma unroll
    for (int i = 0; i < kT; ++i) {
        int t = __ldg(&tok[i]);
        acc += __ldg(&emb[(size_t)t * kC + c]);
    }
    acc *= (1.f / 16.f);
    out[(size_t)n * kC + c] = fmaxf(acc, 0.f);
}

// ---------------------------------------------------------------------------
// Per-head relation transform: out[n, h*16+e] = sum_d in[n, h*16+d] * A[h,d,e]
// ---------------------------------------------------------------------------
__global__ void __launch_bounds__(256) rel_transform(
        const float* __restrict__ in, const float* __restrict__ A,
        float* __restrict__ out, int Nsrc)
{
    __shared__ float As[2048];   // [h][d][e]
    int tid = threadIdx.x;
    for (int i = tid; i < 2048; i += 256) As[i] = __ldg(&A[i]);
    __syncthreads();
    int n = blockIdx.x * 8 + (tid >> 5);
    if (n >= Nsrc) return;
    int c4 = tid & 31;
    int h = c4 >> 2, e4 = c4 & 3;
    const float4* ip = (const float4*)(in + (size_t)n * kC + h * 16);
    float4 r0 = __ldg(&ip[0]), r1 = __ldg(&ip[1]), r2 = __ldg(&ip[2]), r3 = __ldg(&ip[3]);
    float rv[16] = {r0.x, r0.y, r0.z, r0.w, r1.x, r1.y, r1.z, r1.w,
                    r2.x, r2.y, r2.z, r2.w, r3.x, r3.y, r3.z, r3.w};
    float4 acc = make_float4(0.f, 0.f, 0.f, 0.f);
#pragma unroll
    for (int d = 0; d < 16; ++d) {
        float4 a = *(const float4*)&As[h * 256 + d * 16 + e4 * 4];
        float s = rv[d];
        acc.x += s * a.x; acc.y += s * a.y; acc.z += s * a.z; acc.w += s * a.w;
    }
    *(float4*)(out + (size_t)n * kC + c4 * 4) = acc;
}

// ---------------------------------------------------------------------------
// Edge-phase kernels
// ---------------------------------------------------------------------------
__global__ void seg_init(unsigned int* __restrict__ smax, float* __restrict__ ssum, int n) {
    int i = blockIdx.x * 256 + threadIdx.x;
    if (i < n) { smax[i] = 0xFF800000u; ssum[i] = 0.f; }
}

__global__ void zero_kernel(float4* __restrict__ p, int n4) {
    int i = blockIdx.x * 256 + threadIdx.x;
    if (i < n4) p[i] = make_float4(0.f, 0.f, 0.f, 0.f);
}

__device__ __forceinline__ void atomicMaxFloat(float* addr, float v) {
    unsigned int u = __float_as_uint(v);
    if (u >> 31) atomicMin((unsigned int*)addr, u);
    else         atomicMax((int*)addr, (int)u);
}

__global__ void edge_logits(const int* __restrict__ src, const int* __restrict__ dst,
                            const float* __restrict__ q, const float* __restrict__ kr,
                            const float* __restrict__ prel, float* __restrict__ logit,
                            float* __restrict__ smax) {
    int idx = blockIdx.x * 256 + threadIdx.x;
    if (idx >= kE * kH) return;
    int e = idx >> 3, h = idx & 7;
    int s = __ldg(&src[e]), dn = __ldg(&dst[e]);
    const float4* qp = (const float4*)(q  + (size_t)dn * kC + h * kD);
    const float4* kp = (const float4*)(kr + (size_t)s  * kC + h * kD);
    float acc = 0.f;
#pragma unroll
    for (int i = 0; i < 4; ++i) {
        float4 a = __ldg(&qp[i]);
        float4 b = __ldg(&kp[i]);
        acc += a.x * b.x + a.y * b.y + a.z * b.z + a.w * b.w;
    }
    float lg = acc * __ldg(&prel[h]) * 0.25f;
    logit[idx] = lg;
    atomicMaxFloat(&smax[(size_t)dn * kH + h], lg);
}

__global__ void edge_expsum(const int* __restrict__ dst, float* __restrict__ logit,
                            const float* __restrict__ smax, float* __restrict__ ssum) {
    int idx = blockIdx.x * 256 + threadIdx.x;
    if (idx >= kE * kH) return;
    int e = idx >> 3, h = idx & 7;
    int dn = __ldg(&dst[e]);
    float v = expf(logit[idx] - __ldg(&smax[(size_t)dn * kH + h]));
    logit[idx] = v;
    atomicAdd(&ssum[(size_t)dn * kH + h], v);
}

__global__ void edge_scatter(const int* __restrict__ src, const int* __restrict__ dst,
                             const float* __restrict__ vr, const float* __restrict__ ev,
                             const float* __restrict__ ssum, float* __restrict__ agg) {
    int idx = blockIdx.x * 256 + threadIdx.x;
    if (idx >= kE * 32) return;
    int e = idx >> 5, c4 = idx & 31;
    int h = c4 >> 2;
    int s = __ldg(&src[e]), dn = __ldg(&dst[e]);
    float alpha = __ldg(&ev[(size_t)e * kH + h]) /
                  (__ldg(&ssum[(size_t)dn * kH + h]) + 1e-16f);
    float4 v = __ldg((const float4*)(vr + (size_t)s * kC + c4 * 4));
    v.x *= alpha; v.y *= alpha; v.z *= alpha; v.w *= alpha;
    float* p = agg + (size_t)dn * kC + c4 * 4;
    asm volatile("red.global.add.v4.f32 [%0], {%1,%2,%3,%4};"
                 :: "l"(p), "f"(v.x), "f"(v.y), "f"(v.z), "f"(v.w) : "memory");
}

// ---------------------------------------------------------------------------
// Orchestration
// ---------------------------------------------------------------------------
extern "C" void kernel_launch(void* const* d_in, const int* in_sizes, int n_in,
                              void* d_out, int out_size) {
    const int* tok_s = (const int*)d_in[0];
    const int* tok_f = (const int*)d_in[1];
    const int* esrc[3] = {(const int*)d_in[2], (const int*)d_in[4], (const int*)d_in[6]};
    const int* edst[3] = {(const int*)d_in[3], (const int*)d_in[5], (const int*)d_in[7]};
    const float* emb   = (const float*)d_in[8];
    const float* lin_w = (const float*)d_in[9];
    const float* lin_b = (const float*)d_in[10];
    const float* kw = (const float*)d_in[11];
    const float* kb = (const float*)d_in[12];
    const float* qw = (const float*)d_in[13];
    const float* qb = (const float*)d_in[14];
    const float* vw = (const float*)d_in[15];
    const float* vb = (const float*)d_in[16];
    const float* aw = (const float*)d_in[17];
    const float* ab = (const float*)d_in[18];
    const float* skip  = (const float*)d_in[19];
    const float* a_rel = (const float*)d_in[20];
    const float* m_rel = (const float*)d_in[21];
    const float* p_rel = (const float*)d_in[22];
    float* out = (float*)d_out;

    float *pe, *px, *pk, *pq, *pv, *pagg, *pkr, *pvr, *plog, *psm, *pss, *pwt;
    cudaGetSymbolAddress((void**)&pe,   g_e);
    cudaGetSymbolAddress((void**)&px,   g_x);
    cudaGetSymbolAddress((void**)&pk,   g_k);
    cudaGetSymbolAddress((void**)&pq,   g_q);
    cudaGetSymbolAddress((void**)&pv,   g_v);
    cudaGetSymbolAddress((void**)&pagg, g_agg);
    cudaGetSymbolAddress((void**)&pkr,  g_kr);
    cudaGetSymbolAddress((void**)&pvr,  g_vr);
    cudaGetSymbolAddress((void**)&plog, g_logit);
    cudaGetSymbolAddress((void**)&psm,  g_segmax);
    cudaGetSymbolAddress((void**)&pss,  g_segsum);
    cudaGetSymbolAddress((void**)&pwt,  g_wt);

    cudaFuncSetAttribute(tgemm<0,1,1>, cudaFuncAttributeMaxDynamicSharedMemorySize, TG_SMEM);
    cudaFuncSetAttribute(tgemm<0,0,3>, cudaFuncAttributeMaxDynamicSharedMemorySize, TG_SMEM);
    cudaFuncSetAttribute(tgemm<1,2,1>, cudaFuncAttributeMaxDynamicSharedMemorySize, TG_SMEM);

    const int toff[2] = {0, kNStmt};
    const int tN[2]   = {kNStmt, kNFunc};
    const int st[3]  = {0, 0, 1};
    const int dtt[3] = {0, 1, 0};

    // One-time weight fragment prep (runs every call; 18 small blocks, cheap)
    fragw<<<18, 256>>>(lin_w, kw, qw, vw, aw, pwt);

    // Stage A: embedding + per-type input linear (relu)
    embed_kernel<<<kNTot, 128>>>(tok_s, tok_f, emb, pe);
    for (int t = 0; t < 2; ++t) {
        size_t xo = (size_t)toff[t] * kC;
        tgemm<0,1,1><<<(tN[t] + 127) / 128, 256, TG_SMEM>>>(
            pe + xo, pwt + (size_t)t * 16384, nullptr, nullptr,
            lin_b + t * 128, nullptr, nullptr, nullptr, nullptr,
            px + xo, nullptr, nullptr, tN[t]);
    }

    for (int l = 0; l < kL; ++l) {
        for (int t = 0; t < 2; ++t) {
            int mi = l * 2 + t;
            size_t xo = (size_t)toff[t] * kC;
            tgemm<0,0,3><<<(tN[t] + 127) / 128, 256, TG_SMEM>>>(
                px + xo,
                pwt + (size_t)(2 + mi) * 16384, pwt + (size_t)(6 + mi) * 16384,
                pwt + (size_t)(10 + mi) * 16384,
                kb + mi * 128, qb + mi * 128, vb + mi * 128,
                nullptr, nullptr,
                pk + xo, pq + xo, pv + xo, tN[t]);
        }
        zero_kernel<<<(kNTot * 32 + 255) / 256, 256>>>((float4*)pagg, kNTot * 32);

        for (int r = 0; r < 3; ++r) {
            int s = st[r], d = dtt[r];
            int Nsrc = tN[s], Ndst = tN[d];
            size_t so = (size_t)toff[s] * kC, dofs = (size_t)toff[d] * kC;
            const float* Ar = a_rel + (size_t)(l * 3 + r) * 2048;
            const float* Mr = m_rel + (size_t)(l * 3 + r) * 2048;
            rel_transform<<<(Nsrc + 7) / 8, 256>>>(pk + so, Ar, pkr, Nsrc);
            rel_transform<<<(Nsrc + 7) / 8, 256>>>(pv + so, Mr, pvr, Nsrc);
            seg_init<<<(Ndst * kH + 255) / 256, 256>>>((unsigned int*)psm, pss, Ndst * kH);
            edge_logits<<<(kE * kH + 255) / 256, 256>>>(esrc[r], edst[r], pq + dofs, pkr,
                                                        p_rel + (l * 3 + r) * 8, plog, psm);
            edge_expsum<<<(kE * kH + 255) / 256, 256>>>(edst[r], plog, psm, pss);
            edge_scatter<<<(kE * 32 + 255) / 256, 256>>>(esrc[r], edst[r], pvr, plog, pss,
                                                         pagg + dofs);
        }

        for (int t = 0; t < 2; ++t) {
            int mi = l * 2 + t;
            size_t xo = (size_t)toff[t] * kC;
            float* dst = (l == kL - 1) ? (out + xo) : (px + xo);
            tgemm<1,2,1><<<(tN[t] + 127) / 128, 256, TG_SMEM>>>(
                pagg + xo, pwt + (size_t)(14 + mi) * 16384, nullptr, nullptr,
                ab + mi * 128, nullptr, nullptr,
                px + xo, skip + mi,
                dst, nullptr, nullptr, tN[t]);
        }
    }
}

// round 5
// speedup vs baseline: 2.2508x; 1.1494x over previous
#include <cuda_runtime.h>
#include <cstdint>

// ---------------------------------------------------------------------------
// HGT forward. Node layout: stmt rows [0,100000), func rows [100000,150000).
// GEMMs: mma.sync tf32. Edge phase: CSR + fused online-softmax attention,
// with relation transforms moved to per-dst (q-side / post-agg) via linearity.
// ---------------------------------------------------------------------------
constexpr int kNStmt = 100000;
constexpr int kNFunc = 50000;
constexpr int kNTot  = 150000;
constexpr int kC = 128;
constexpr int kE = 200000;
constexpr int kL = 2;
constexpr int kT = 16;

// Scratch (device globals: no allocation allowed)
__device__ float g_e  [(size_t)kNTot * kC];
__device__ float g_x  [(size_t)kNTot * kC];
__device__ float g_k  [(size_t)kNTot * kC];
__device__ float g_q  [(size_t)kNTot * kC];
__device__ float g_v  [(size_t)kNTot * kC];
__device__ float g_agg[(size_t)kNTot * kC];
__device__ float g_wt [(size_t)18 * 16384];   // fragment-ordered tf32 weights
// CSR scratch: cnt[250000] then cur[250000]
__device__ int g_tmp[500000];
__device__ int g_starts[250003];              // offsets {0, 100001, 150002}
__device__ int g_srt[600000];                 // sorted src, 200000 per relation

__device__ __forceinline__ float totf32(float x) {
    uint32_t r;
    asm("cvt.rna.tf32.f32 %0, %1;" : "=r"(r) : "f"(x));
    return __uint_as_float(r);
}
__device__ __forceinline__ float gelu_t(float u) {
    return 0.5f * u * (1.f + tanhf(0.7978845608028654f * (u + 0.044715f * u * u * u)));
}

#define MMA_TF32(c, a, bv0, bv1) \
    asm volatile("mma.sync.aligned.m16n8k8.row.col.f32.tf32.tf32.f32 " \
        "{%0,%1,%2,%3}, {%4,%5,%6,%7}, {%8,%9}, {%0,%1,%2,%3};" \
        : "+f"((c)[0]), "+f"((c)[1]), "+f"((c)[2]), "+f"((c)[3]) \
        : "r"((a)[0]), "r"((a)[1]), "r"((a)[2]), "r"((a)[3]), "r"(bv0), "r"(bv1))

// ---------------------------------------------------------------------------
// Weight prep: W[k][n] -> fragment-ordered tf32
// ---------------------------------------------------------------------------
__global__ void __launch_bounds__(256) fragw(
        const float* __restrict__ lin_w, const float* __restrict__ kw,
        const float* __restrict__ qw, const float* __restrict__ vw,
        const float* __restrict__ aw, float* __restrict__ wt) {
    int m = blockIdx.x;
    const float* W = (m < 2)  ? lin_w + (size_t)m * 16384
                   : (m < 6)  ? kw + (size_t)(m - 2) * 16384
                   : (m < 10) ? qw + (size_t)(m - 6) * 16384
                   : (m < 14) ? vw + (size_t)(m - 10) * 16384
                              : aw + (size_t)(m - 14) * 16384;
    float* dst = wt + (size_t)m * 16384;
    for (int idx = threadIdx.x; idx < 16384; idx += 256) {
        int reg = idx & 1, lane = (idx >> 1) & 31, ks = (idx >> 6) & 15, nt = idx >> 10;
        int k = ks * 8 + (lane & 3) + reg * 4;
        int n = nt * 8 + (lane >> 2);
        dst[idx] = totf32(__ldg(&W[k * 128 + n]));
    }
}

// ---------------------------------------------------------------------------
// tf32 GEMM: A in smem only; B fragments streamed via __ldg (L1/L2 resident).
// Tile M=128,N=128,K=128. 8 warps (4Mx2N). 2 CTAs/SM.
// PRE: 0=none, 1=tanh-gelu.  POST: 0=none, 1=relu, 2=skip blend.
// ---------------------------------------------------------------------------
constexpr int TG_SMEM = 128 * 132 * 4;

template<int PRE, int POST, int NB>
__global__ void __launch_bounds__(256, 2) tgemm(
        const float* __restrict__ A,
        const float* __restrict__ Bf0, const float* __restrict__ Bf1,
        const float* __restrict__ Bf2,
        const float* __restrict__ b0, const float* __restrict__ b1,
        const float* __restrict__ b2,
        const float* __restrict__ Xold, const float* __restrict__ skipp,
        float* __restrict__ O0, float* __restrict__ O1, float* __restrict__ O2,
        int N)
{
    extern __shared__ float sm[];
    float* As = sm;                       // [128][132]
    uint32_t* Asu = (uint32_t*)As;

    int tid = threadIdx.x, wid = tid >> 5, lane = tid & 31;
    int warpM = wid & 3, warpN = wid >> 2;
    int rowBase = blockIdx.x * 128;

#pragma unroll 4
    for (int p = 0; p < 16; ++p) {
        int idx = p * 256 + tid;
        int r = idx >> 5, c4 = idx & 31;
        int n = rowBase + r;
        float4 v = make_float4(0.f, 0.f, 0.f, 0.f);
        if (n < N) v = __ldg((const float4*)(A + (size_t)n * 128 + c4 * 4));
        if (PRE == 1) {
            v.x = gelu_t(v.x); v.y = gelu_t(v.y); v.z = gelu_t(v.z); v.w = gelu_t(v.w);
        }
        v.x = totf32(v.x); v.y = totf32(v.y); v.z = totf32(v.z); v.w = totf32(v.w);
        *(float4*)&As[r * 132 + c4 * 4] = v;
    }
    __syncthreads();

    const float* Bfs[3] = {Bf0, Bf1, Bf2};
    const float* bss[3] = {b0, b1, b2};
    float* Os[3] = {O0, O1, O2};

    float gate = 1.f, og = 0.f;
    if (POST == 2) {
        float sv = __ldg(skipp);
        gate = 1.f / (1.f + expf(-sv));
        og = 1.f - gate;
    }

#pragma unroll
    for (int j = 0; j < NB; ++j) {
        const float* Bf = Bfs[j];
        float acc[2][8][4];
#pragma unroll
        for (int mt = 0; mt < 2; ++mt)
#pragma unroll
            for (int nt = 0; nt < 8; ++nt)
#pragma unroll
                for (int i = 0; i < 4; ++i) acc[mt][nt][i] = 0.f;

#pragma unroll
        for (int ks = 0; ks < 16; ++ks) {
            uint32_t a[2][4];
#pragma unroll
            for (int mt = 0; mt < 2; ++mt) {
                int rb = warpM * 32 + mt * 16 + (lane >> 2);
                int cb = ks * 8 + (lane & 3);
                a[mt][0] = Asu[rb * 132 + cb];
                a[mt][1] = Asu[(rb + 8) * 132 + cb];
                a[mt][2] = Asu[rb * 132 + cb + 4];
                a[mt][3] = Asu[(rb + 8) * 132 + cb + 4];
            }
#pragma unroll
            for (int nt = 0; nt < 8; ++nt) {
                int ntA = warpN * 8 + nt;
                uint2 bv = __ldg((const uint2*)(Bf + ((ntA * 16 + ks) * 32 + lane) * 2));
#pragma unroll
                for (int mt = 0; mt < 2; ++mt)
                    MMA_TF32(acc[mt][nt], a[mt], bv.x, bv.y);
            }
        }

        int g = lane >> 2, t2 = (lane & 3) * 2;
#pragma unroll
        for (int mt = 0; mt < 2; ++mt) {
            int r0 = rowBase + warpM * 32 + mt * 16 + g;
#pragma unroll
            for (int nt = 0; nt < 8; ++nt) {
                int col = warpN * 64 + nt * 8 + t2;
                float bb0 = __ldg(&bss[j][col]), bb1 = __ldg(&bss[j][col + 1]);
                float o0 = acc[mt][nt][0] + bb0, o1 = acc[mt][nt][1] + bb1;
                float o2 = acc[mt][nt][2] + bb0, o3 = acc[mt][nt][3] + bb1;
                if (POST == 1) {
                    o0 = fmaxf(o0, 0.f); o1 = fmaxf(o1, 0.f);
                    o2 = fmaxf(o2, 0.f); o3 = fmaxf(o3, 0.f);
                }
                if (POST == 2) {
                    if (r0 < N) {
                        float2 x = *(const float2*)(Xold + (size_t)r0 * 128 + col);
                        o0 = gate * o0 + og * x.x; o1 = gate * o1 + og * x.y;
                    }
                    if (r0 + 8 < N) {
                        float2 x = *(const float2*)(Xold + (size_t)(r0 + 8) * 128 + col);
                        o2 = gate * o2 + og * x.x; o3 = gate * o3 + og * x.y;
                    }
                }
                if (r0 < N)
                    *(float2*)(Os[j] + (size_t)r0 * 128 + col) = make_float2(o0, o1);
                if (r0 + 8 < N)
                    *(float2*)(Os[j] + (size_t)(r0 + 8) * 128 + col) = make_float2(o2, o3);
            }
        }
    }
}

// ---------------------------------------------------------------------------
// Embedding: e[n,c] = relu(mean_t emb[tok[n,t], c])
// ---------------------------------------------------------------------------
__global__ void embed_kernel(const int* __restrict__ tok_s, const int* __restrict__ tok_f,
                             const float* __restrict__ emb, float* __restrict__ out) {
    int n = blockIdx.x;
    int c = threadIdx.x;
    const int* tok = (n < kNStmt) ? (tok_s + (size_t)n * kT)
                                  : (tok_f + (size_t)(n - kNStmt) * kT);
    float acc = 0.f;
#pragma unroll
    for (int i = 0; i < kT; ++i) {
        int t = __ldg(&tok[i]);
        acc += __ldg(&emb[(size_t)t * kC + c]);
    }
    acc *= (1.f / 16.f);
    out[(size_t)n * kC + c] = fmaxf(acc, 0.f);
}

// ---------------------------------------------------------------------------
// CSR build: zero, hist, 3-block scan, scatter
// ---------------------------------------------------------------------------
__global__ void zero_int(int* __restrict__ p, int n) {
    int i = blockIdx.x * 256 + threadIdx.x;
    if (i < n) p[i] = 0;
}

__global__ void hist_k(const int* __restrict__ dst, int* __restrict__ cnt, int E) {
    int i = blockIdx.x * 256 + threadIdx.x;
    if (i < E) atomicAdd(&cnt[__ldg(&dst[i])], 1);
}

__global__ void __launch_bounds__(1024) exscan3(const int* __restrict__ cnt,
                                                int* __restrict__ starts) {
    __shared__ int wsum[32];
    __shared__ int carry_s;
    const int cntOff[3] = {0, kNStmt, kNStmt + kNFunc};
    const int stOff[3]  = {0, kNStmt + 1, kNStmt + kNFunc + 2};
    const int ns[3]     = {kNStmt, kNFunc, kNStmt};
    int r = blockIdx.x;
    const int* c = cnt + cntOff[r];
    int* st = starts + stOff[r];
    int n = ns[r];
    int tid = threadIdx.x, lane = tid & 31, w = tid >> 5;
    if (tid == 0) carry_s = 0;
    __syncthreads();
    for (int base = 0; base < n; base += 1024) {
        int i = base + tid;
        int v = (i < n) ? c[i] : 0;
        int x = v;
#pragma unroll
        for (int o = 1; o < 32; o <<= 1) {
            int t = __shfl_up_sync(0xffffffffu, x, o);
            if (lane >= o) x += t;
        }
        if (lane == 31) wsum[w] = x;
        __syncthreads();
        if (w == 0) {
            int y = wsum[lane];
#pragma unroll
            for (int o = 1; o < 32; o <<= 1) {
                int t = __shfl_up_sync(0xffffffffu, y, o);
                if (lane >= o) y += t;
            }
            wsum[lane] = y;
        }
        __syncthreads();
        int incl = x + (w > 0 ? wsum[w - 1] : 0);
        int carry = carry_s;
        if (i < n) st[i] = carry + incl - v;
        __syncthreads();
        if (tid == 0) carry_s = carry + wsum[31];
        __syncthreads();
    }
    if (tid == 0) st[n] = carry_s;
}

__global__ void scat_k(const int* __restrict__ src, const int* __restrict__ dst,
                       const int* __restrict__ starts, int* __restrict__ cur,
                       int* __restrict__ out, int E) {
    int i = blockIdx.x * 256 + threadIdx.x;
    if (i < E) {
        int d = __ldg(&dst[i]);
        int pos = __ldg(&starts[d]) + atomicAdd(&cur[d], 1);
        out[pos] = __ldg(&src[i]);
    }
}

// ---------------------------------------------------------------------------
// Fused edge attention. One warp per dst node; lane = h*4+qq (4 dims each).
// qa = pscale * (A @ q[dst]); per edge: logit = dot(qa, k[src]); online
// softmax accumulates raw v[src]; final agg-quarter = M-transform of acc/s.
// ---------------------------------------------------------------------------
__device__ __forceinline__ float4 attn_rel(
        int dn, int lane, float4 qv,
        const int* __restrict__ starts, const int* __restrict__ srcs,
        const float* __restrict__ kb, const float* __restrict__ vb,
        const float* __restrict__ Asq, const float* __restrict__ Ms, float pscale)
{
    // qa (distributed by d-quarter)
    float4 qa = make_float4(0.f, 0.f, 0.f, 0.f);
#pragma unroll
    for (int g = 0; g < 4; ++g) {
        int sl = (lane & ~3) | g;
        float q0 = __shfl_sync(0xffffffffu, qv.x, sl);
        float q1 = __shfl_sync(0xffffffffu, qv.y, sl);
        float q2 = __shfl_sync(0xffffffffu, qv.z, sl);
        float q3 = __shfl_sync(0xffffffffu, qv.w, sl);
        float4 A0 = *(const float4*)&Asq[(g * 4 + 0) * 128 + lane * 4];
        float4 A1 = *(const float4*)&Asq[(g * 4 + 1) * 128 + lane * 4];
        float4 A2 = *(const float4*)&Asq[(g * 4 + 2) * 128 + lane * 4];
        float4 A3 = *(const float4*)&Asq[(g * 4 + 3) * 128 + lane * 4];
        qa.x += q0 * A0.x + q1 * A1.x + q2 * A2.x + q3 * A3.x;
        qa.y += q0 * A0.y + q1 * A1.y + q2 * A2.y + q3 * A3.y;
        qa.z += q0 * A0.z + q1 * A1.z + q2 * A2.z + q3 * A3.z;
        qa.w += q0 * A0.w + q1 * A1.w + q2 * A2.w + q3 * A3.w;
    }
    qa.x *= pscale; qa.y *= pscale; qa.z *= pscale; qa.w *= pscale;

    int e0 = __ldg(&starts[dn]), e1 = __ldg(&starts[dn + 1]);
    float m = -INFINITY, s = 0.f;
    float4 acc = make_float4(0.f, 0.f, 0.f, 0.f);
    for (int e = e0; e < e1; ++e) {
        int src = __ldg(&srcs[e]);
        float4 kq = __ldg((const float4*)(kb + (size_t)src * 128) + lane);
        float4 vq = __ldg((const float4*)(vb + (size_t)src * 128) + lane);
        float lg = qa.x * kq.x + qa.y * kq.y + qa.z * kq.z + qa.w * kq.w;
        lg += __shfl_xor_sync(0xffffffffu, lg, 1);
        lg += __shfl_xor_sync(0xffffffffu, lg, 2);
        float nm = fmaxf(m, lg);
        float corr = __expf(m - nm);
        float p = __expf(lg - nm);
        s = s * corr + p;
        acc.x = acc.x * corr + p * vq.x;
        acc.y = acc.y * corr + p * vq.y;
        acc.z = acc.z * corr + p * vq.z;
        acc.w = acc.w * corr + p * vq.w;
        m = nm;
    }
    float inv = 1.f / (s + 1e-16f);
    float4 fin = make_float4(acc.x * inv, acc.y * inv, acc.z * inv, acc.w * inv);

    float4 ov = make_float4(0.f, 0.f, 0.f, 0.f);
#pragma unroll
    for (int g = 0; g < 4; ++g) {
        int sl = (lane & ~3) | g;
        float d0 = __shfl_sync(0xffffffffu, fin.x, sl);
        float d1 = __shfl_sync(0xffffffffu, fin.y, sl);
        float d2 = __shfl_sync(0xffffffffu, fin.z, sl);
        float d3 = __shfl_sync(0xffffffffu, fin.w, sl);
        float4 M0 = *(const float4*)&Ms[(g * 4 + 0) * 128 + lane * 4];
        float4 M1 = *(const float4*)&Ms[(g * 4 + 1) * 128 + lane * 4];
        float4 M2 = *(const float4*)&Ms[(g * 4 + 2) * 128 + lane * 4];
        float4 M3 = *(const float4*)&Ms[(g * 4 + 3) * 128 + lane * 4];
        ov.x += d0 * M0.x + d1 * M1.x + d2 * M2.x + d3 * M3.x;
        ov.y += d0 * M0.y + d1 * M1.y + d2 * M2.y + d3 * M3.y;
        ov.z += d0 * M0.z + d1 * M1.z + d2 * M2.z + d3 * M3.z;
        ov.w += d0 * M0.w + d1 * M1.w + d2 * M2.w + d3 * M3.w;
    }
    return ov;
}

template<int TWO>
__global__ void __launch_bounds__(256) attn_kernel(
        const float* __restrict__ q,
        const float* __restrict__ kb0, const float* __restrict__ vb0,
        const int* __restrict__ st0, const int* __restrict__ sr0,
        const float* __restrict__ A0, const float* __restrict__ M0,
        const float* __restrict__ p0,
        const float* __restrict__ kb2, const float* __restrict__ vb2,
        const int* __restrict__ st2, const int* __restrict__ sr2,
        const float* __restrict__ A2, const float* __restrict__ M2,
        const float* __restrict__ p2,
        float* __restrict__ agg)
{
    __shared__ float As0[2048], Ms0[2048], As2[2048], Ms2[2048];
    int tid = threadIdx.x;
    for (int i = tid; i < 2048; i += 256) {
        // Asq layout [e][h][d]; Ms layout [d][h][e]
        int a = i >> 7, he = i & 127, h = he >> 4, b = he & 15;
        As0[i] = __ldg(&A0[(h * 16 + b) * 16 + a]);   // a=e, b=d
        Ms0[i] = __ldg(&M0[(h * 16 + a) * 16 + b]);   // a=d, b=e
        if (TWO) {
            As2[i] = __ldg(&A2[(h * 16 + b) * 16 + a]);
            Ms2[i] = __ldg(&M2[(h * 16 + a) * 16 + b]);
        }
    }
    __syncthreads();
    int wid = tid >> 5, lane = tid & 31;
    int dn = blockIdx.x * 8 + wid;
    int h = lane >> 2;
    float4 qv = __ldg((const float4*)(q + (size_t)dn * 128) + lane);
    float4 r = attn_rel(dn, lane, qv, st0, sr0, kb0, vb0, As0, Ms0,
                        __ldg(&p0[h]) * 0.25f);
    if (TWO) {
        float4 r2 = attn_rel(dn, lane, qv, st2, sr2, kb2, vb2, As2, Ms2,
                             __ldg(&p2[h]) * 0.25f);
        r.x += r2.x; r.y += r2.y; r.z += r2.z; r.w += r2.w;
    }
    ((float4*)(agg + (size_t)dn * 128))[lane] = r;
}

// ---------------------------------------------------------------------------
// Orchestration
// ---------------------------------------------------------------------------
extern "C" void kernel_launch(void* const* d_in, const int* in_sizes, int n_in,
                              void* d_out, int out_size) {
    const int* tok_s = (const int*)d_in[0];
    const int* tok_f = (const int*)d_in[1];
    const int* esrc[3] = {(const int*)d_in[2], (const int*)d_in[4], (const int*)d_in[6]};
    const int* edst[3] = {(const int*)d_in[3], (const int*)d_in[5], (const int*)d_in[7]};
    const float* emb   = (const float*)d_in[8];
    const float* lin_w = (const float*)d_in[9];
    const float* lin_b = (const float*)d_in[10];
    const float* kw = (const float*)d_in[11];
    const float* kb = (const float*)d_in[12];
    const float* qw = (const float*)d_in[13];
    const float* qb = (const float*)d_in[14];
    const float* vw = (const float*)d_in[15];
    const float* vb = (const float*)d_in[16];
    const float* aw = (const float*)d_in[17];
    const float* ab = (const float*)d_in[18];
    const float* skip  = (const float*)d_in[19];
    const float* a_rel = (const float*)d_in[20];
    const float* m_rel = (const float*)d_in[21];
    const float* p_rel = (const float*)d_in[22];
    float* out = (float*)d_out;

    float *pe, *px, *pk, *pq, *pv, *pagg, *pwt;
    int *ptmp, *pst, *psrt;
    cudaGetSymbolAddress((void**)&pe,   g_e);
    cudaGetSymbolAddress((void**)&px,   g_x);
    cudaGetSymbolAddress((void**)&pk,   g_k);
    cudaGetSymbolAddress((void**)&pq,   g_q);
    cudaGetSymbolAddress((void**)&pv,   g_v);
    cudaGetSymbolAddress((void**)&pagg, g_agg);
    cudaGetSymbolAddress((void**)&pwt,  g_wt);
    cudaGetSymbolAddress((void**)&ptmp, g_tmp);
    cudaGetSymbolAddress((void**)&pst,  g_starts);
    cudaGetSymbolAddress((void**)&psrt, g_srt);

    cudaFuncSetAttribute(tgemm<0,1,1>, cudaFuncAttributeMaxDynamicSharedMemorySize, TG_SMEM);
    cudaFuncSetAttribute(tgemm<0,0,3>, cudaFuncAttributeMaxDynamicSharedMemorySize, TG_SMEM);
    cudaFuncSetAttribute(tgemm<1,2,1>, cudaFuncAttributeMaxDynamicSharedMemorySize, TG_SMEM);

    const int toff[2] = {0, kNStmt};
    const int tN[2]   = {kNStmt, kNFunc};
    const int cntOff[3] = {0, kNStmt, kNStmt + kNFunc};
    const int stOff[3]  = {0, kNStmt + 1, kNStmt + kNFunc + 2};
    int egrid = (kE + 255) / 256;

    // CSR build (edges identical across layers -> once per call)
    zero_int<<<(500000 + 255) / 256, 256>>>(ptmp, 500000);
    for (int r = 0; r < 3; ++r)
        hist_k<<<egrid, 256>>>(edst[r], ptmp + cntOff[r], kE);
    exscan3<<<3, 1024>>>(ptmp, pst);
    for (int r = 0; r < 3; ++r)
        scat_k<<<egrid, 256>>>(esrc[r], edst[r], pst + stOff[r],
                               ptmp + 250000 + cntOff[r], psrt + r * kE, kE);

    // Weight fragment prep + embedding + input linear (relu)
    fragw<<<18, 256>>>(lin_w, kw, qw, vw, aw, pwt);
    embed_kernel<<<kNTot, 128>>>(tok_s, tok_f, emb, pe);
    for (int t = 0; t < 2; ++t) {
        size_t xo = (size_t)toff[t] * kC;
        tgemm<0,1,1><<<(tN[t] + 127) / 128, 256, TG_SMEM>>>(
            pe + xo, pwt + (size_t)t * 16384, nullptr, nullptr,
            lin_b + t * 128, nullptr, nullptr, nullptr, nullptr,
            px + xo, nullptr, nullptr, tN[t]);
    }

    for (int l = 0; l < kL; ++l) {
        for (int t = 0; t < 2; ++t) {
            int mi = l * 2 + t;
            size_t xo = (size_t)toff[t] * kC;
            tgemm<0,0,3><<<(tN[t] + 127) / 128, 256, TG_SMEM>>>(
                px + xo,
                pwt + (size_t)(2 + mi) * 16384, pwt + (size_t)(6 + mi) * 16384,
                pwt + (size_t)(10 + mi) * 16384,
                kb + mi * 128, qb + mi * 128, vb + mi * 128,
                nullptr, nullptr,
                pk + xo, pq + xo, pv + xo, tN[t]);
        }

        const float* Ar0 = a_rel + (size_t)(l * 3 + 0) * 2048;
        const float* Ar1 = a_rel + (size_t)(l * 3 + 1) * 2048;
        const float* Ar2 = a_rel + (size_t)(l * 3 + 2) * 2048;
        const float* Mr0 = m_rel + (size_t)(l * 3 + 0) * 2048;
        const float* Mr1 = m_rel + (size_t)(l * 3 + 1) * 2048;
        const float* Mr2 = m_rel + (size_t)(l * 3 + 2) * 2048;
        const float* pr0 = p_rel + (l * 3 + 0) * 8;
        const float* pr1 = p_rel + (l * 3 + 1) * 8;
        const float* pr2 = p_rel + (l * 3 + 2) * 8;
        const float* kFunc = pk + (size_t)kNStmt * kC;
        const float* vFunc = pv + (size_t)kNStmt * kC;

        // dst = stmt: relations 0 (src stmt) and 2 (src func)
        attn_kernel<1><<<kNStmt / 8, 256>>>(
            pq, pk, pv, pst + stOff[0], psrt + 0, Ar0, Mr0, pr0,
            kFunc, vFunc, pst + stOff[2], psrt + 2 * kE, Ar2, Mr2, pr2,
            pagg);
        // dst = func: relation 1 (src stmt)
        attn_kernel<0><<<kNFunc / 8, 256>>>(
            pq + (size_t)kNStmt * kC, pk, pv, pst + stOff[1], psrt + kE,
            Ar1, Mr1, pr1,
            nullptr, nullptr, nullptr, nullptr, nullptr, nullptr, nullptr,
            pagg + (size_t)kNStmt * kC);

        for (int t = 0; t < 2; ++t) {
            int mi = l * 2 + t;
            size_t xo = (size_t)toff[t] * kC;
            float* dst = (l == kL - 1) ? (out + xo) : (px + xo);
            tgemm<1,2,1><<<(tN[t] + 127) / 128, 256, TG_SMEM>>>(
                pagg + xo, pwt + (size_t)(14 + mi) * 16384, nullptr, nullptr,
                ab + mi * 128, nullptr, nullptr,
                px + xo, skip + mi,
                dst, nullptr, nullptr, tN[t]);
        }
    }
}

// round 7
// speedup vs baseline: 2.4022x; 1.0673x over previous
#include <cuda_runtime.h>
#include <cuda_fp16.h>
#include <cstdint>

// ---------------------------------------------------------------------------
// HGT forward. Node layout: stmt rows [0,100000), func rows [100000,150000).
// GEMMs: mma.sync tf32, merged stmt+func grids. k/v stored fp16 for the
// attention gather phase. Attention: CSR + warp-per-dst online softmax.
// ---------------------------------------------------------------------------
constexpr int kNStmt = 100000;
constexpr int kNFunc = 50000;
constexpr int kNTot  = 150000;
constexpr int kC = 128;
constexpr int kE = 200000;
constexpr int kL = 2;
constexpr int kT = 16;
constexpr int kGridS = (kNStmt + 127) / 128;            // 782
constexpr int kGridF = (kNFunc + 127) / 128;            // 391
constexpr int kGridAll = kGridS + kGridF;               // 1173

// Scratch (device globals: no allocation allowed)
__device__ float  g_e  [(size_t)kNTot * kC];
__device__ float  g_x  [(size_t)kNTot * kC];
__device__ float  g_q  [(size_t)kNTot * kC];
__device__ __half g_kh [(size_t)kNTot * kC];
__device__ __half g_vh [(size_t)kNTot * kC];
__device__ float  g_agg[(size_t)kNTot * kC];
__device__ float  g_wt [(size_t)18 * 16384];
__device__ int    g_tmp[500000];          // cnt[250000] then cur[250000]
__device__ int    g_starts[250003];       // per-rel offsets {0, 100001, 150002}
__device__ int    g_srt[600000];

__device__ __forceinline__ float totf32(float x) {
    uint32_t r;
    asm("cvt.rna.tf32.f32 %0, %1;" : "=r"(r) : "f"(x));
    return __uint_as_float(r);
}
__device__ __forceinline__ float gelu_t(float u) {
    return 0.5f * u * (1.f + tanhf(0.7978845608028654f * (u + 0.044715f * u * u * u)));
}

#define MMA_TF32(c, a, bv0, bv1) \
    asm volatile("mma.sync.aligned.m16n8k8.row.col.f32.tf32.tf32.f32 " \
        "{%0,%1,%2,%3}, {%4,%5,%6,%7}, {%8,%9}, {%0,%1,%2,%3};" \
        : "+f"((c)[0]), "+f"((c)[1]), "+f"((c)[2]), "+f"((c)[3]) \
        : "r"((a)[0]), "r"((a)[1]), "r"((a)[2]), "r"((a)[3]), "r"(bv0), "r"(bv1))

// ---------------------------------------------------------------------------
// Weight prep: W[k][n] -> fragment-ordered tf32
// ---------------------------------------------------------------------------
__global__ void __launch_bounds__(256) fragw(
        const float* __restrict__ lin_w, const float* __restrict__ kw,
        const float* __restrict__ qw, const float* __restrict__ vw,
        const float* __restrict__ aw, float* __restrict__ wt) {
    int m = blockIdx.x;
    const float* W = (m < 2)  ? lin_w + (size_t)m * 16384
                   : (m < 6)  ? kw + (size_t)(m - 2) * 16384
                   : (m < 10) ? qw + (size_t)(m - 6) * 16384
                   : (m < 14) ? vw + (size_t)(m - 10) * 16384
                              : aw + (size_t)(m - 14) * 16384;
    float* dst = wt + (size_t)m * 16384;
    for (int idx = threadIdx.x; idx < 16384; idx += 256) {
        int reg = idx & 1, lane = (idx >> 1) & 31, ks = (idx >> 6) & 15, nt = idx >> 10;
        int k = ks * 8 + (lane & 3) + reg * 4;
        int n = nt * 8 + (lane >> 2);
        dst[idx] = totf32(__ldg(&W[k * 128 + n]));
    }
}

// ---------------------------------------------------------------------------
// Merged-type tf32 GEMM. Blocks [0,kGridS) are stmt rows, rest func rows.
// A in smem; B fragments streamed via __ldg. HMASK bit j => output j is fp16.
// PRE: 0=none, 1=tanh-gelu.  POST: 0=none, 1=relu, 2=skip blend.
// ---------------------------------------------------------------------------
constexpr int TG_SMEM = 128 * 132 * 4;

template<int PRE, int POST, int NB, int HMASK>
__global__ void __launch_bounds__(256, 2) tgemm2(
        const float* __restrict__ A,
        const float* __restrict__ B00, const float* __restrict__ B01,
        const float* __restrict__ B02,
        const float* __restrict__ B10, const float* __restrict__ B11,
        const float* __restrict__ B12,
        const float* __restrict__ bb00, const float* __restrict__ bb01,
        const float* __restrict__ bb02,
        const float* __restrict__ bb10, const float* __restrict__ bb11,
        const float* __restrict__ bb12,
        const float* __restrict__ Xold,
        const float* __restrict__ skip0, const float* __restrict__ skip1,
        void* __restrict__ O0v, void* __restrict__ O1v, void* __restrict__ O2v)
{
    extern __shared__ float sm[];
    float* As = sm;                       // [128][132]
    uint32_t* Asu = (uint32_t*)As;

    int tid = threadIdx.x, wid = tid >> 5, lane = tid & 31;
    int warpM = wid & 3, warpN = wid >> 2;

    int b = blockIdx.x;
    bool tf = (b >= kGridS);
    int rowBase = tf ? (kNStmt + (b - kGridS) * 128) : b * 128;
    int Nend = tf ? kNTot : kNStmt;

    const float* Bfs[3] = {tf ? B10 : B00, tf ? B11 : B01, tf ? B12 : B02};
    const float* bss[3] = {tf ? bb10 : bb00, tf ? bb11 : bb01, tf ? bb12 : bb02};
    void* Os[3] = {O0v, O1v, O2v};

#pragma unroll 4
    for (int p = 0; p < 16; ++p) {
        int idx = p * 256 + tid;
        int r = idx >> 5, c4 = idx & 31;
        int n = rowBase + r;
        float4 v = make_float4(0.f, 0.f, 0.f, 0.f);
        if (n < Nend) v = __ldg((const float4*)(A + (size_t)n * 128 + c4 * 4));
        if (PRE == 1) {
            v.x = gelu_t(v.x); v.y = gelu_t(v.y); v.z = gelu_t(v.z); v.w = gelu_t(v.w);
        }
        v.x = totf32(v.x); v.y = totf32(v.y); v.z = totf32(v.z); v.w = totf32(v.w);
        *(float4*)&As[r * 132 + c4 * 4] = v;
    }
    __syncthreads();

    float gate = 1.f, og = 0.f;
    if (POST == 2) {
        float sv = __ldg(tf ? skip1 : skip0);
        gate = 1.f / (1.f + expf(-sv));
        og = 1.f - gate;
    }

#pragma unroll
    for (int j = 0; j < NB; ++j) {
        const float* Bf = Bfs[j];
        float acc[2][8][4];
#pragma unroll
        for (int mt = 0; mt < 2; ++mt)
#pragma unroll
            for (int nt = 0; nt < 8; ++nt)
#pragma unroll
                for (int i = 0; i < 4; ++i) acc[mt][nt][i] = 0.f;

#pragma unroll
        for (int ks = 0; ks < 16; ++ks) {
            uint32_t a[2][4];
#pragma unroll
            for (int mt = 0; mt < 2; ++mt) {
                int rb = warpM * 32 + mt * 16 + (lane >> 2);
                int cb = ks * 8 + (lane & 3);
                a[mt][0] = Asu[rb * 132 + cb];
                a[mt][1] = Asu[(rb + 8) * 132 + cb];
                a[mt][2] = Asu[rb * 132 + cb + 4];
                a[mt][3] = Asu[(rb + 8) * 132 + cb + 4];
            }
#pragma unroll
            for (int nt = 0; nt < 8; ++nt) {
                int ntA = warpN * 8 + nt;
                uint2 bv = __ldg((const uint2*)(Bf + ((ntA * 16 + ks) * 32 + lane) * 2));
#pragma unroll
                for (int mt = 0; mt < 2; ++mt)
                    MMA_TF32(acc[mt][nt], a[mt], bv.x, bv.y);
            }
        }

        int g = lane >> 2, t2 = (lane & 3) * 2;
#pragma unroll
        for (int mt = 0; mt < 2; ++mt) {
            int r0 = rowBase + warpM * 32 + mt * 16 + g;
#pragma unroll
            for (int nt = 0; nt < 8; ++nt) {
                int col = warpN * 64 + nt * 8 + t2;
                float bb0 = __ldg(&bss[j][col]), bb1 = __ldg(&bss[j][col + 1]);
                float o0 = acc[mt][nt][0] + bb0, o1 = acc[mt][nt][1] + bb1;
                float o2 = acc[mt][nt][2] + bb0, o3 = acc[mt][nt][3] + bb1;
                if (POST == 1) {
                    o0 = fmaxf(o0, 0.f); o1 = fmaxf(o1, 0.f);
                    o2 = fmaxf(o2, 0.f); o3 = fmaxf(o3, 0.f);
                }
                if (POST == 2) {
                    if (r0 < Nend) {
                        float2 x = *(const float2*)(Xold + (size_t)r0 * 128 + col);
                        o0 = gate * o0 + og * x.x; o1 = gate * o1 + og * x.y;
                    }
                    if (r0 + 8 < Nend) {
                        float2 x = *(const float2*)(Xold + (size_t)(r0 + 8) * 128 + col);
                        o2 = gate * o2 + og * x.x; o3 = gate * o3 + og * x.y;
                    }
                }
                if ((HMASK >> j) & 1) {
                    __half* Oh = (__half*)Os[j];
                    if (r0 < Nend)
                        *(__half2*)(Oh + (size_t)r0 * 128 + col) = __floats2half2_rn(o0, o1);
                    if (r0 + 8 < Nend)
                        *(__half2*)(Oh + (size_t)(r0 + 8) * 128 + col) = __floats2half2_rn(o2, o3);
                } else {
                    float* Of = (float*)Os[j];
                    if (r0 < Nend)
                        *(float2*)(Of + (size_t)r0 * 128 + col) = make_float2(o0, o1);
                    if (r0 + 8 < Nend)
                        *(float2*)(Of + (size_t)(r0 + 8) * 128 + col) = make_float2(o2, o3);
                }
            }
        }
    }
}

// ---------------------------------------------------------------------------
// Embedding: e[n,c] = relu(mean_t emb[tok[n,t], c])
// ---------------------------------------------------------------------------
__global__ void embed_kernel(const int* __restrict__ tok_s, const int* __restrict__ tok_f,
                             const float* __restrict__ emb, float* __restrict__ out) {
    int n = blockIdx.x;
    int c = threadIdx.x;
    const int* tok = (n < kNStmt) ? (tok_s + (size_t)n * kT)
                                  : (tok_f + (size_t)(n - kNStmt) * kT);
    float acc = 0.f;
#pragma unroll
    for (int i = 0; i < kT; ++i) {
        int t = __ldg(&tok[i]);
        acc += __ldg(&emb[(size_t)t * kC + c]);
    }
    acc *= (1.f / 16.f);
    out[(size_t)n * kC + c] = fmaxf(acc, 0.f);
}

// ---------------------------------------------------------------------------
// CSR build
// ---------------------------------------------------------------------------
__global__ void zero_int(int* __restrict__ p, int n) {
    int i = blockIdx.x * 256 + threadIdx.x;
    if (i < n) p[i] = 0;
}

__global__ void hist3(const int* __restrict__ d0, const int* __restrict__ d1,
                      const int* __restrict__ d2, int* __restrict__ cnt) {
    int r = blockIdx.y;
    const int* dst = (r == 0) ? d0 : (r == 1) ? d1 : d2;
    int off = (r == 0) ? 0 : (r == 1) ? kNStmt : kNStmt + kNFunc;
    int i = blockIdx.x * 256 + threadIdx.x;
    if (i < kE) atomicAdd(&cnt[off + __ldg(&dst[i])], 1);
}

__global__ void __launch_bounds__(1024) exscan3(const int* __restrict__ cnt,
                                                int* __restrict__ starts) {
    __shared__ int wsum[32];
    __shared__ int carry_s;
    const int cntOff[3] = {0, kNStmt, kNStmt + kNFunc};
    const int stOff[3]  = {0, kNStmt + 1, kNStmt + kNFunc + 2};
    const int ns[3]     = {kNStmt, kNFunc, kNStmt};
    int r = blockIdx.x;
    const int* c = cnt + cntOff[r];
    int* st = starts + stOff[r];
    int n = ns[r];
    int tid = threadIdx.x, lane = tid & 31, w = tid >> 5;
    if (tid == 0) carry_s = 0;
    __syncthreads();
    for (int base = 0; base < n; base += 1024) {
        int i = base + tid;
        int v = (i < n) ? c[i] : 0;
        int x = v;
#pragma unroll
        for (int o = 1; o < 32; o <<= 1) {
            int t = __shfl_up_sync(0xffffffffu, x, o);
            if (lane >= o) x += t;
        }
        if (lane == 31) wsum[w] = x;
        __syncthreads();
        if (w == 0) {
            int y = wsum[lane];
#pragma unroll
            for (int o = 1; o < 32; o <<= 1) {
                int t = __shfl_up_sync(0xffffffffu, y, o);
                if (lane >= o) y += t;
            }
            wsum[lane] = y;
        }
        __syncthreads();
        int incl = x + (w > 0 ? wsum[w - 1] : 0);
        int carry = carry_s;
        if (i < n) st[i] = carry + incl - v;
        __syncthreads();
        if (tid == 0) carry_s = carry + wsum[31];
        __syncthreads();
    }
    if (tid == 0) st[n] = carry_s;
}

__global__ void scat3(const int* __restrict__ s0, const int* __restrict__ d0,
                      const int* __restrict__ s1, const int* __restrict__ d1,
                      const int* __restrict__ s2, const int* __restrict__ d2,
                      const int* __restrict__ starts, int* __restrict__ cur,
                      int* __restrict__ out) {
    int r = blockIdx.y;
    const int* src = (r == 0) ? s0 : (r == 1) ? s1 : s2;
    const int* dst = (r == 0) ? d0 : (r == 1) ? d1 : d2;
    int cOff = (r == 0) ? 0 : (r == 1) ? kNStmt : kNStmt + kNFunc;
    int sOff = (r == 0) ? 0 : (r == 1) ? kNStmt + 1 : kNStmt + kNFunc + 2;
    int i = blockIdx.x * 256 + threadIdx.x;
    if (i < kE) {
        int d = __ldg(&dst[i]);
        int pos = __ldg(&starts[sOff + d]) + atomicAdd(&cur[cOff + d], 1);
        out[(size_t)r * kE + pos] = __ldg(&src[i]);
    }
}

// ---------------------------------------------------------------------------
// Fused attention. One warp per dst; lane = h*4+quarter. fp16 k/v gathers,
// software-pipelined edge loop, single launch for both node types.
// ---------------------------------------------------------------------------
__device__ __forceinline__ float4 attn_rel(
        int dn, int lane, float4 qv,
        const int* __restrict__ starts, const int* __restrict__ srcs,
        const __half* __restrict__ kb, const __half* __restrict__ vb,
        const float* __restrict__ Asq, const float* __restrict__ Ms, float pscale)
{
    float4 qa = make_float4(0.f, 0.f, 0.f, 0.f);
#pragma unroll
    for (int g = 0; g < 4; ++g) {
        int sl = (lane & ~3) | g;
        float q0 = __shfl_sync(0xffffffffu, qv.x, sl);
        float q1 = __shfl_sync(0xffffffffu, qv.y, sl);
        float q2 = __shfl_sync(0xffffffffu, qv.z, sl);
        float q3 = __shfl_sync(0xffffffffu, qv.w, sl);
        float4 A0 = *(const float4*)&Asq[(g * 4 + 0) * 128 + lane * 4];
        float4 A1 = *(const float4*)&Asq[(g * 4 + 1) * 128 + lane * 4];
        float4 A2 = *(const float4*)&Asq[(g * 4 + 2) * 128 + lane * 4];
        float4 A3 = *(const float4*)&Asq[(g * 4 + 3) * 128 + lane * 4];
        qa.x += q0 * A0.x + q1 * A1.x + q2 * A2.x + q3 * A3.x;
        qa.y += q0 * A0.y + q1 * A1.y + q2 * A2.y + q3 * A3.y;
        qa.z += q0 * A0.z + q1 * A1.z + q2 * A2.z + q3 * A3.z;
        qa.w += q0 * A0.w + q1 * A1.w + q2 * A2.w + q3 * A3.w;
    }
    qa.x *= pscale; qa.y *= pscale; qa.z *= pscale; qa.w *= pscale;

    int e0 = __ldg(&starts[dn]), e1 = __ldg(&starts[dn + 1]);
    float m = -INFINITY, s = 0.f;
    float4 acc = make_float4(0.f, 0.f, 0.f, 0.f);

    if (e0 < e1) {
        int src = __ldg(&srcs[e0]);
        uint2 uk = __ldg((const uint2*)(kb + (size_t)src * 128) + lane);
        uint2 uv = __ldg((const uint2*)(vb + (size_t)src * 128) + lane);
        for (int e = e0; ; ) {
            int ne = e + 1;
            bool more = ne < e1;
            int nsrc = 0;
            uint2 nuk, nuv;
            if (more) {
                nsrc = __ldg(&srcs[ne]);
                nuk = __ldg((const uint2*)(kb + (size_t)nsrc * 128) + lane);
                nuv = __ldg((const uint2*)(vb + (size_t)nsrc * 128) + lane);
            }
            float2 k01 = __half22float2(*(__half2*)&uk.x);
            float2 k23 = __half22float2(*(__half2*)&uk.y);
            float2 v01 = __half22float2(*(__half2*)&uv.x);
            float2 v23 = __half22float2(*(__half2*)&uv.y);
            float lg = qa.x * k01.x + qa.y * k01.y + qa.z * k23.x + qa.w * k23.y;
            lg += __shfl_xor_sync(0xffffffffu, lg, 1);
            lg += __shfl_xor_sync(0xffffffffu, lg, 2);
            float nm = fmaxf(m, lg);
            float corr = __expf(m - nm);
            float p = __expf(lg - nm);
            s = s * corr + p;
            acc.x = acc.x * corr + p * v01.x;
            acc.y = acc.y * corr + p * v01.y;
            acc.z = acc.z * corr + p * v23.x;
            acc.w = acc.w * corr + p * v23.y;
            m = nm;
            if (!more) break;
            e = ne; uk = nuk; uv = nuv;
        }
    }
    float inv = 1.f / (s + 1e-16f);
    float4 fin = make_float4(acc.x * inv, acc.y * inv, acc.z * inv, acc.w * inv);

    float4 ov = make_float4(0.f, 0.f, 0.f, 0.f);
#pragma unroll
    for (int g = 0; g < 4; ++g) {
        int sl = (lane & ~3) | g;
        float d0 = __shfl_sync(0xffffffffu, fin.x, sl);
        float d1 = __shfl_sync(0xffffffffu, fin.y, sl);
        float d2 = __shfl_sync(0xffffffffu, fin.z, sl);
        float d3 = __shfl_sync(0xffffffffu, fin.w, sl);
        float4 M0 = *(const float4*)&Ms[(g * 4 + 0) * 128 + lane * 4];
        float4 M1 = *(const float4*)&Ms[(g * 4 + 1) * 128 + lane * 4];
        float4 M2 = *(const float4*)&Ms[(g * 4 + 2) * 128 + lane * 4];
        float4 M3 = *(const float4*)&Ms[(g * 4 + 3) * 128 + lane * 4];
        ov.x += d0 * M0.x + d1 * M1.x + d2 * M2.x + d3 * M3.x;
        ov.y += d0 * M0.y + d1 * M1.y + d2 * M2.y + d3 * M3.y;
        ov.z += d0 * M0.z + d1 * M1.z + d2 * M2.z + d3 * M3.z;
        ov.w += d0 * M0.w + d1 * M1.w + d2 * M2.w + d3 * M3.w;
    }
    return ov;
}

constexpr int kAttnGridS = kNStmt / 8;   // 12500
constexpr int kAttnGridF = kNFunc / 8;   // 6250

__global__ void __launch_bounds__(256) attn_all(
        const float* __restrict__ q,
        const __half* __restrict__ kb, const __half* __restrict__ vb,
        const int* __restrict__ st, const int* __restrict__ srt,
        const float* __restrict__ Al, const float* __restrict__ Ml,
        const float* __restrict__ pl,
        float* __restrict__ agg)
{
    __shared__ float As0[2048], Ms0[2048], As2[2048], Ms2[2048];
    int tid = threadIdx.x;
    int b = blockIdx.x;
    bool tf = (b >= kAttnGridS);
    for (int i = tid; i < 2048; i += 256) {
        int a = i >> 7, he = i & 127, h = he >> 4, d = he & 15;
        if (!tf) {
            As0[i] = __ldg(&Al[(h * 16 + d) * 16 + a]);
            Ms0[i] = __ldg(&Ml[(h * 16 + a) * 16 + d]);
            As2[i] = __ldg(&Al[2 * 2048 + (h * 16 + d) * 16 + a]);
            Ms2[i] = __ldg(&Ml[2 * 2048 + (h * 16 + a) * 16 + d]);
        } else {
            As0[i] = __ldg(&Al[2048 + (h * 16 + d) * 16 + a]);
            Ms0[i] = __ldg(&Ml[2048 + (h * 16 + a) * 16 + d]);
        }
    }
    __syncthreads();
    int wid = tid >> 5, lane = tid & 31;
    int h = lane >> 2;
    if (!tf) {
        int dn = b * 8 + wid;
        float4 qv = __ldg((const float4*)(q + (size_t)dn * 128) + lane);
        float4 r = attn_rel(dn, lane, qv, st, srt, kb, vb, As0, Ms0,
                            __ldg(&pl[h]) * 0.25f);
        float4 r2 = attn_rel(dn, lane, qv, st + (kNStmt + kNFunc + 2), srt + 2 * kE,
                             kb + (size_t)kNStmt * 128, vb + (size_t)kNStmt * 128,
                             As2, Ms2, __ldg(&pl[16 + h]) * 0.25f);
        r.x += r2.x; r.y += r2.y; r.z += r2.z; r.w += r2.w;
        ((float4*)(agg + (size_t)dn * 128))[lane] = r;
    } else {
        int dn = (b - kAttnGridS) * 8 + wid;
        int qrow = kNStmt + dn;
        float4 qv = __ldg((const float4*)(q + (size_t)qrow * 128) + lane);
        float4 r = attn_rel(dn, lane, qv, st + (kNStmt + 1), srt + kE,
                            kb, vb, As0, Ms0, __ldg(&pl[8 + h]) * 0.25f);
        ((float4*)(agg + (size_t)qrow * 128))[lane] = r;
    }
}

// ---------------------------------------------------------------------------
// Orchestration
// ---------------------------------------------------------------------------
extern "C" void kernel_launch(void* const* d_in, const int* in_sizes, int n_in,
                              void* d_out, int out_size) {
    const int* tok_s = (const int*)d_in[0];
    const int* tok_f = (const int*)d_in[1];
    const int* e0s = (const int*)d_in[2], *e0d = (const int*)d_in[3];
    const int* e1s = (const int*)d_in[4], *e1d = (const int*)d_in[5];
    const int* e2s = (const int*)d_in[6], *e2d = (const int*)d_in[7];
    const float* emb   = (const float*)d_in[8];
    const float* lin_w = (const float*)d_in[9];
    const float* lin_b = (const float*)d_in[10];
    const float* kw = (const float*)d_in[11];
    const float* kb = (const float*)d_in[12];
    const float* qw = (const float*)d_in[13];
    const float* qb = (const float*)d_in[14];
    const float* vw = (const float*)d_in[15];
    const float* vb = (const float*)d_in[16];
    const float* aw = (const float*)d_in[17];
    const float* ab = (const float*)d_in[18];
    const float* skip  = (const float*)d_in[19];
    const float* a_rel = (const float*)d_in[20];
    const float* m_rel = (const float*)d_in[21];
    const float* p_rel = (const float*)d_in[22];
    float* out = (float*)d_out;

    float *pe, *px, *pq, *pagg, *pwt;
    __half *pkh, *pvh;
    int *ptmp, *pst, *psrt;
    cudaGetSymbolAddress((void**)&pe,   g_e);
    cudaGetSymbolAddress((void**)&px,   g_x);
    cudaGetSymbolAddress((void**)&pq,   g_q);
    cudaGetSymbolAddress((void**)&pkh,  g_kh);
    cudaGetSymbolAddress((void**)&pvh,  g_vh);
    cudaGetSymbolAddress((void**)&pagg, g_agg);
    cudaGetSymbolAddress((void**)&pwt,  g_wt);
    cudaGetSymbolAddress((void**)&ptmp, g_tmp);
    cudaGetSymbolAddress((void**)&pst,  g_starts);
    cudaGetSymbolAddress((void**)&psrt, g_srt);

    cudaFuncSetAttribute(tgemm2<0,1,1,0>, cudaFuncAttributeMaxDynamicSharedMemorySize, TG_SMEM);
    cudaFuncSetAttribute(tgemm2<0,0,3,5>, cudaFuncAttributeMaxDynamicSharedMemorySize, TG_SMEM);
    cudaFuncSetAttribute(tgemm2<1,2,1,0>, cudaFuncAttributeMaxDynamicSharedMemorySize, TG_SMEM);

    int egrid = (kE + 255) / 256;

    // CSR build
    zero_int<<<(500000 + 255) / 256, 256>>>(ptmp, 500000);
    hist3<<<dim3(egrid, 3), 256>>>(e0d, e1d, e2d, ptmp);
    exscan3<<<3, 1024>>>(ptmp, pst);
    scat3<<<dim3(egrid, 3), 256>>>(e0s, e0d, e1s, e1d, e2s, e2d,
                                   pst, ptmp + 250000, psrt);

    // Weight prep + embedding + input linear (relu)
    fragw<<<18, 256>>>(lin_w, kw, qw, vw, aw, pwt);
    embed_kernel<<<kNTot, 128>>>(tok_s, tok_f, emb, pe);
    tgemm2<0,1,1,0><<<kGridAll, 256, TG_SMEM>>>(
        pe, pwt, nullptr, nullptr, pwt + 16384, nullptr, nullptr,
        lin_b, nullptr, nullptr, lin_b + 128, nullptr, nullptr,
        nullptr, nullptr, nullptr, px, nullptr, nullptr);

    for (int l = 0; l < kL; ++l) {
        int m0 = l * 2, m1 = l * 2 + 1;
        // kqv: outputs k (fp16), q (fp32), v (fp16)
        tgemm2<0,0,3,5><<<kGridAll, 256, TG_SMEM>>>(
            px,
            pwt + (size_t)(2 + m0) * 16384, pwt + (size_t)(6 + m0) * 16384,
            pwt + (size_t)(10 + m0) * 16384,
            pwt + (size_t)(2 + m1) * 16384, pwt + (size_t)(6 + m1) * 16384,
            pwt + (size_t)(10 + m1) * 16384,
            kb + m0 * 128, qb + m0 * 128, vb + m0 * 128,
            kb + m1 * 128, qb + m1 * 128, vb + m1 * 128,
            nullptr, nullptr, nullptr,
            pkh, pq, pvh);

        attn_all<<<kAttnGridS + kAttnGridF, 256>>>(
            pq, pkh, pvh, pst, psrt,
            a_rel + (size_t)l * 3 * 2048, m_rel + (size_t)l * 3 * 2048,
            p_rel + l * 24, pagg);

        float* dst = (l == kL - 1) ? out : px;
        tgemm2<1,2,1,0><<<kGridAll, 256, TG_SMEM>>>(
            pagg,
            pwt + (size_t)(14 + m0) * 16384, nullptr, nullptr,
            pwt + (size_t)(14 + m1) * 16384, nullptr, nullptr,
            ab + m0 * 128, nullptr, nullptr, ab + m1 * 128, nullptr, nullptr,
            px, skip + m0, skip + m1,
            dst, nullptr, nullptr);
    }
}

// round 9
// speedup vs baseline: 3.0555x; 1.2720x over previous
#include <cuda_runtime.h>
#include <cuda_fp16.h>
#include <cstdint>

// ---------------------------------------------------------------------------
// HGT forward. Node layout: stmt rows [0,100000), func rows [100000,150000).
// Relation transforms folded into GEMM weights (qa = q@A-fold*p, v_r = v@M-fold).
// Attention = pure CSR gather + online softmax. Embed fused into input GEMM.
// ---------------------------------------------------------------------------
constexpr int kNStmt = 100000;
constexpr int kNFunc = 50000;
constexpr int kNTot  = 150000;
constexpr int kC = 128;
constexpr int kE = 200000;
constexpr int kL = 2;
constexpr int kGridS = (kNStmt + 127) / 128;            // 782
constexpr int kGridF = (kNFunc + 127) / 128;            // 391
constexpr int kGridAll = kGridS + kGridF;               // 1173

// Scratch (device globals: no allocation allowed)
__device__ float  g_x  [(size_t)kNTot * kC];
__device__ float  g_qa [(size_t)kNTot * kC];   // stmt: qa0, func: qa1
__device__ float  g_qa2[(size_t)kNStmt * kC];  // stmt: qa2
__device__ __half g_kh [(size_t)kNTot * kC];
__device__ __half g_vA [(size_t)kNTot * kC];   // stmt: v@M0, func: v@M2
__device__ __half g_vB [(size_t)kNStmt * kC];  // stmt: v@M1
__device__ float  g_agg[(size_t)kNTot * kC];
__device__ float  g_wt [(size_t)22 * 16384];   // fragment-ordered tf32 weights
__device__ float  g_tb [12 * 128];             // transformed biases
__device__ int    g_tmp[500000];               // cnt[250000] then cur[250000]
__device__ int    g_starts[250003];
__device__ int    g_srt[600000];

__device__ __forceinline__ float totf32(float x) {
    uint32_t r;
    asm("cvt.rna.tf32.f32 %0, %1;" : "=r"(r) : "f"(x));
    return __uint_as_float(r);
}
__device__ __forceinline__ float gelu_t(float u) {
    return 0.5f * u * (1.f + tanhf(0.7978845608028654f * (u + 0.044715f * u * u * u)));
}

#define MMA_TF32(c, a, bv0, bv1) \
    asm volatile("mma.sync.aligned.m16n8k8.row.col.f32.tf32.tf32.f32 " \
        "{%0,%1,%2,%3}, {%4,%5,%6,%7}, {%8,%9}, {%0,%1,%2,%3};" \
        : "+f"((c)[0]), "+f"((c)[1]), "+f"((c)[2]), "+f"((c)[3]) \
        : "r"((a)[0]), "r"((a)[1]), "r"((a)[2]), "r"((a)[3]), "r"(bv0), "r"(bv1))

// ---------------------------------------------------------------------------
// prep_mats: build all fragment-ordered tf32 weight matrices.
// Slots: 0,1 = lin; 2-5 = kw(mi); 6-9 = aw(mi);
//        10+l*6+{0:v0,1:v1,2:v2,3:qa0,4:qa2,5:qa1}
// v fold:  out[h,e] = sum_d W[.,h*16+d] * M[h,d,e]     (apply M to v)
// qa fold: out[h,d] = sum_e W[.,h*16+e] * A[h,d,e]     (logit = qa . k)
// Frag layout: idx=((nt*16+ks)*32+lane)*2+reg; k=ks*8+(lane&3)+reg*4, n=nt*8+(lane>>2)
// ---------------------------------------------------------------------------
__global__ void __launch_bounds__(256) prep_mats(
        const float* __restrict__ lin_w, const float* __restrict__ kw,
        const float* __restrict__ qw, const float* __restrict__ vw,
        const float* __restrict__ aw,
        const float* __restrict__ a_rel, const float* __restrict__ m_rel,
        const float* __restrict__ p_rel,
        const float* __restrict__ qb, const float* __restrict__ vb,
        float* __restrict__ wt, float* __restrict__ tb)
{
    int b = blockIdx.x, tid = threadIdx.x;
    float* dst = wt + (size_t)b * 16384;
    if (b < 10) {
        const float* W = (b < 2) ? lin_w + (size_t)b * 16384
                       : (b < 6) ? kw + (size_t)(b - 2) * 16384
                                 : aw + (size_t)(b - 6) * 16384;
        for (int i = tid; i < 16384; i += 256) {
            int reg = i & 1, lane = (i >> 1) & 31, ks = (i >> 6) & 15, nt = i >> 10;
            int k = ks * 8 + (lane & 3) + reg * 4;
            int n = nt * 8 + (lane >> 2);
            dst[i] = totf32(__ldg(&W[k * 128 + n]));
        }
        return;
    }
    int c = b - 10, l = c / 6, idx = c % 6;
    const int srcT[3] = {0, 0, 1}, dstT[3] = {0, 1, 0};
    int rel = (idx < 3) ? idx : (idx == 3 ? 0 : (idx == 4 ? 2 : 1));
    bool isQA = (idx >= 3);
    const float* W  = isQA ? qw + (size_t)(l * 2 + dstT[rel]) * 16384
                           : vw + (size_t)(l * 2 + srcT[rel]) * 16384;
    const float* T  = (isQA ? a_rel : m_rel) + (size_t)(l * 3 + rel) * 2048;
    const float* Bi = isQA ? qb + (l * 2 + dstT[rel]) * 128
                           : vb + (l * 2 + srcT[rel]) * 128;
    __shared__ float Ts[2048];
    __shared__ float sc[8];
    for (int i = tid; i < 2048; i += 256) Ts[i] = __ldg(&T[i]);
    if (tid < 8) sc[tid] = isQA ? __ldg(&p_rel[(l * 3 + rel) * 8 + tid]) * 0.25f : 1.f;
    __syncthreads();
    for (int i = tid; i < 16384; i += 256) {
        int reg = i & 1, lane = (i >> 1) & 31, ks = (i >> 6) & 15, nt = i >> 10;
        int k = ks * 8 + (lane & 3) + reg * 4;
        int n = nt * 8 + (lane >> 2);
        int h = n >> 4, j = n & 15;   // output within-head index
        float s = 0.f;
        if (isQA) {
#pragma unroll
            for (int d = 0; d < 16; ++d)   // sum over A's last index (e)
                s += __ldg(&W[k * 128 + h * 16 + d]) * Ts[h * 256 + j * 16 + d];
        } else {
#pragma unroll
            for (int d = 0; d < 16; ++d)   // sum over M's middle index (d)
                s += __ldg(&W[k * 128 + h * 16 + d]) * Ts[h * 256 + d * 16 + j];
        }
        dst[i] = totf32(s * sc[h]);
    }
    if (tid < 128) {
        int h = tid >> 4, j = tid & 15;
        float s = 0.f;
        if (isQA) {
#pragma unroll
            for (int d = 0; d < 16; ++d)
                s += __ldg(&Bi[h * 16 + d]) * Ts[h * 256 + j * 16 + d];
        } else {
#pragma unroll
            for (int d = 0; d < 16; ++d)
                s += __ldg(&Bi[h * 16 + d]) * Ts[h * 256 + d * 16 + j];
        }
        tb[c * 128 + tid] = s * sc[h];
    }
}

// ---------------------------------------------------------------------------
// Shared GEMM mainloop pieces
// ---------------------------------------------------------------------------
constexpr int TG_SMEM = 128 * 132 * 4;

__device__ __forceinline__ void gemm_tile(
        const uint32_t* Asu, const float* __restrict__ Bf,
        int warpM, int warpN, int lane, float acc[2][8][4])
{
#pragma unroll
    for (int mt = 0; mt < 2; ++mt)
#pragma unroll
        for (int nt = 0; nt < 8; ++nt)
#pragma unroll
            for (int i = 0; i < 4; ++i) acc[mt][nt][i] = 0.f;
#pragma unroll
    for (int ks = 0; ks < 16; ++ks) {
        uint2 bv[8];
#pragma unroll
        for (int nt = 0; nt < 8; ++nt) {
            int ntA = warpN * 8 + nt;
            bv[nt] = __ldg((const uint2*)(Bf + ((ntA * 16 + ks) * 32 + lane) * 2));
        }
        uint32_t a[2][4];
#pragma unroll
        for (int mt = 0; mt < 2; ++mt) {
            int rb = warpM * 32 + mt * 16 + (lane >> 2);
            int cb = ks * 8 + (lane & 3);
            a[mt][0] = Asu[rb * 132 + cb];
            a[mt][1] = Asu[(rb + 8) * 132 + cb];
            a[mt][2] = Asu[rb * 132 + cb + 4];
            a[mt][3] = Asu[(rb + 8) * 132 + cb + 4];
        }
#pragma unroll
        for (int nt = 0; nt < 8; ++nt)
#pragma unroll
            for (int mt = 0; mt < 2; ++mt)
                MMA_TF32(acc[mt][nt], a[mt], bv[nt].x, bv[nt].y);
    }
}

// ---------------------------------------------------------------------------
// tgemm1: single-output GEMM (input or output projection), merged type grid.
// PRE: 1=tanh-gelu, 2=embed(mean+relu).  POST: 1=relu, 2=skip blend.
// ---------------------------------------------------------------------------
template<int PRE, int POST>
__global__ void __launch_bounds__(256, 2) tgemm1(
        const float* __restrict__ A,
        const int* __restrict__ tok_s, const int* __restrict__ tok_f,
        const float* __restrict__ emb,
        const float* __restrict__ B0, const float* __restrict__ B1,
        const float* __restrict__ b0, const float* __restrict__ b1,
        const float* __restrict__ Xold,
        const float* __restrict__ skip0, const float* __restrict__ skip1,
        float* __restrict__ Out)
{
    extern __shared__ float sm[];
    float* As = sm;
    uint32_t* Asu = (uint32_t*)As;
    int tid = threadIdx.x, wid = tid >> 5, lane = tid & 31;
    int warpM = wid & 3, warpN = wid >> 2;
    int b = blockIdx.x;
    bool tf = (b >= kGridS);
    int rowBase = tf ? (kNStmt + (b - kGridS) * 128) : b * 128;
    int Nend = tf ? kNTot : kNStmt;
    const float* Bf = tf ? B1 : B0;
    const float* bs = tf ? b1 : b0;

#pragma unroll 2
    for (int p = 0; p < 16; ++p) {
        int idx = p * 256 + tid;
        int r = idx >> 5, c4 = idx & 31;
        int n = rowBase + r;
        float4 v = make_float4(0.f, 0.f, 0.f, 0.f);
        if (n < Nend) {
            if (PRE == 2) {
                const int* tok = tf ? tok_f + (size_t)(n - kNStmt) * 16
                                    : tok_s + (size_t)n * 16;
#pragma unroll
                for (int i = 0; i < 16; ++i) {
                    int t = __ldg(&tok[i]);
                    float4 e4 = __ldg((const float4*)(emb + (size_t)t * 128) + c4);
                    v.x += e4.x; v.y += e4.y; v.z += e4.z; v.w += e4.w;
                }
                v.x = fmaxf(v.x * (1.f / 16.f), 0.f);
                v.y = fmaxf(v.y * (1.f / 16.f), 0.f);
                v.z = fmaxf(v.z * (1.f / 16.f), 0.f);
                v.w = fmaxf(v.w * (1.f / 16.f), 0.f);
            } else {
                v = __ldg((const float4*)(A + (size_t)n * 128 + c4 * 4));
                if (PRE == 1) {
                    v.x = gelu_t(v.x); v.y = gelu_t(v.y);
                    v.z = gelu_t(v.z); v.w = gelu_t(v.w);
                }
            }
        }
        v.x = totf32(v.x); v.y = totf32(v.y); v.z = totf32(v.z); v.w = totf32(v.w);
        *(float4*)&As[r * 132 + c4 * 4] = v;
    }
    __syncthreads();

    float gate = 1.f, og = 0.f;
    if (POST == 2) {
        float sv = __ldg(tf ? skip1 : skip0);
        gate = 1.f / (1.f + expf(-sv));
        og = 1.f - gate;
    }

    float acc[2][8][4];
    gemm_tile(Asu, Bf, warpM, warpN, lane, acc);

    int g = lane >> 2, t2 = (lane & 3) * 2;
#pragma unroll
    for (int mt = 0; mt < 2; ++mt) {
        int r0 = rowBase + warpM * 32 + mt * 16 + g;
#pragma unroll
        for (int nt = 0; nt < 8; ++nt) {
            int col = warpN * 64 + nt * 8 + t2;
            float bb0 = __ldg(&bs[col]), bb1 = __ldg(&bs[col + 1]);
            float o0 = acc[mt][nt][0] + bb0, o1 = acc[mt][nt][1] + bb1;
            float o2 = acc[mt][nt][2] + bb0, o3 = acc[mt][nt][3] + bb1;
            if (POST == 1) {
                o0 = fmaxf(o0, 0.f); o1 = fmaxf(o1, 0.f);
                o2 = fmaxf(o2, 0.f); o3 = fmaxf(o3, 0.f);
            }
            if (POST == 2) {
                if (r0 < Nend) {
                    float2 x = *(const float2*)(Xold + (size_t)r0 * 128 + col);
                    o0 = gate * o0 + og * x.x; o1 = gate * o1 + og * x.y;
                }
                if (r0 + 8 < Nend) {
                    float2 x = *(const float2*)(Xold + (size_t)(r0 + 8) * 128 + col);
                    o2 = gate * o2 + og * x.x; o3 = gate * o3 + og * x.y;
                }
            }
            if (r0 < Nend)
                *(float2*)(Out + (size_t)r0 * 128 + col) = make_float2(o0, o1);
            if (r0 + 8 < Nend)
                *(float2*)(Out + (size_t)(r0 + 8) * 128 + col) = make_float2(o2, o3);
        }
    }
}

// ---------------------------------------------------------------------------
// tgemm_kqv: 5 outputs. j: 0=k(h16) 1=vA(h16) 2=vB(h16,stmt) 3=qa(f32) 4=qa2(f32,stmt)
// func blocks skip j=2,4 (their vA=v2, qa=qa1).
// ---------------------------------------------------------------------------
struct KqvP {
    const float* B[2][5];
    const float* bs[2][5];
};

__global__ void __launch_bounds__(256, 2) tgemm_kqv(
        const float* __restrict__ A, KqvP P,
        __half* __restrict__ Ok, __half* __restrict__ OvA, __half* __restrict__ OvB,
        float* __restrict__ Oqa, float* __restrict__ Oqa2)
{
    extern __shared__ float sm[];
    float* As = sm;
    uint32_t* Asu = (uint32_t*)As;
    int tid = threadIdx.x, wid = tid >> 5, lane = tid & 31;
    int warpM = wid & 3, warpN = wid >> 2;
    int b = blockIdx.x;
    bool tf = (b >= kGridS);
    int rowBase = tf ? (kNStmt + (b - kGridS) * 128) : b * 128;
    int Nend = tf ? kNTot : kNStmt;
    int ti = tf ? 1 : 0;

#pragma unroll 4
    for (int p = 0; p < 16; ++p) {
        int idx = p * 256 + tid;
        int r = idx >> 5, c4 = idx & 31;
        int n = rowBase + r;
        float4 v = make_float4(0.f, 0.f, 0.f, 0.f);
        if (n < Nend) v = __ldg((const float4*)(A + (size_t)n * 128 + c4 * 4));
        v.x = totf32(v.x); v.y = totf32(v.y); v.z = totf32(v.z); v.w = totf32(v.w);
        *(float4*)&As[r * 132 + c4 * 4] = v;
    }
    __syncthreads();

    int g = lane >> 2, t2 = (lane & 3) * 2;
#pragma unroll
    for (int j = 0; j < 5; ++j) {
        if (tf && (j == 2 || j == 4)) continue;
        float acc[2][8][4];
        gemm_tile(Asu, P.B[ti][j], warpM, warpN, lane, acc);
        const float* bs = P.bs[ti][j];
#pragma unroll
        for (int mt = 0; mt < 2; ++mt) {
            int r0 = rowBase + warpM * 32 + mt * 16 + g;
#pragma unroll
            for (int nt = 0; nt < 8; ++nt) {
                int col = warpN * 64 + nt * 8 + t2;
                float bb0 = __ldg(&bs[col]), bb1 = __ldg(&bs[col + 1]);
                float o0 = acc[mt][nt][0] + bb0, o1 = acc[mt][nt][1] + bb1;
                float o2 = acc[mt][nt][2] + bb0, o3 = acc[mt][nt][3] + bb1;
                if (j < 3) {
                    __half* Oh = (j == 0) ? Ok : (j == 1) ? OvA : OvB;
                    if (r0 < Nend)
                        *(__half2*)(Oh + (size_t)r0 * 128 + col) = __floats2half2_rn(o0, o1);
                    if (r0 + 8 < Nend)
                        *(__half2*)(Oh + (size_t)(r0 + 8) * 128 + col) = __floats2half2_rn(o2, o3);
                } else {
                    float* Of = (j == 3) ? Oqa : Oqa2;
                    if (r0 < Nend)
                        *(float2*)(Of + (size_t)r0 * 128 + col) = make_float2(o0, o1);
                    if (r0 + 8 < Nend)
                        *(float2*)(Of + (size_t)(r0 + 8) * 128 + col) = make_float2(o2, o3);
                }
            }
        }
    }
}

// ---------------------------------------------------------------------------
// CSR build
// ---------------------------------------------------------------------------
__global__ void zero_int(int* __restrict__ p, int n) {
    int i = blockIdx.x * 256 + threadIdx.x;
    if (i < n) p[i] = 0;
}

__global__ void hist3(const int* __restrict__ d0, const int* __restrict__ d1,
                      const int* __restrict__ d2, int* __restrict__ cnt) {
    int r = blockIdx.y;
    const int* dst = (r == 0) ? d0 : (r == 1) ? d1 : d2;
    int off = (r == 0) ? 0 : (r == 1) ? kNStmt : kNStmt + kNFunc;
    int i = blockIdx.x * 256 + threadIdx.x;
    if (i < kE) atomicAdd(&cnt[off + __ldg(&dst[i])], 1);
}

__global__ void __launch_bounds__(1024) exscan3(const int* __restrict__ cnt,
                                                int* __restrict__ starts) {
    __shared__ int wsum[32];
    __shared__ int carry_s;
    const int cntOff[3] = {0, kNStmt, kNStmt + kNFunc};
    const int stOff[3]  = {0, kNStmt + 1, kNStmt + kNFunc + 2};
    const int ns[3]     = {kNStmt, kNFunc, kNStmt};
    int r = blockIdx.x;
    const int* c = cnt + cntOff[r];
    int* st = starts + stOff[r];
    int n = ns[r];
    int tid = threadIdx.x, lane = tid & 31, w = tid >> 5;
    if (tid == 0) carry_s = 0;
    __syncthreads();
    for (int base = 0; base < n; base += 1024) {
        int i = base + tid;
        int v = (i < n) ? c[i] : 0;
        int x = v;
#pragma unroll
        for (int o = 1; o < 32; o <<= 1) {
            int t = __shfl_up_sync(0xffffffffu, x, o);
            if (lane >= o) x += t;
        }
        if (lane == 31) wsum[w] = x;
        __syncthreads();
        if (w == 0) {
            int y = wsum[lane];
#pragma unroll
            for (int o = 1; o < 32; o <<= 1) {
                int t = __shfl_up_sync(0xffffffffu, y, o);
                if (lane >= o) y += t;
            }
            wsum[lane] = y;
        }
        __syncthreads();
        int incl = x + (w > 0 ? wsum[w - 1] : 0);
        int carry = carry_s;
        if (i < n) st[i] = carry + incl - v;
        __syncthreads();
        if (tid == 0) carry_s = carry + wsum[31];
        __syncthreads();
    }
    if (tid == 0) st[n] = carry_s;
}

__global__ void scat3(const int* __restrict__ s0, const int* __restrict__ d0,
                      const int* __restrict__ s1, const int* __restrict__ d1,
                      const int* __restrict__ s2, const int* __restrict__ d2,
                      const int* __restrict__ starts, int* __restrict__ cur,
                      int* __restrict__ out) {
    int r = blockIdx.y;
    const int* src = (r == 0) ? s0 : (r == 1) ? s1 : s2;
    const int* dst = (r == 0) ? d0 : (r == 1) ? d1 : d2;
    int cOff = (r == 0) ? 0 : (r == 1) ? kNStmt : kNStmt + kNFunc;
    int sOff = (r == 0) ? 0 : (r == 1) ? kNStmt + 1 : kNStmt + kNFunc + 2;
    int i = blockIdx.x * 256 + threadIdx.x;
    if (i < kE) {
        int d = __ldg(&dst[i]);
        int pos = __ldg(&starts[sOff + d]) + atomicAdd(&cur[cOff + d], 1);
        out[(size_t)r * kE + pos] = __ldg(&src[i]);
    }
}

// ---------------------------------------------------------------------------
// Attention: pure gather + online softmax. Warp per dst, lane = 4 channels.
// ---------------------------------------------------------------------------
__device__ __forceinline__ float4 attn_edges(
        int e0, int e1, int lane, float4 qa,
        const int* __restrict__ srcs,
        const __half* __restrict__ kb, const __half* __restrict__ vb)
{
    float m = -INFINITY, s = 0.f;
    float4 acc = make_float4(0.f, 0.f, 0.f, 0.f);
    if (e0 < e1) {
        int src = __ldg(&srcs[e0]);
        uint2 uk = __ldg((const uint2*)(kb + (size_t)src * 128) + lane);
        uint2 uv = __ldg((const uint2*)(vb + (size_t)src * 128) + lane);
        for (int e = e0; ; ) {
            int ne = e + 1;
            bool more = ne < e1;
            uint2 nuk, nuv;
            if (more) {
                int nsrc = __ldg(&srcs[ne]);
                nuk = __ldg((const uint2*)(kb + (size_t)nsrc * 128) + lane);
                nuv = __ldg((const uint2*)(vb + (size_t)nsrc * 128) + lane);
            }
            float2 k01 = __half22float2(*(__half2*)&uk.x);
            float2 k23 = __half22float2(*(__half2*)&uk.y);
            float2 v01 = __half22float2(*(__half2*)&uv.x);
            float2 v23 = __half22float2(*(__half2*)&uv.y);
            float lg = qa.x * k01.x + qa.y * k01.y + qa.z * k23.x + qa.w * k23.y;
            lg += __shfl_xor_sync(0xffffffffu, lg, 1);
            lg += __shfl_xor_sync(0xffffffffu, lg, 2);
            float nm = fmaxf(m, lg);
            float corr = __expf(m - nm);
            float p = __expf(lg - nm);
            s = s * corr + p;
            acc.x = acc.x * corr + p * v01.x;
            acc.y = acc.y * corr + p * v01.y;
            acc.z = acc.z * corr + p * v23.x;
            acc.w = acc.w * corr + p * v23.y;
            m = nm;
            if (!more) break;
            e = ne; uk = nuk; uv = nuv;
        }
    }
    float inv = 1.f / (s + 1e-16f);
    return make_float4(acc.x * inv, acc.y * inv, acc.z * inv, acc.w * inv);
}

constexpr int kAttnGridS = kNStmt / 8;   // 12500

__global__ void __launch_bounds__(256) attn_all(
        const float* __restrict__ qa, const float* __restrict__ qa2,
        const __half* __restrict__ kh, const __half* __restrict__ vA,
        const __half* __restrict__ vB,
        const int* __restrict__ st, const int* __restrict__ srt,
        float* __restrict__ agg)
{
    int tid = threadIdx.x, wid = tid >> 5, lane = tid & 31;
    int b = blockIdx.x;
    if (b < kAttnGridS) {
        int dn = b * 8 + wid;
        float4 q0 = __ldg((const float4*)(qa + (size_t)dn * 128) + lane);
        float4 r = attn_edges(__ldg(&st[dn]), __ldg(&st[dn + 1]), lane, q0,
                              srt, kh, vA);
        float4 q2 = __ldg((const float4*)(qa2 + (size_t)dn * 128) + lane);
        const int* st2 = st + (kNStmt + kNFunc + 2);
        float4 r2 = attn_edges(__ldg(&st2[dn]), __ldg(&st2[dn + 1]), lane, q2,
                               srt + 2 * kE,
                               kh + (size_t)kNStmt * 128, vA + (size_t)kNStmt * 128);
        r.x += r2.x; r.y += r2.y; r.z += r2.z; r.w += r2.w;
        ((float4*)(agg + (size_t)dn * 128))[lane] = r;
    } else {
        int dn = (b - kAttnGridS) * 8 + wid;
        const int* st1 = st + (kNStmt + 1);
        float4 q1 = __ldg((const float4*)(qa + (size_t)(kNStmt + dn) * 128) + lane);
        float4 r = attn_edges(__ldg(&st1[dn]), __ldg(&st1[dn + 1]), lane, q1,
                              srt + kE, kh, vB);
        ((float4*)(agg + (size_t)(kNStmt + dn) * 128))[lane] = r;
    }
}

// ---------------------------------------------------------------------------
// Orchestration
// ---------------------------------------------------------------------------
extern "C" void kernel_launch(void* const* d_in, const int* in_sizes, int n_in,
                              void* d_out, int out_size) {
    const int* tok_s = (const int*)d_in[0];
    const int* tok_f = (const int*)d_in[1];
    const int* e0s = (const int*)d_in[2], *e0d = (const int*)d_in[3];
    const int* e1s = (const int*)d_in[4], *e1d = (const int*)d_in[5];
    const int* e2s = (const int*)d_in[6], *e2d = (const int*)d_in[7];
    const float* emb   = (const float*)d_in[8];
    const float* lin_w = (const float*)d_in[9];
    const float* lin_b = (const float*)d_in[10];
    const float* kw = (const float*)d_in[11];
    const float* kb = (const float*)d_in[12];
    const float* qw = (const float*)d_in[13];
    const float* qb = (const float*)d_in[14];
    const float* vw = (const float*)d_in[15];
    const float* vb = (const float*)d_in[16];
    const float* aw = (const float*)d_in[17];
    const float* ab = (const float*)d_in[18];
    const float* skip  = (const float*)d_in[19];
    const float* a_rel = (const float*)d_in[20];
    const float* m_rel = (const float*)d_in[21];
    const float* p_rel = (const float*)d_in[22];
    float* out = (float*)d_out;

    float *px, *pqa, *pqa2, *pagg, *pwt, *ptb;
    __half *pkh, *pvA, *pvB;
    int *ptmp, *pst, *psrt;
    cudaGetSymbolAddress((void**)&px,   g_x);
    cudaGetSymbolAddress((void**)&pqa,  g_qa);
    cudaGetSymbolAddress((void**)&pqa2, g_qa2);
    cudaGetSymbolAddress((void**)&pkh,  g_kh);
    cudaGetSymbolAddress((void**)&pvA,  g_vA);
    cudaGetSymbolAddress((void**)&pvB,  g_vB);
    cudaGetSymbolAddress((void**)&pagg, g_agg);
    cudaGetSymbolAddress((void**)&pwt,  g_wt);
    cudaGetSymbolAddress((void**)&ptb,  g_tb);
    cudaGetSymbolAddress((void**)&ptmp, g_tmp);
    cudaGetSymbolAddress((void**)&pst,  g_starts);
    cudaGetSymbolAddress((void**)&psrt, g_srt);

    cudaFuncSetAttribute(tgemm1<2,1>, cudaFuncAttributeMaxDynamicSharedMemorySize, TG_SMEM);
    cudaFuncSetAttribute(tgemm1<1,2>, cudaFuncAttributeMaxDynamicSharedMemorySize, TG_SMEM);
    cudaFuncSetAttribute(tgemm_kqv, cudaFuncAttributeMaxDynamicSharedMemorySize, TG_SMEM);

    int egrid = (kE + 255) / 256;

    // CSR build
    zero_int<<<(500000 + 255) / 256, 256>>>(ptmp, 500000);
    hist3<<<dim3(egrid, 3), 256>>>(e0d, e1d, e2d, ptmp);
    exscan3<<<3, 1024>>>(ptmp, pst);
    scat3<<<dim3(egrid, 3), 256>>>(e0s, e0d, e1s, e1d, e2s, e2d,
                                   pst, ptmp + 250000, psrt);

    // Weight prep (plain + relation-folded), then input linear with fused embed
    prep_mats<<<22, 256>>>(lin_w, kw, qw, vw, aw, a_rel, m_rel, p_rel, qb, vb,
                           pwt, ptb);
    tgemm1<2,1><<<kGridAll, 256, TG_SMEM>>>(
        nullptr, tok_s, tok_f, emb,
        pwt, pwt + 16384, lin_b, lin_b + 128,
        nullptr, nullptr, nullptr, px);

    for (int l = 0; l < kL; ++l) {
        int m0 = l * 2, m1 = l * 2 + 1;
        size_t cs = 10 + (size_t)l * 6;   // computed slot base

        KqvP P;
        // stmt (type 0): k, v0, v1, qa0, qa2
        P.B[0][0] = pwt + (size_t)(2 + m0) * 16384;
        P.B[0][1] = pwt + (cs + 0) * 16384;
        P.B[0][2] = pwt + (cs + 1) * 16384;
        P.B[0][3] = pwt + (cs + 3) * 16384;
        P.B[0][4] = pwt + (cs + 4) * 16384;
        P.bs[0][0] = kb + m0 * 128;
        P.bs[0][1] = ptb + (l * 6 + 0) * 128;
        P.bs[0][2] = ptb + (l * 6 + 1) * 128;
        P.bs[0][3] = ptb + (l * 6 + 3) * 128;
        P.bs[0][4] = ptb + (l * 6 + 4) * 128;
        // func (type 1): k, v2, -, qa1, -
        P.B[1][0] = pwt + (size_t)(2 + m1) * 16384;
        P.B[1][1] = pwt + (cs + 2) * 16384;
        P.B[1][2] = nullptr;
        P.B[1][3] = pwt + (cs + 5) * 16384;
        P.B[1][4] = nullptr;
        P.bs[1][0] = kb + m1 * 128;
        P.bs[1][1] = ptb + (l * 6 + 2) * 128;
        P.bs[1][2] = nullptr;
        P.bs[1][3] = ptb + (l * 6 + 5) * 128;
        P.bs[1][4] = nullptr;

        tgemm_kqv<<<kGridAll, 256, TG_SMEM>>>(px, P, pkh, pvA, pvB, pqa, pqa2);

        attn_all<<<kAttnGridS + kNFunc / 8, 256>>>(pqa, pqa2, pkh, pvA, pvB,
                                                   pst, psrt, pagg);

        float* dst = (l == kL - 1) ? out : px;
        tgemm1<1,2><<<kGridAll, 256, TG_SMEM>>>(
            pagg, nullptr, nullptr, nullptr,
            pwt + (size_t)(6 + m0) * 16384, pwt + (size_t)(6 + m1) * 16384,
            ab + m0 * 128, ab + m1 * 128,
            px, skip + m0, skip + m1, dst);
    }
}

// round 10
// speedup vs baseline: 3.0869x; 1.0103x over previous
#include <cuda_runtime.h>
#include <cuda_fp16.h>
#include <cstdint>

// ---------------------------------------------------------------------------
// HGT forward. Node layout: stmt rows [0,100000), func rows [100000,150000).
// Relation transforms folded into GEMM weights. Attention = pure CSR gather +
// online softmax. Embed fused into input GEMM. GEMMs: 512thr, 32x32 warp tile.
// ---------------------------------------------------------------------------
constexpr int kNStmt = 100000;
constexpr int kNFunc = 50000;
constexpr int kNTot  = 150000;
constexpr int kC = 128;
constexpr int kE = 200000;
constexpr int kL = 2;
constexpr int kGridS = (kNStmt + 127) / 128;            // 782
constexpr int kGridF = (kNFunc + 127) / 128;            // 391
constexpr int kGridAll = kGridS + kGridF;               // 1173

// Scratch (device globals: no allocation allowed)
__device__ float  g_x  [(size_t)kNTot * kC];
__device__ float  g_qa [(size_t)kNTot * kC];   // stmt: qa0, func: qa1
__device__ float  g_qa2[(size_t)kNStmt * kC];  // stmt: qa2
__device__ __half g_kh [(size_t)kNTot * kC];
__device__ __half g_vA [(size_t)kNTot * kC];   // stmt: v@M0, func: v@M2
__device__ __half g_vB [(size_t)kNStmt * kC];  // stmt: v@M1
__device__ float  g_agg[(size_t)kNTot * kC];
__device__ float  g_wt [(size_t)22 * 16384];   // fragment-ordered tf32 weights
__device__ float  g_tb [12 * 128];             // transformed biases
__device__ int    g_tmp[500000];               // cnt[250000] then cur[250000]
__device__ int    g_starts[250003];
__device__ int    g_srt[600000];

__device__ __forceinline__ float totf32(float x) {
    uint32_t r;
    asm("cvt.rna.tf32.f32 %0, %1;" : "=r"(r) : "f"(x));
    return __uint_as_float(r);
}
__device__ __forceinline__ float gelu_t(float u) {
    return 0.5f * u * (1.f + tanhf(0.7978845608028654f * (u + 0.044715f * u * u * u)));
}

#define MMA_TF32(c, a, bv0, bv1) \
    asm volatile("mma.sync.aligned.m16n8k8.row.col.f32.tf32.tf32.f32 " \
        "{%0,%1,%2,%3}, {%4,%5,%6,%7}, {%8,%9}, {%0,%1,%2,%3};" \
        : "+f"((c)[0]), "+f"((c)[1]), "+f"((c)[2]), "+f"((c)[3]) \
        : "r"((a)[0]), "r"((a)[1]), "r"((a)[2]), "r"((a)[3]), "r"(bv0), "r"(bv1))

// ---------------------------------------------------------------------------
// prep_mats: build all fragment-ordered tf32 weight matrices.
// Slots: 0,1 = lin; 2-5 = kw(mi); 6-9 = aw(mi);
//        10+l*6+{0:v0,1:v1,2:v2,3:qa0,4:qa2,5:qa1}
// v fold:  out[h,j] = sum_d W[.,h*16+d] * M[h,d,j]     (apply M to v)
// qa fold: out[h,j] = sum_d W[.,h*16+d] * A[h,j,d]     (logit = qa . k)
// Frag layout: idx=((nt*16+ks)*32+lane)*2+reg; k=ks*8+(lane&3)+reg*4, n=nt*8+(lane>>2)
// ---------------------------------------------------------------------------
__global__ void __launch_bounds__(256) prep_mats(
        const float* __restrict__ lin_w, const float* __restrict__ kw,
        const float* __restrict__ qw, const float* __restrict__ vw,
        const float* __restrict__ aw,
        const float* __restrict__ a_rel, const float* __restrict__ m_rel,
        const float* __restrict__ p_rel,
        const float* __restrict__ qb, const float* __restrict__ vb,
        float* __restrict__ wt, float* __restrict__ tb)
{
    int b = blockIdx.x, tid = threadIdx.x;
    float* dst = wt + (size_t)b * 16384;
    if (b < 10) {
        const float* W = (b < 2) ? lin_w + (size_t)b * 16384
                       : (b < 6) ? kw + (size_t)(b - 2) * 16384
                                 : aw + (size_t)(b - 6) * 16384;
        for (int i = tid; i < 16384; i += 256) {
            int reg = i & 1, lane = (i >> 1) & 31, ks = (i >> 6) & 15, nt = i >> 10;
            int k = ks * 8 + (lane & 3) + reg * 4;
            int n = nt * 8 + (lane >> 2);
            dst[i] = totf32(__ldg(&W[k * 128 + n]));
        }
        return;
    }
    int c = b - 10, l = c / 6, idx = c % 6;
    const int srcT[3] = {0, 0, 1}, dstT[3] = {0, 1, 0};
    int rel = (idx < 3) ? idx : (idx == 3 ? 0 : (idx == 4 ? 2 : 1));
    bool isQA = (idx >= 3);
    const float* W  = isQA ? qw + (size_t)(l * 2 + dstT[rel]) * 16384
                           : vw + (size_t)(l * 2 + srcT[rel]) * 16384;
    const float* T  = (isQA ? a_rel : m_rel) + (size_t)(l * 3 + rel) * 2048;
    const float* Bi = isQA ? qb + (l * 2 + dstT[rel]) * 128
                           : vb + (l * 2 + srcT[rel]) * 128;
    __shared__ float Ts[2048];
    __shared__ float sc[8];
    for (int i = tid; i < 2048; i += 256) Ts[i] = __ldg(&T[i]);
    if (tid < 8) sc[tid] = isQA ? __ldg(&p_rel[(l * 3 + rel) * 8 + tid]) * 0.25f : 1.f;
    __syncthreads();
    for (int i = tid; i < 16384; i += 256) {
        int reg = i & 1, lane = (i >> 1) & 31, ks = (i >> 6) & 15, nt = i >> 10;
        int k = ks * 8 + (lane & 3) + reg * 4;
        int n = nt * 8 + (lane >> 2);
        int h = n >> 4, j = n & 15;   // output within-head index
        float s = 0.f;
        if (isQA) {
#pragma unroll
            for (int d = 0; d < 16; ++d)
                s += __ldg(&W[k * 128 + h * 16 + d]) * Ts[h * 256 + j * 16 + d];
        } else {
#pragma unroll
            for (int d = 0; d < 16; ++d)
                s += __ldg(&W[k * 128 + h * 16 + d]) * Ts[h * 256 + d * 16 + j];
        }
        dst[i] = totf32(s * sc[h]);
    }
    if (tid < 128) {
        int h = tid >> 4, j = tid & 15;
        float s = 0.f;
        if (isQA) {
#pragma unroll
            for (int d = 0; d < 16; ++d)
                s += __ldg(&Bi[h * 16 + d]) * Ts[h * 256 + j * 16 + d];
        } else {
#pragma unroll
            for (int d = 0; d < 16; ++d)
                s += __ldg(&Bi[h * 16 + d]) * Ts[h * 256 + d * 16 + j];
        }
        tb[c * 128 + tid] = s * sc[h];
    }
}

// ---------------------------------------------------------------------------
// GEMM mainloop: 512 threads, 16 warps (4M x 4N), warp tile 32x32.
// ---------------------------------------------------------------------------
constexpr int TG_SMEM = 128 * 132 * 4;
constexpr int TG_THR = 512;

__device__ __forceinline__ void gemm_tile(
        const uint32_t* Asu, const float* __restrict__ Bf,
        int warpM, int warpN, int lane, float acc[2][4][4])
{
#pragma unroll
    for (int mt = 0; mt < 2; ++mt)
#pragma unroll
        for (int nt = 0; nt < 4; ++nt)
#pragma unroll
            for (int i = 0; i < 4; ++i) acc[mt][nt][i] = 0.f;
#pragma unroll
    for (int ks = 0; ks < 16; ++ks) {
        uint2 bv[4];
#pragma unroll
        for (int nt = 0; nt < 4; ++nt) {
            int ntA = warpN * 4 + nt;
            bv[nt] = __ldg((const uint2*)(Bf + ((ntA * 16 + ks) * 32 + lane) * 2));
        }
        uint32_t a[2][4];
#pragma unroll
        for (int mt = 0; mt < 2; ++mt) {
            int rb = warpM * 32 + mt * 16 + (lane >> 2);
            int cb = ks * 8 + (lane & 3);
            a[mt][0] = Asu[rb * 132 + cb];
            a[mt][1] = Asu[(rb + 8) * 132 + cb];
            a[mt][2] = Asu[rb * 132 + cb + 4];
            a[mt][3] = Asu[(rb + 8) * 132 + cb + 4];
        }
#pragma unroll
        for (int nt = 0; nt < 4; ++nt)
#pragma unroll
            for (int mt = 0; mt < 2; ++mt)
                MMA_TF32(acc[mt][nt], a[mt], bv[nt].x, bv[nt].y);
    }
}

// ---------------------------------------------------------------------------
// tgemm1: single-output GEMM (input or output projection), merged type grid.
// PRE: 1=tanh-gelu, 2=embed(mean+relu).  POST: 1=relu, 2=skip blend.
// ---------------------------------------------------------------------------
template<int PRE, int POST>
__global__ void __launch_bounds__(TG_THR, 2) tgemm1(
        const float* __restrict__ A,
        const int* __restrict__ tok_s, const int* __restrict__ tok_f,
        const float* __restrict__ emb,
        const float* __restrict__ B0, const float* __restrict__ B1,
        const float* __restrict__ b0, const float* __restrict__ b1,
        const float* __restrict__ Xold,
        const float* __restrict__ skip0, const float* __restrict__ skip1,
        float* __restrict__ Out)
{
    extern __shared__ float sm[];
    float* As = sm;
    uint32_t* Asu = (uint32_t*)As;
    int tid = threadIdx.x, wid = tid >> 5, lane = tid & 31;
    int warpM = wid & 3, warpN = wid >> 2;
    int b = blockIdx.x;
    bool tf = (b >= kGridS);
    int rowBase = tf ? (kNStmt + (b - kGridS) * 128) : b * 128;
    int Nend = tf ? kNTot : kNStmt;
    const float* Bf = tf ? B1 : B0;
    const float* bs = tf ? b1 : b0;

#pragma unroll 2
    for (int p = 0; p < 8; ++p) {
        int idx = p * TG_THR + tid;
        int r = idx >> 5, c4 = idx & 31;
        int n = rowBase + r;
        float4 v = make_float4(0.f, 0.f, 0.f, 0.f);
        if (n < Nend) {
            if (PRE == 2) {
                const int* tok = tf ? tok_f + (size_t)(n - kNStmt) * 16
                                    : tok_s + (size_t)n * 16;
#pragma unroll
                for (int i = 0; i < 16; ++i) {
                    int t = __ldg(&tok[i]);
                    float4 e4 = __ldg((const float4*)(emb + (size_t)t * 128) + c4);
                    v.x += e4.x; v.y += e4.y; v.z += e4.z; v.w += e4.w;
                }
                v.x = fmaxf(v.x * (1.f / 16.f), 0.f);
                v.y = fmaxf(v.y * (1.f / 16.f), 0.f);
                v.z = fmaxf(v.z * (1.f / 16.f), 0.f);
                v.w = fmaxf(v.w * (1.f / 16.f), 0.f);
            } else {
                v = __ldg((const float4*)(A + (size_t)n * 128 + c4 * 4));
                if (PRE == 1) {
                    v.x = gelu_t(v.x); v.y = gelu_t(v.y);
                    v.z = gelu_t(v.z); v.w = gelu_t(v.w);
                }
            }
        }
        v.x = totf32(v.x); v.y = totf32(v.y); v.z = totf32(v.z); v.w = totf32(v.w);
        *(float4*)&As[r * 132 + c4 * 4] = v;
    }
    __syncthreads();

    float gate = 1.f, og = 0.f;
    if (POST == 2) {
        float sv = __ldg(tf ? skip1 : skip0);
        gate = 1.f / (1.f + expf(-sv));
        og = 1.f - gate;
    }

    float acc[2][4][4];
    gemm_tile(Asu, Bf, warpM, warpN, lane, acc);

    int g = lane >> 2, t2 = (lane & 3) * 2;
#pragma unroll
    for (int mt = 0; mt < 2; ++mt) {
        int r0 = rowBase + warpM * 32 + mt * 16 + g;
#pragma unroll
        for (int nt = 0; nt < 4; ++nt) {
            int col = warpN * 32 + nt * 8 + t2;
            float bb0 = __ldg(&bs[col]), bb1 = __ldg(&bs[col + 1]);
            float o0 = acc[mt][nt][0] + bb0, o1 = acc[mt][nt][1] + bb1;
            float o2 = acc[mt][nt][2] + bb0, o3 = acc[mt][nt][3] + bb1;
            if (POST == 1) {
                o0 = fmaxf(o0, 0.f); o1 = fmaxf(o1, 0.f);
                o2 = fmaxf(o2, 0.f); o3 = fmaxf(o3, 0.f);
            }
            if (POST == 2) {
                if (r0 < Nend) {
                    float2 x = *(const float2*)(Xold + (size_t)r0 * 128 + col);
                    o0 = gate * o0 + og * x.x; o1 = gate * o1 + og * x.y;
                }
                if (r0 + 8 < Nend) {
                    float2 x = *(const float2*)(Xold + (size_t)(r0 + 8) * 128 + col);
                    o2 = gate * o2 + og * x.x; o3 = gate * o3 + og * x.y;
                }
            }
            if (r0 < Nend)
                *(float2*)(Out + (size_t)r0 * 128 + col) = make_float2(o0, o1);
            if (r0 + 8 < Nend)
                *(float2*)(Out + (size_t)(r0 + 8) * 128 + col) = make_float2(o2, o3);
        }
    }
}

// ---------------------------------------------------------------------------
// tgemm_kqv: 5 outputs. j: 0=k(h16) 1=vA(h16) 2=vB(h16,stmt) 3=qa(f32) 4=qa2(f32,stmt)
// func blocks skip j=2,4 (their vA=v2, qa=qa1).
// ---------------------------------------------------------------------------
struct KqvP {
    const float* B[2][5];
    const float* bs[2][5];
};

__global__ void __launch_bounds__(TG_THR, 2) tgemm_kqv(
        const float* __restrict__ A, KqvP P,
        __half* __restrict__ Ok, __half* __restrict__ OvA, __half* __restrict__ OvB,
        float* __restrict__ Oqa, float* __restrict__ Oqa2)
{
    extern __shared__ float sm[];
    float* As = sm;
    uint32_t* Asu = (uint32_t*)As;
    int tid = threadIdx.x, wid = tid >> 5, lane = tid & 31;
    int warpM = wid & 3, warpN = wid >> 2;
    int b = blockIdx.x;
    bool tf = (b >= kGridS);
    int rowBase = tf ? (kNStmt + (b - kGridS) * 128) : b * 128;
    int Nend = tf ? kNTot : kNStmt;
    int ti = tf ? 1 : 0;

#pragma unroll 4
    for (int p = 0; p < 8; ++p) {
        int idx = p * TG_THR + tid;
        int r = idx >> 5, c4 = idx & 31;
        int n = rowBase + r;
        float4 v = make_float4(0.f, 0.f, 0.f, 0.f);
        if (n < Nend) v = __ldg((const float4*)(A + (size_t)n * 128 + c4 * 4));
        v.x = totf32(v.x); v.y = totf32(v.y); v.z = totf32(v.z); v.w = totf32(v.w);
        *(float4*)&As[r * 132 + c4 * 4] = v;
    }
    __syncthreads();

    int g = lane >> 2, t2 = (lane & 3) * 2;
#pragma unroll
    for (int j = 0; j < 5; ++j) {
        if (tf && (j == 2 || j == 4)) continue;
        float acc[2][4][4];
        gemm_tile(Asu, P.B[ti][j], warpM, warpN, lane, acc);
        const float* bs = P.bs[ti][j];
#pragma unroll
        for (int mt = 0; mt < 2; ++mt) {
            int r0 = rowBase + warpM * 32 + mt * 16 + g;
#pragma unroll
            for (int nt = 0; nt < 4; ++nt) {
                int col = warpN * 32 + nt * 8 + t2;
                float bb0 = __ldg(&bs[col]), bb1 = __ldg(&bs[col + 1]);
                float o0 = acc[mt][nt][0] + bb0, o1 = acc[mt][nt][1] + bb1;
                float o2 = acc[mt][nt][2] + bb0, o3 = acc[mt][nt][3] + bb1;
                if (j < 3) {
                    __half* Oh = (j == 0) ? Ok : (j == 1) ? OvA : OvB;
                    if (r0 < Nend)
                        *(__half2*)(Oh + (size_t)r0 * 128 + col) = __floats2half2_rn(o0, o1);
                    if (r0 + 8 < Nend)
                        *(__half2*)(Oh + (size_t)(r0 + 8) * 128 + col) = __floats2half2_rn(o2, o3);
                } else {
                    float* Of = (j == 3) ? Oqa : Oqa2;
                    if (r0 < Nend)
                        *(float2*)(Of + (size_t)r0 * 128 + col) = make_float2(o0, o1);
                    if (r0 + 8 < Nend)
                        *(float2*)(Of + (size_t)(r0 + 8) * 128 + col) = make_float2(o2, o3);
                }
            }
        }
    }
}

// ---------------------------------------------------------------------------
// CSR build
// ---------------------------------------------------------------------------
__global__ void zero_int(int* __restrict__ p, int n) {
    int i = blockIdx.x * 256 + threadIdx.x;
    if (i < n) p[i] = 0;
}

__global__ void hist3(const int* __restrict__ d0, const int* __restrict__ d1,
                      const int* __restrict__ d2, int* __restrict__ cnt) {
    int r = blockIdx.y;
    const int* dst = (r == 0) ? d0 : (r == 1) ? d1 : d2;
    int off = (r == 0) ? 0 : (r == 1) ? kNStmt : kNStmt + kNFunc;
    int i = blockIdx.x * 256 + threadIdx.x;
    if (i < kE) atomicAdd(&cnt[off + __ldg(&dst[i])], 1);
}

__global__ void __launch_bounds__(1024) exscan3(const int* __restrict__ cnt,
                                                int* __restrict__ starts) {
    __shared__ int wsum[32];
    __shared__ int carry_s;
    const int cntOff[3] = {0, kNStmt, kNStmt + kNFunc};
    const int stOff[3]  = {0, kNStmt + 1, kNStmt + kNFunc + 2};
    const int ns[3]     = {kNStmt, kNFunc, kNStmt};
    int r = blockIdx.x;
    const int* c = cnt + cntOff[r];
    int* st = starts + stOff[r];
    int n = ns[r];
    int tid = threadIdx.x, lane = tid & 31, w = tid >> 5;
    if (tid == 0) carry_s = 0;
    __syncthreads();
    for (int base = 0; base < n; base += 1024) {
        int i = base + tid;
        int v = (i < n) ? c[i] : 0;
        int x = v;
#pragma unroll
        for (int o = 1; o < 32; o <<= 1) {
            int t = __shfl_up_sync(0xffffffffu, x, o);
            if (lane >= o) x += t;
        }
        if (lane == 31) wsum[w] = x;
        __syncthreads();
        if (w == 0) {
            int y = wsum[lane];
#pragma unroll
            for (int o = 1; o < 32; o <<= 1) {
                int t = __shfl_up_sync(0xffffffffu, y, o);
                if (lane >= o) y += t;
            }
            wsum[lane] = y;
        }
        __syncthreads();
        int incl = x + (w > 0 ? wsum[w - 1] : 0);
        int carry = carry_s;
        if (i < n) st[i] = carry + incl - v;
        __syncthreads();
        if (tid == 0) carry_s = carry + wsum[31];
        __syncthreads();
    }
    if (tid == 0) st[n] = carry_s;
}

__global__ void scat3(const int* __restrict__ s0, const int* __restrict__ d0,
                      const int* __restrict__ s1, const int* __restrict__ d1,
                      const int* __restrict__ s2, const int* __restrict__ d2,
                      const int* __restrict__ starts, int* __restrict__ cur,
                      int* __restrict__ out) {
    int r = blockIdx.y;
    const int* src = (r == 0) ? s0 : (r == 1) ? s1 : s2;
    const int* dst = (r == 0) ? d0 : (r == 1) ? d1 : d2;
    int cOff = (r == 0) ? 0 : (r == 1) ? kNStmt : kNStmt + kNFunc;
    int sOff = (r == 0) ? 0 : (r == 1) ? kNStmt + 1 : kNStmt + kNFunc + 2;
    int i = blockIdx.x * 256 + threadIdx.x;
    if (i < kE) {
        int d = __ldg(&dst[i]);
        int pos = __ldg(&starts[sOff + d]) + atomicAdd(&cur[cOff + d], 1);
        out[(size_t)r * kE + pos] = __ldg(&src[i]);
    }
}

// ---------------------------------------------------------------------------
// Attention: pure gather + online softmax. Warp per dst, lane = 4 channels.
// ---------------------------------------------------------------------------
__device__ __forceinline__ float4 attn_edges(
        int e0, int e1, int lane, float4 qa,
        const int* __restrict__ srcs,
        const __half* __restrict__ kb, const __half* __restrict__ vb)
{
    float m = -INFINITY, s = 0.f;
    float4 acc = make_float4(0.f, 0.f, 0.f, 0.f);
    if (e0 < e1) {
        int src = __ldg(&srcs[e0]);
        uint2 uk = __ldg((const uint2*)(kb + (size_t)src * 128) + lane);
        uint2 uv = __ldg((const uint2*)(vb + (size_t)src * 128) + lane);
        for (int e = e0; ; ) {
            int ne = e + 1;
            bool more = ne < e1;
            uint2 nuk, nuv;
            if (more) {
                int nsrc = __ldg(&srcs[ne]);
                nuk = __ldg((const uint2*)(kb + (size_t)nsrc * 128) + lane);
                nuv = __ldg((const uint2*)(vb + (size_t)nsrc * 128) + lane);
            }
            float2 k01 = __half22float2(*(__half2*)&uk.x);
            float2 k23 = __half22float2(*(__half2*)&uk.y);
            float2 v01 = __half22float2(*(__half2*)&uv.x);
            float2 v23 = __half22float2(*(__half2*)&uv.y);
            float lg = qa.x * k01.x + qa.y * k01.y + qa.z * k23.x + qa.w * k23.y;
            lg += __shfl_xor_sync(0xffffffffu, lg, 1);
            lg += __shfl_xor_sync(0xffffffffu, lg, 2);
            float nm = fmaxf(m, lg);
            float corr = __expf(m - nm);
            float p = __expf(lg - nm);
            s = s * corr + p;
            acc.x = acc.x * corr + p * v01.x;
            acc.y = acc.y * corr + p * v01.y;
            acc.z = acc.z * corr + p * v23.x;
            acc.w = acc.w * corr + p * v23.y;
            m = nm;
            if (!more) break;
            e = ne; uk = nuk; uv = nuv;
        }
    }
    float inv = 1.f / (s + 1e-16f);
    return make_float4(acc.x * inv, acc.y * inv, acc.z * inv, acc.w * inv);
}

constexpr int kAttnGridS = kNStmt / 8;   // 12500

__global__ void __launch_bounds__(256) attn_all(
        const float* __restrict__ qa, const float* __restrict__ qa2,
        const __half* __restrict__ kh, const __half* __restrict__ vA,
        const __half* __restrict__ vB,
        const int* __restrict__ st, const int* __restrict__ srt,
        float* __restrict__ agg)
{
    int tid = threadIdx.x, wid = tid >> 5, lane = tid & 31;
    int b = blockIdx.x;
    if (b < kAttnGridS) {
        int dn = b * 8 + wid;
        float4 q0 = __ldg((const float4*)(qa + (size_t)dn * 128) + lane);
        float4 r = attn_edges(__ldg(&st[dn]), __ldg(&st[dn + 1]), lane, q0,
                              srt, kh, vA);
        float4 q2 = __ldg((const float4*)(qa2 + (size_t)dn * 128) + lane);
        const int* st2 = st + (kNStmt + kNFunc + 2);
        float4 r2 = attn_edges(__ldg(&st2[dn]), __ldg(&st2[dn + 1]), lane, q2,
                               srt + 2 * kE,
                               kh + (size_t)kNStmt * 128, vA + (size_t)kNStmt * 128);
        r.x += r2.x; r.y += r2.y; r.z += r2.z; r.w += r2.w;
        ((float4*)(agg + (size_t)dn * 128))[lane] = r;
    } else {
        int dn = (b - kAttnGridS) * 8 + wid;
        const int* st1 = st + (kNStmt + 1);
        float4 q1 = __ldg((const float4*)(qa + (size_t)(kNStmt + dn) * 128) + lane);
        float4 r = attn_edges(__ldg(&st1[dn]), __ldg(&st1[dn + 1]), lane, q1,
                              srt + kE, kh, vB);
        ((float4*)(agg + (size_t)(kNStmt + dn) * 128))[lane] = r;
    }
}

// ---------------------------------------------------------------------------
// Orchestration
// ---------------------------------------------------------------------------
extern "C" void kernel_launch(void* const* d_in, const int* in_sizes, int n_in,
                              void* d_out, int out_size) {
    const int* tok_s = (const int*)d_in[0];
    const int* tok_f = (const int*)d_in[1];
    const int* e0s = (const int*)d_in[2], *e0d = (const int*)d_in[3];
    const int* e1s = (const int*)d_in[4], *e1d = (const int*)d_in[5];
    const int* e2s = (const int*)d_in[6], *e2d = (const int*)d_in[7];
    const float* emb   = (const float*)d_in[8];
    const float* lin_w = (const float*)d_in[9];
    const float* lin_b = (const float*)d_in[10];
    const float* kw = (const float*)d_in[11];
    const float* kb = (const float*)d_in[12];
    const float* qw = (const float*)d_in[13];
    const float* qb = (const float*)d_in[14];
    const float* vw = (const float*)d_in[15];
    const float* vb = (const float*)d_in[16];
    const float* aw = (const float*)d_in[17];
    const float* ab = (const float*)d_in[18];
    const float* skip  = (const float*)d_in[19];
    const float* a_rel = (const float*)d_in[20];
    const float* m_rel = (const float*)d_in[21];
    const float* p_rel = (const float*)d_in[22];
    float* out = (float*)d_out;

    float *px, *pqa, *pqa2, *pagg, *pwt, *ptb;
    __half *pkh, *pvA, *pvB;
    int *ptmp, *pst, *psrt;
    cudaGetSymbolAddress((void**)&px,   g_x);
    cudaGetSymbolAddress((void**)&pqa,  g_qa);
    cudaGetSymbolAddress((void**)&pqa2, g_qa2);
    cudaGetSymbolAddress((void**)&pkh,  g_kh);
    cudaGetSymbolAddress((void**)&pvA,  g_vA);
    cudaGetSymbolAddress((void**)&pvB,  g_vB);
    cudaGetSymbolAddress((void**)&pagg, g_agg);
    cudaGetSymbolAddress((void**)&pwt,  g_wt);
    cudaGetSymbolAddress((void**)&ptb,  g_tb);
    cudaGetSymbolAddress((void**)&ptmp, g_tmp);
    cudaGetSymbolAddress((void**)&pst,  g_starts);
    cudaGetSymbolAddress((void**)&psrt, g_srt);

    cudaFuncSetAttribute(tgemm1<2,1>, cudaFuncAttributeMaxDynamicSharedMemorySize, TG_SMEM);
    cudaFuncSetAttribute(tgemm1<1,2>, cudaFuncAttributeMaxDynamicSharedMemorySize, TG_SMEM);
    cudaFuncSetAttribute(tgemm_kqv, cudaFuncAttributeMaxDynamicSharedMemorySize, TG_SMEM);

    int egrid = (kE + 255) / 256;

    // CSR build
    zero_int<<<(500000 + 255) / 256, 256>>>(ptmp, 500000);
    hist3<<<dim3(egrid, 3), 256>>>(e0d, e1d, e2d, ptmp);
    exscan3<<<3, 1024>>>(ptmp, pst);
    scat3<<<dim3(egrid, 3), 256>>>(e0s, e0d, e1s, e1d, e2s, e2d,
                                   pst, ptmp + 250000, psrt);

    // Weight prep (plain + relation-folded), then input linear with fused embed
    prep_mats<<<22, 256>>>(lin_w, kw, qw, vw, aw, a_rel, m_rel, p_rel, qb, vb,
                           pwt, ptb);
    tgemm1<2,1><<<kGridAll, TG_THR, TG_SMEM>>>(
        nullptr, tok_s, tok_f, emb,
        pwt, pwt + 16384, lin_b, lin_b + 128,
        nullptr, nullptr, nullptr, px);

    for (int l = 0; l < kL; ++l) {
        int m0 = l * 2, m1 = l * 2 + 1;
        size_t cs = 10 + (size_t)l * 6;   // computed slot base

        KqvP P;
        // stmt (type 0): k, v0, v1, qa0, qa2
        P.B[0][0] = pwt + (size_t)(2 + m0) * 16384;
        P.B[0][1] = pwt + (cs + 0) * 16384;
        P.B[0][2] = pwt + (cs + 1) * 16384;
        P.B[0][3] = pwt + (cs + 3) * 16384;
        P.B[0][4] = pwt + (cs + 4) * 16384;
        P.bs[0][0] = kb + m0 * 128;
        P.bs[0][1] = ptb + (l * 6 + 0) * 128;
        P.bs[0][2] = ptb + (l * 6 + 1) * 128;
        P.bs[0][3] = ptb + (l * 6 + 3) * 128;
        P.bs[0][4] = ptb + (l * 6 + 4) * 128;
        // func (type 1): k, v2, -, qa1, -
        P.B[1][0] = pwt + (size_t)(2 + m1) * 16384;
        P.B[1][1] = pwt + (cs + 2) * 16384;
        P.B[1][2] = nullptr;
        P.B[1][3] = pwt + (cs + 5) * 16384;
        P.B[1][4] = nullptr;
        P.bs[1][0] = kb + m1 * 128;
        P.bs[1][1] = ptb + (l * 6 + 2) * 128;
        P.bs[1][2] = nullptr;
        P.bs[1][3] = ptb + (l * 6 + 5) * 128;
        P.bs[1][4] = nullptr;

        tgemm_kqv<<<kGridAll, TG_THR, TG_SMEM>>>(px, P, pkh, pvA, pvB, pqa, pqa2);

        attn_all<<<kAttnGridS + kNFunc / 8, 256>>>(pqa, pqa2, pkh, pvA, pvB,
                                                   pst, psrt, pagg);

        float* dst = (l == kL - 1) ? out : px;
        tgemm1<1,2><<<kGridAll, TG_THR, TG_SMEM>>>(
            pagg, nullptr, nullptr, nullptr,
            pwt + (size_t)(6 + m0) * 16384, pwt + (size_t)(6 + m1) * 16384,
            ab + m0 * 128, ab + m1 * 128,
            px, skip + m0, skip + m1, dst);
    }
}

// round 11
// speedup vs baseline: 3.7542x; 1.2162x over previous
#include <cuda_runtime.h>
#include <cuda_fp16.h>
#include <cstdint>

// ---------------------------------------------------------------------------
// HGT forward. Node layout: stmt rows [0,100000), func rows [100000,150000).
// Relation transforms folded into GEMM weights. Attention = pure CSR gather +
// online softmax. k/v GEMMs on fp16 m16n8k16 (2x MMA throughput); qa/in/out
// GEMMs on tf32 m16n8k8.
// ---------------------------------------------------------------------------
constexpr int kNStmt = 100000;
constexpr int kNFunc = 50000;
constexpr int kNTot  = 150000;
constexpr int kC = 128;
constexpr int kE = 200000;
constexpr int kL = 2;
constexpr int kGridS = (kNStmt + 127) / 128;            // 782
constexpr int kGridF = (kNFunc + 127) / 128;            // 391
constexpr int kGridAll = kGridS + kGridF;               // 1173

// Scratch (device globals: no allocation allowed)
__device__ float  g_x  [(size_t)kNTot * kC];
__device__ float  g_qa [(size_t)kNTot * kC];   // stmt: qa0, func: qa1
__device__ float  g_qa2[(size_t)kNStmt * kC];  // stmt: qa2
__device__ __half g_kh [(size_t)kNTot * kC];
__device__ __half g_vA [(size_t)kNTot * kC];   // stmt: v@M0, func: v@M2
__device__ __half g_vB [(size_t)kNStmt * kC];  // stmt: v@M1
__device__ float  g_agg[(size_t)kNTot * kC];
__device__ float  g_wt [(size_t)22 * 16384];   // fragment-ordered tf32 weights
__device__ __half g_wth[(size_t)10 * 16384];   // fragment-ordered fp16 weights
__device__ float  g_tb [12 * 128];             // transformed biases
__device__ int    g_tmp[500000];               // cnt[250000] then cur[250000]
__device__ int    g_starts[250003];
__device__ int    g_srt[600000];

__device__ __forceinline__ float totf32(float x) {
    uint32_t r;
    asm("cvt.rna.tf32.f32 %0, %1;" : "=r"(r) : "f"(x));
    return __uint_as_float(r);
}
__device__ __forceinline__ float gelu_t(float u) {
    return 0.5f * u * (1.f + tanhf(0.7978845608028654f * (u + 0.044715f * u * u * u)));
}

#define MMA_TF32(c, a, bv0, bv1) \
    asm volatile("mma.sync.aligned.m16n8k8.row.col.f32.tf32.tf32.f32 " \
        "{%0,%1,%2,%3}, {%4,%5,%6,%7}, {%8,%9}, {%0,%1,%2,%3};" \
        : "+f"((c)[0]), "+f"((c)[1]), "+f"((c)[2]), "+f"((c)[3]) \
        : "r"((a)[0]), "r"((a)[1]), "r"((a)[2]), "r"((a)[3]), "r"(bv0), "r"(bv1))

#define MMA_F16(c, a, bv0, bv1) \
    asm volatile("mma.sync.aligned.m16n8k16.row.col.f32.f16.f16.f32 " \
        "{%0,%1,%2,%3}, {%4,%5,%6,%7}, {%8,%9}, {%0,%1,%2,%3};" \
        : "+f"((c)[0]), "+f"((c)[1]), "+f"((c)[2]), "+f"((c)[3]) \
        : "r"((a)[0]), "r"((a)[1]), "r"((a)[2]), "r"((a)[3]), "r"(bv0), "r"(bv1))

// ---------------------------------------------------------------------------
// prep_mats: build fragment-ordered weights.
// tf32 slots (g_wt, 16384 f32 each): 0,1=lin; 2-5=kw(mi) [legacy, unused];
//   6-9=aw(mi); 10+l*6+{0:v0,1:v1,2:v2 [legacy], 3:qa0,4:qa2,5:qa1}
// fp16 slots (g_wth, 16384 half each): 0-3=kw(mi); 4+l*3+rel = v-folded
// tf32 frag: idx=((nt*16+ks)*32+lane)*2+reg; k=ks*8+(lane&3)+reg*4, n=nt*8+(lane>>2)
// fp16 frag (half2 idx i, reg=i&1): k0=ks*16+(lane&3)*2+reg*8 (pair k0,k0+1),
//   n=nt*8+(lane>>2), with ks=(i>>6)&7, nt=i>>9, lane=(i>>1)&31
// qa fold: out[h,j] = sum_d W[.,h*16+d] * A[h,j,d];  v fold: sum_d W * M[h,d,j]
// ---------------------------------------------------------------------------
__global__ void __launch_bounds__(256) prep_mats(
        const float* __restrict__ lin_w, const float* __restrict__ kw,
        const float* __restrict__ qw, const float* __restrict__ vw,
        const float* __restrict__ aw,
        const float* __restrict__ a_rel, const float* __restrict__ m_rel,
        const float* __restrict__ p_rel,
        const float* __restrict__ qb, const float* __restrict__ vb,
        float* __restrict__ wt, __half* __restrict__ wth, float* __restrict__ tb)
{
    int b = blockIdx.x, tid = threadIdx.x;
    const int srcT[3] = {0, 0, 1}, dstT[3] = {0, 1, 0};
    __shared__ float Ts[2048];
    __shared__ float sc[8];

    if (b < 10) {
        float* dst = wt + (size_t)b * 16384;
        const float* W = (b < 2) ? lin_w + (size_t)b * 16384
                       : (b < 6) ? kw + (size_t)(b - 2) * 16384
                                 : aw + (size_t)(b - 6) * 16384;
        for (int i = tid; i < 16384; i += 256) {
            int reg = i & 1, lane = (i >> 1) & 31, ks = (i >> 6) & 15, nt = i >> 10;
            int k = ks * 8 + (lane & 3) + reg * 4;
            int n = nt * 8 + (lane >> 2);
            dst[i] = totf32(__ldg(&W[k * 128 + n]));
        }
        return;
    }
    if (b < 22) {
        // tf32 folded (qa used; v slots legacy but compute tb biases here)
        int c = b - 10, l = c / 6, idx = c % 6;
        int rel = (idx < 3) ? idx : (idx == 3 ? 0 : (idx == 4 ? 2 : 1));
        bool isQA = (idx >= 3);
        const float* W  = isQA ? qw + (size_t)(l * 2 + dstT[rel]) * 16384
                               : vw + (size_t)(l * 2 + srcT[rel]) * 16384;
        const float* T  = (isQA ? a_rel : m_rel) + (size_t)(l * 3 + rel) * 2048;
        const float* Bi = isQA ? qb + (l * 2 + dstT[rel]) * 128
                               : vb + (l * 2 + srcT[rel]) * 128;
        float* dst = wt + (size_t)b * 16384;
        for (int i = tid; i < 2048; i += 256) Ts[i] = __ldg(&T[i]);
        if (tid < 8) sc[tid] = isQA ? __ldg(&p_rel[(l * 3 + rel) * 8 + tid]) * 0.25f : 1.f;
        __syncthreads();
        if (isQA) {   // only qa slots are consumed in tf32 form
            for (int i = tid; i < 16384; i += 256) {
                int reg = i & 1, lane = (i >> 1) & 31, ks = (i >> 6) & 15, nt = i >> 10;
                int k = ks * 8 + (lane & 3) + reg * 4;
                int n = nt * 8 + (lane >> 2);
                int h = n >> 4, j = n & 15;
                float s = 0.f;
#pragma unroll
                for (int d = 0; d < 16; ++d)
                    s += __ldg(&W[k * 128 + h * 16 + d]) * Ts[h * 256 + j * 16 + d];
                dst[i] = totf32(s * sc[h]);
            }
        }
        if (tid < 128) {
            int h = tid >> 4, j = tid & 15;
            float s = 0.f;
            if (isQA) {
#pragma unroll
                for (int d = 0; d < 16; ++d)
                    s += __ldg(&Bi[h * 16 + d]) * Ts[h * 256 + j * 16 + d];
            } else {
#pragma unroll
                for (int d = 0; d < 16; ++d)
                    s += __ldg(&Bi[h * 16 + d]) * Ts[h * 256 + d * 16 + j];
            }
            tb[c * 128 + tid] = s * sc[h];
        }
        return;
    }
    // fp16 fragment weights
    int c = b - 22;
    __half2* dsth = (__half2*)(wth + (size_t)c * 16384);
    if (c < 4) {   // plain kw, mi = c
        const float* W = kw + (size_t)c * 16384;
        for (int i = tid; i < 8192; i += 256) {
            int reg = i & 1, lane = (i >> 1) & 31, ks = (i >> 6) & 7, nt = i >> 9;
            int k0 = ks * 16 + (lane & 3) * 2 + reg * 8;
            int n = nt * 8 + (lane >> 2);
            dsth[i] = __floats2half2_rn(__ldg(&W[k0 * 128 + n]),
                                        __ldg(&W[(k0 + 1) * 128 + n]));
        }
        return;
    }
    int cc = c - 4, l = cc / 3, rel = cc % 3;
    const float* W = vw + (size_t)(l * 2 + srcT[rel]) * 16384;
    const float* T = m_rel + (size_t)(l * 3 + rel) * 2048;
    for (int i = tid; i < 2048; i += 256) Ts[i] = __ldg(&T[i]);
    __syncthreads();
    for (int i = tid; i < 8192; i += 256) {
        int reg = i & 1, lane = (i >> 1) & 31, ks = (i >> 6) & 7, nt = i >> 9;
        int k0 = ks * 16 + (lane & 3) * 2 + reg * 8;
        int n = nt * 8 + (lane >> 2);
        int h = n >> 4, j = n & 15;
        float s0 = 0.f, s1 = 0.f;
#pragma unroll
        for (int d = 0; d < 16; ++d) {
            float t = Ts[h * 256 + d * 16 + j];
            s0 += __ldg(&W[k0 * 128 + h * 16 + d]) * t;
            s1 += __ldg(&W[(k0 + 1) * 128 + h * 16 + d]) * t;
        }
        dsth[i] = __floats2half2_rn(s0, s1);
    }
}

// ---------------------------------------------------------------------------
// GEMM mainloops: 512 threads, 16 warps (4M x 4N), warp tile 32x32.
// ---------------------------------------------------------------------------
constexpr int TG_THR = 512;
constexpr int TG_SMEM1 = 128 * 132 * 4;                 // tf32 A only
constexpr int ASH_OFF = 128 * 132;                      // float offset of fp16 A
constexpr int TG_SMEMK = 128 * 132 * 4 + 128 * 136 * 2; // tf32 A + fp16 A

__device__ __forceinline__ void gemm_tile(
        const uint32_t* Asu, const float* __restrict__ Bf,
        int warpM, int warpN, int lane, float acc[2][4][4])
{
#pragma unroll
    for (int mt = 0; mt < 2; ++mt)
#pragma unroll
        for (int nt = 0; nt < 4; ++nt)
#pragma unroll
            for (int i = 0; i < 4; ++i) acc[mt][nt][i] = 0.f;
#pragma unroll
    for (int ks = 0; ks < 16; ++ks) {
        uint2 bv[4];
#pragma unroll
        for (int nt = 0; nt < 4; ++nt) {
            int ntA = warpN * 4 + nt;
            bv[nt] = __ldg((const uint2*)(Bf + ((ntA * 16 + ks) * 32 + lane) * 2));
        }
        uint32_t a[2][4];
#pragma unroll
        for (int mt = 0; mt < 2; ++mt) {
            int rb = warpM * 32 + mt * 16 + (lane >> 2);
            int cb = ks * 8 + (lane & 3);
            a[mt][0] = Asu[rb * 132 + cb];
            a[mt][1] = Asu[(rb + 8) * 132 + cb];
            a[mt][2] = Asu[rb * 132 + cb + 4];
            a[mt][3] = Asu[(rb + 8) * 132 + cb + 4];
        }
#pragma unroll
        for (int nt = 0; nt < 4; ++nt)
#pragma unroll
            for (int mt = 0; mt < 2; ++mt)
                MMA_TF32(acc[mt][nt], a[mt], bv[nt].x, bv[nt].y);
    }
}

// fp16: AshU = uint32 view of half A tile, stride 68 half2/row (136 halves).
__device__ __forceinline__ void gemm_tile_h(
        const uint32_t* AshU, const uint32_t* __restrict__ Bfh,
        int warpM, int warpN, int lane, float acc[2][4][4])
{
#pragma unroll
    for (int mt = 0; mt < 2; ++mt)
#pragma unroll
        for (int nt = 0; nt < 4; ++nt)
#pragma unroll
            for (int i = 0; i < 4; ++i) acc[mt][nt][i] = 0.f;
#pragma unroll
    for (int ks = 0; ks < 8; ++ks) {
        uint2 bv[4];
#pragma unroll
        for (int nt = 0; nt < 4; ++nt) {
            int ntA = warpN * 4 + nt;
            bv[nt] = __ldg((const uint2*)Bfh + ((ntA * 8 + ks) * 32 + lane));
        }
        uint32_t a[2][4];
#pragma unroll
        for (int mt = 0; mt < 2; ++mt) {
            int rb = warpM * 32 + mt * 16 + (lane >> 2);
            int cb = ks * 8 + (lane & 3);
            a[mt][0] = AshU[rb * 68 + cb];
            a[mt][1] = AshU[(rb + 8) * 68 + cb];
            a[mt][2] = AshU[rb * 68 + cb + 4];
            a[mt][3] = AshU[(rb + 8) * 68 + cb + 4];
        }
#pragma unroll
        for (int nt = 0; nt < 4; ++nt)
#pragma unroll
            for (int mt = 0; mt < 2; ++mt)
                MMA_F16(acc[mt][nt], a[mt], bv[nt].x, bv[nt].y);
    }
}

// ---------------------------------------------------------------------------
// tgemm1: single-output tf32 GEMM, merged type grid.
// PRE: 1=tanh-gelu, 2=embed(mean+relu).  POST: 1=relu, 2=skip blend.
// ---------------------------------------------------------------------------
template<int PRE, int POST>
__global__ void __launch_bounds__(TG_THR, 2) tgemm1(
        const float* __restrict__ A,
        const int* __restrict__ tok_s, const int* __restrict__ tok_f,
        const float* __restrict__ emb,
        const float* __restrict__ B0, const float* __restrict__ B1,
        const float* __restrict__ b0, const float* __restrict__ b1,
        const float* __restrict__ Xold,
        const float* __restrict__ skip0, const float* __restrict__ skip1,
        float* __restrict__ Out)
{
    extern __shared__ float sm[];
    float* As = sm;
    uint32_t* Asu = (uint32_t*)As;
    int tid = threadIdx.x, wid = tid >> 5, lane = tid & 31;
    int warpM = wid & 3, warpN = wid >> 2;
    int b = blockIdx.x;
    bool tf = (b >= kGridS);
    int rowBase = tf ? (kNStmt + (b - kGridS) * 128) : b * 128;
    int Nend = tf ? kNTot : kNStmt;
    const float* Bf = tf ? B1 : B0;
    const float* bs = tf ? b1 : b0;

#pragma unroll 2
    for (int p = 0; p < 8; ++p) {
        int idx = p * TG_THR + tid;
        int r = idx >> 5, c4 = idx & 31;
        int n = rowBase + r;
        float4 v = make_float4(0.f, 0.f, 0.f, 0.f);
        if (n < Nend) {
            if (PRE == 2) {
                const int* tok = tf ? tok_f + (size_t)(n - kNStmt) * 16
                                    : tok_s + (size_t)n * 16;
#pragma unroll
                for (int i = 0; i < 16; ++i) {
                    int t = __ldg(&tok[i]);
                    float4 e4 = __ldg((const float4*)(emb + (size_t)t * 128) + c4);
                    v.x += e4.x; v.y += e4.y; v.z += e4.z; v.w += e4.w;
                }
                v.x = fmaxf(v.x * (1.f / 16.f), 0.f);
                v.y = fmaxf(v.y * (1.f / 16.f), 0.f);
                v.z = fmaxf(v.z * (1.f / 16.f), 0.f);
                v.w = fmaxf(v.w * (1.f / 16.f), 0.f);
            } else {
                v = __ldg((const float4*)(A + (size_t)n * 128 + c4 * 4));
                if (PRE == 1) {
                    v.x = gelu_t(v.x); v.y = gelu_t(v.y);
                    v.z = gelu_t(v.z); v.w = gelu_t(v.w);
                }
            }
        }
        v.x = totf32(v.x); v.y = totf32(v.y); v.z = totf32(v.z); v.w = totf32(v.w);
        *(float4*)&As[r * 132 + c4 * 4] = v;
    }
    __syncthreads();

    float gate = 1.f, og = 0.f;
    if (POST == 2) {
        float sv = __ldg(tf ? skip1 : skip0);
        gate = 1.f / (1.f + expf(-sv));
        og = 1.f - gate;
    }

    float acc[2][4][4];
    gemm_tile(Asu, Bf, warpM, warpN, lane, acc);

    int g = lane >> 2, t2 = (lane & 3) * 2;
#pragma unroll
    for (int mt = 0; mt < 2; ++mt) {
        int r0 = rowBase + warpM * 32 + mt * 16 + g;
#pragma unroll
        for (int nt = 0; nt < 4; ++nt) {
            int col = warpN * 32 + nt * 8 + t2;
            float bb0 = __ldg(&bs[col]), bb1 = __ldg(&bs[col + 1]);
            float o0 = acc[mt][nt][0] + bb0, o1 = acc[mt][nt][1] + bb1;
            float o2 = acc[mt][nt][2] + bb0, o3 = acc[mt][nt][3] + bb1;
            if (POST == 1) {
                o0 = fmaxf(o0, 0.f); o1 = fmaxf(o1, 0.f);
                o2 = fmaxf(o2, 0.f); o3 = fmaxf(o3, 0.f);
            }
            if (POST == 2) {
                if (r0 < Nend) {
                    float2 x = *(const float2*)(Xold + (size_t)r0 * 128 + col);
                    o0 = gate * o0 + og * x.x; o1 = gate * o1 + og * x.y;
                }
                if (r0 + 8 < Nend) {
                    float2 x = *(const float2*)(Xold + (size_t)(r0 + 8) * 128 + col);
                    o2 = gate * o2 + og * x.x; o3 = gate * o3 + og * x.y;
                }
            }
            if (r0 < Nend)
                *(float2*)(Out + (size_t)r0 * 128 + col) = make_float2(o0, o1);
            if (r0 + 8 < Nend)
                *(float2*)(Out + (size_t)(r0 + 8) * 128 + col) = make_float2(o2, o3);
        }
    }
}

// ---------------------------------------------------------------------------
// tgemm_kqv: fp16 outputs k,vA,vB (fp16 MMA) + tf32 outputs qa,qa2.
// func blocks skip vB and qa2.
// ---------------------------------------------------------------------------
struct KqvP {
    const uint32_t* Bh[2][3];    // fp16 frag weights: k, vA, vB
    const float*    Bq[2][2];    // tf32 frag weights: qa, qa2
    const float*    bh[2][3];
    const float*    bq[2][2];
};

__global__ void __launch_bounds__(TG_THR, 2) tgemm_kqv(
        const float* __restrict__ A, KqvP P,
        __half* __restrict__ Ok, __half* __restrict__ OvA, __half* __restrict__ OvB,
        float* __restrict__ Oqa, float* __restrict__ Oqa2)
{
    extern __shared__ float sm[];
    float* As = sm;
    uint32_t* Asu = (uint32_t*)As;
    uint32_t* AshU = (uint32_t*)(sm + ASH_OFF);   // fp16 tile, 68 half2/row
    __half2* Ash2 = (__half2*)AshU;
    int tid = threadIdx.x, wid = tid >> 5, lane = tid & 31;
    int warpM = wid & 3, warpN = wid >> 2;
    int b = blockIdx.x;
    bool tf = (b >= kGridS);
    int rowBase = tf ? (kNStmt + (b - kGridS) * 128) : b * 128;
    int Nend = tf ? kNTot : kNStmt;
    int ti = tf ? 1 : 0;

#pragma unroll 4
    for (int p = 0; p < 8; ++p) {
        int idx = p * TG_THR + tid;
        int r = idx >> 5, c4 = idx & 31;
        int n = rowBase + r;
        float4 v = make_float4(0.f, 0.f, 0.f, 0.f);
        if (n < Nend) v = __ldg((const float4*)(A + (size_t)n * 128 + c4 * 4));
        Ash2[r * 68 + c4 * 2]     = __floats2half2_rn(v.x, v.y);
        Ash2[r * 68 + c4 * 2 + 1] = __floats2half2_rn(v.z, v.w);
        v.x = totf32(v.x); v.y = totf32(v.y); v.z = totf32(v.z); v.w = totf32(v.w);
        *(float4*)&As[r * 132 + c4 * 4] = v;
    }
    __syncthreads();

    int g = lane >> 2, t2 = (lane & 3) * 2;

    // fp16 outputs: 0=k, 1=vA, 2=vB(stmt only)
#pragma unroll
    for (int j = 0; j < 3; ++j) {
        if (tf && j == 2) continue;
        float acc[2][4][4];
        gemm_tile_h(AshU, P.Bh[ti][j], warpM, warpN, lane, acc);
        const float* bs = P.bh[ti][j];
        __half* Oh = (j == 0) ? Ok : (j == 1) ? OvA : OvB;
#pragma unroll
        for (int mt = 0; mt < 2; ++mt) {
            int r0 = rowBase + warpM * 32 + mt * 16 + g;
#pragma unroll
            for (int nt = 0; nt < 4; ++nt) {
                int col = warpN * 32 + nt * 8 + t2;
                float bb0 = __ldg(&bs[col]), bb1 = __ldg(&bs[col + 1]);
                if (r0 < Nend)
                    *(__half2*)(Oh + (size_t)r0 * 128 + col) =
                        __floats2half2_rn(acc[mt][nt][0] + bb0, acc[mt][nt][1] + bb1);
                if (r0 + 8 < Nend)
                    *(__half2*)(Oh + (size_t)(r0 + 8) * 128 + col) =
                        __floats2half2_rn(acc[mt][nt][2] + bb0, acc[mt][nt][3] + bb1);
            }
        }
    }
    // tf32 outputs: 0=qa, 1=qa2(stmt only)
#pragma unroll
    for (int j = 0; j < 2; ++j) {
        if (tf && j == 1) continue;
        float acc[2][4][4];
        gemm_tile(Asu, P.Bq[ti][j], warpM, warpN, lane, acc);
        const float* bs = P.bq[ti][j];
        float* Of = (j == 0) ? Oqa : Oqa2;
#pragma unroll
        for (int mt = 0; mt < 2; ++mt) {
            int r0 = rowBase + warpM * 32 + mt * 16 + g;
#pragma unroll
            for (int nt = 0; nt < 4; ++nt) {
                int col = warpN * 32 + nt * 8 + t2;
                float bb0 = __ldg(&bs[col]), bb1 = __ldg(&bs[col + 1]);
                if (r0 < Nend)
                    *(float2*)(Of + (size_t)r0 * 128 + col) =
                        make_float2(acc[mt][nt][0] + bb0, acc[mt][nt][1] + bb1);
                if (r0 + 8 < Nend)
                    *(float2*)(Of + (size_t)(r0 + 8) * 128 + col) =
                        make_float2(acc[mt][nt][2] + bb0, acc[mt][nt][3] + bb1);
            }
        }
    }
}

// ---------------------------------------------------------------------------
// CSR build
// ---------------------------------------------------------------------------
__global__ void zero_int(int* __restrict__ p, int n) {
    int i = blockIdx.x * 256 + threadIdx.x;
    if (i < n) p[i] = 0;
}

__global__ void hist3(const int* __restrict__ d0, const int* __restrict__ d1,
                      const int* __restrict__ d2, int* __restrict__ cnt) {
    int r = blockIdx.y;
    const int* dst = (r == 0) ? d0 : (r == 1) ? d1 : d2;
    int off = (r == 0) ? 0 : (r == 1) ? kNStmt : kNStmt + kNFunc;
    int i = blockIdx.x * 256 + threadIdx.x;
    if (i < kE) atomicAdd(&cnt[off + __ldg(&dst[i])], 1);
}

__global__ void __launch_bounds__(1024) exscan3(const int* __restrict__ cnt,
                                                int* __restrict__ starts) {
    __shared__ int wsum[32];
    __shared__ int carry_s;
    const int cntOff[3] = {0, kNStmt, kNStmt + kNFunc};
    const int stOff[3]  = {0, kNStmt + 1, kNStmt + kNFunc + 2};
    const int ns[3]     = {kNStmt, kNFunc, kNStmt};
    int r = blockIdx.x;
    const int* c = cnt + cntOff[r];
    int* st = starts + stOff[r];
    int n = ns[r];
    int tid = threadIdx.x, lane = tid & 31, w = tid >> 5;
    if (tid == 0) carry_s = 0;
    __syncthreads();
    for (int base = 0; base < n; base += 1024) {
        int i = base + tid;
        int v = (i < n) ? c[i] : 0;
        int x = v;
#pragma unroll
        for (int o = 1; o < 32; o <<= 1) {
            int t = __shfl_up_sync(0xffffffffu, x, o);
            if (lane >= o) x += t;
        }
        if (lane == 31) wsum[w] = x;
        __syncthreads();
        if (w == 0) {
            int y = wsum[lane];
#pragma unroll
            for (int o = 1; o < 32; o <<= 1) {
                int t = __shfl_up_sync(0xffffffffu, y, o);
                if (lane >= o) y += t;
            }
            wsum[lane] = y;
        }
        __syncthreads();
        int incl = x + (w > 0 ? wsum[w - 1] : 0);
        int carry = carry_s;
        if (i < n) st[i] = carry + incl - v;
        __syncthreads();
        if (tid == 0) carry_s = carry + wsum[31];
        __syncthreads();
    }
    if (tid == 0) st[n] = carry_s;
}

__global__ void scat3(const int* __restrict__ s0, const int* __restrict__ d0,
                      const int* __restrict__ s1, const int* __restrict__ d1,
                      const int* __restrict__ s2, const int* __restrict__ d2,
                      const int* __restrict__ starts, int* __restrict__ cur,
                      int* __restrict__ out) {
    int r = blockIdx.y;
    const int* src = (r == 0) ? s0 : (r == 1) ? s1 : s2;
    const int* dst = (r == 0) ? d0 : (r == 1) ? d1 : d2;
    int cOff = (r == 0) ? 0 : (r == 1) ? kNStmt : kNStmt + kNFunc;
    int sOff = (r == 0) ? 0 : (r == 1) ? kNStmt + 1 : kNStmt + kNFunc + 2;
    int i = blockIdx.x * 256 + threadIdx.x;
    if (i < kE) {
        int d = __ldg(&dst[i]);
        int pos = __ldg(&starts[sOff + d]) + atomicAdd(&cur[cOff + d], 1);
        out[(size_t)r * kE + pos] = __ldg(&src[i]);
    }
}

// ---------------------------------------------------------------------------
// Attention: pure gather + online softmax. Warp per dst, lane = 4 channels.
// ---------------------------------------------------------------------------
__device__ __forceinline__ float4 attn_edges(
        int e0, int e1, int lane, float4 qa,
        const int* __restrict__ srcs,
        const __half* __restrict__ kb, const __half* __restrict__ vb)
{
    float m = -INFINITY, s = 0.f;
    float4 acc = make_float4(0.f, 0.f, 0.f, 0.f);
    if (e0 < e1) {
        int src = __ldg(&srcs[e0]);
        uint2 uk = __ldg((const uint2*)(kb + (size_t)src * 128) + lane);
        uint2 uv = __ldg((const uint2*)(vb + (size_t)src * 128) + lane);
        for (int e = e0; ; ) {
            int ne = e + 1;
            bool more = ne < e1;
            uint2 nuk, nuv;
            if (more) {
                int nsrc = __ldg(&srcs[ne]);
                nuk = __ldg((const uint2*)(kb + (size_t)nsrc * 128) + lane);
                nuv = __ldg((const uint2*)(vb + (size_t)nsrc * 128) + lane);
            }
            float2 k01 = __half22float2(*(__half2*)&uk.x);
            float2 k23 = __half22float2(*(__half2*)&uk.y);
            float2 v01 = __half22float2(*(__half2*)&uv.x);
            float2 v23 = __half22float2(*(__half2*)&uv.y);
            float lg = qa.x * k01.x + qa.y * k01.y + qa.z * k23.x + qa.w * k23.y;
            lg += __shfl_xor_sync(0xffffffffu, lg, 1);
            lg += __shfl_xor_sync(0xffffffffu, lg, 2);
            float nm = fmaxf(m, lg);
            float corr = __expf(m - nm);
            float p = __expf(lg - nm);
            s = s * corr + p;
            acc.x = acc.x * corr + p * v01.x;
            acc.y = acc.y * corr + p * v01.y;
            acc.z = acc.z * corr + p * v23.x;
            acc.w = acc.w * corr + p * v23.y;
            m = nm;
            if (!more) break;
            e = ne; uk = nuk; uv = nuv;
        }
    }
    float inv = 1.f / (s + 1e-16f);
    return make_float4(acc.x * inv, acc.y * inv, acc.z * inv, acc.w * inv);
}

constexpr int kAttnGridS = kNStmt / 8;   // 12500

__global__ void __launch_bounds__(256) attn_all(
        const float* __restrict__ qa, const float* __restrict__ qa2,
        const __half* __restrict__ kh, const __half* __restrict__ vA,
        const __half* __restrict__ vB,
        const int* __restrict__ st, const int* __restrict__ srt,
        float* __restrict__ agg)
{
    int tid = threadIdx.x, wid = tid >> 5, lane = tid & 31;
    int b = blockIdx.x;
    if (b < kAttnGridS) {
        int dn = b * 8 + wid;
        float4 q0 = __ldg((const float4*)(qa + (size_t)dn * 128) + lane);
        float4 r = attn_edges(__ldg(&st[dn]), __ldg(&st[dn + 1]), lane, q0,
                              srt, kh, vA);
        float4 q2 = __ldg((const float4*)(qa2 + (size_t)dn * 128) + lane);
        const int* st2 = st + (kNStmt + kNFunc + 2);
        float4 r2 = attn_edges(__ldg(&st2[dn]), __ldg(&st2[dn + 1]), lane, q2,
                               srt + 2 * kE,
                               kh + (size_t)kNStmt * 128, vA + (size_t)kNStmt * 128);
        r.x += r2.x; r.y += r2.y; r.z += r2.z; r.w += r2.w;
        ((float4*)(agg + (size_t)dn * 128))[lane] = r;
    } else {
        int dn = (b - kAttnGridS) * 8 + wid;
        const int* st1 = st + (kNStmt + 1);
        float4 q1 = __ldg((const float4*)(qa + (size_t)(kNStmt + dn) * 128) + lane);
        float4 r = attn_edges(__ldg(&st1[dn]), __ldg(&st1[dn + 1]), lane, q1,
                              srt + kE, kh, vB);
        ((float4*)(agg + (size_t)(kNStmt + dn) * 128))[lane] = r;
    }
}

// ---------------------------------------------------------------------------
// Orchestration
// ---------------------------------------------------------------------------
extern "C" void kernel_launch(void* const* d_in, const int* in_sizes, int n_in,
                              void* d_out, int out_size) {
    const int* tok_s = (const int*)d_in[0];
    const int* tok_f = (const int*)d_in[1];
    const int* e0s = (const int*)d_in[2], *e0d = (const int*)d_in[3];
    const int* e1s = (const int*)d_in[4], *e1d = (const int*)d_in[5];
    const int* e2s = (const int*)d_in[6], *e2d = (const int*)d_in[7];
    const float* emb   = (const float*)d_in[8];
    const float* lin_w = (const float*)d_in[9];
    const float* lin_b = (const float*)d_in[10];
    const float* kw = (const float*)d_in[11];
    const float* kb = (const float*)d_in[12];
    const float* qw = (const float*)d_in[13];
    const float* qb = (const float*)d_in[14];
    const float* vw = (const float*)d_in[15];
    const float* vb = (const float*)d_in[16];
    const float* aw = (const float*)d_in[17];
    const float* ab = (const float*)d_in[18];
    const float* skip  = (const float*)d_in[19];
    const float* a_rel = (const float*)d_in[20];
    const float* m_rel = (const float*)d_in[21];
    const float* p_rel = (const float*)d_in[22];
    float* out = (float*)d_out;

    float *px, *pqa, *pqa2, *pagg, *pwt, *ptb;
    __half *pkh, *pvA, *pvB, *pwth;
    int *ptmp, *pst, *psrt;
    cudaGetSymbolAddress((void**)&px,   g_x);
    cudaGetSymbolAddress((void**)&pqa,  g_qa);
    cudaGetSymbolAddress((void**)&pqa2, g_qa2);
    cudaGetSymbolAddress((void**)&pkh,  g_kh);
    cudaGetSymbolAddress((void**)&pvA,  g_vA);
    cudaGetSymbolAddress((void**)&pvB,  g_vB);
    cudaGetSymbolAddress((void**)&pagg, g_agg);
    cudaGetSymbolAddress((void**)&pwt,  g_wt);
    cudaGetSymbolAddress((void**)&pwth, g_wth);
    cudaGetSymbolAddress((void**)&ptb,  g_tb);
    cudaGetSymbolAddress((void**)&ptmp, g_tmp);
    cudaGetSymbolAddress((void**)&pst,  g_starts);
    cudaGetSymbolAddress((void**)&psrt, g_srt);

    cudaFuncSetAttribute(tgemm1<2,1>, cudaFuncAttributeMaxDynamicSharedMemorySize, TG_SMEM1);
    cudaFuncSetAttribute(tgemm1<1,2>, cudaFuncAttributeMaxDynamicSharedMemorySize, TG_SMEM1);
    cudaFuncSetAttribute(tgemm_kqv, cudaFuncAttributeMaxDynamicSharedMemorySize, TG_SMEMK);

    int egrid = (kE + 255) / 256;

    // CSR build
    zero_int<<<(500000 + 255) / 256, 256>>>(ptmp, 500000);
    hist3<<<dim3(egrid, 3), 256>>>(e0d, e1d, e2d, ptmp);
    exscan3<<<3, 1024>>>(ptmp, pst);
    scat3<<<dim3(egrid, 3), 256>>>(e0s, e0d, e1s, e1d, e2s, e2d,
                                   pst, ptmp + 250000, psrt);

    // Weight prep, then input linear with fused embed
    prep_mats<<<32, 256>>>(lin_w, kw, qw, vw, aw, a_rel, m_rel, p_rel, qb, vb,
                           pwt, pwth, ptb);
    tgemm1<2,1><<<kGridAll, TG_THR, TG_SMEM1>>>(
        nullptr, tok_s, tok_f, emb,
        pwt, pwt + 16384, lin_b, lin_b + 128,
        nullptr, nullptr, nullptr, px);

    const uint32_t* wth32 = (const uint32_t*)pwth;   // 8192 uint32 per matrix

    for (int l = 0; l < kL; ++l) {
        int m0 = l * 2, m1 = l * 2 + 1;
        size_t cs = 10 + (size_t)l * 6;

        KqvP P;
        // stmt: k(slot m0), vA=v0(4+l*3+0), vB=v1(4+l*3+1)
        P.Bh[0][0] = wth32 + (size_t)m0 * 8192;
        P.Bh[0][1] = wth32 + (size_t)(4 + l * 3 + 0) * 8192;
        P.Bh[0][2] = wth32 + (size_t)(4 + l * 3 + 1) * 8192;
        P.bh[0][0] = kb + m0 * 128;
        P.bh[0][1] = ptb + (l * 6 + 0) * 128;
        P.bh[0][2] = ptb + (l * 6 + 1) * 128;
        // func: k(slot m1), vA=v2(4+l*3+2)
        P.Bh[1][0] = wth32 + (size_t)m1 * 8192;
        P.Bh[1][1] = wth32 + (size_t)(4 + l * 3 + 2) * 8192;
        P.Bh[1][2] = nullptr;
        P.bh[1][0] = kb + m1 * 128;
        P.bh[1][1] = ptb + (l * 6 + 2) * 128;
        P.bh[1][2] = nullptr;
        // qa (tf32): stmt qa0, qa2; func qa1
        P.Bq[0][0] = pwt + (cs + 3) * 16384;
        P.Bq[0][1] = pwt + (cs + 4) * 16384;
        P.Bq[1][0] = pwt + (cs + 5) * 16384;
        P.Bq[1][1] = nullptr;
        P.bq[0][0] = ptb + (l * 6 + 3) * 128;
        P.bq[0][1] = ptb + (l * 6 + 4) * 128;
        P.bq[1][0] = ptb + (l * 6 + 5) * 128;
        P.bq[1][1] = nullptr;

        tgemm_kqv<<<kGridAll, TG_THR, TG_SMEMK>>>(px, P, pkh, pvA, pvB, pqa, pqa2);

        attn_all<<<kAttnGridS + kNFunc / 8, 256>>>(pqa, pqa2, pkh, pvA, pvB,
                                                   pst, psrt, pagg);

        float* dst = (l == kL - 1) ? out : px;
        tgemm1<1,2><<<kGridAll, TG_THR, TG_SMEM1>>>(
            pagg, nullptr, nullptr, nullptr,
            pwt + (size_t)(6 + m0) * 16384, pwt + (size_t)(6 + m1) * 16384,
            ab + m0 * 128, ab + m1 * 128,
            px, skip + m0, skip + m1, dst);
    }
}

// round 12
// speedup vs baseline: 4.1734x; 1.1117x over previous
#include <cuda_runtime.h>
#include <cuda_fp16.h>
#include <cstdint>

// ---------------------------------------------------------------------------
// HGT forward. Node layout: stmt rows [0,100000), func rows [100000,150000).
// Relation transforms folded into GEMM weights. Attention = pure CSR gather +
// online softmax. ALL GEMMs on fp16 m16n8k16 MMA with fp32 accumulate
// (fp16 mantissa == tf32 mantissa; measured rel_err invariant).
// ---------------------------------------------------------------------------
constexpr int kNStmt = 100000;
constexpr int kNFunc = 50000;
constexpr int kNTot  = 150000;
constexpr int kC = 128;
constexpr int kE = 200000;
constexpr int kL = 2;
constexpr int kGridS = (kNStmt + 127) / 128;            // 782
constexpr int kGridF = (kNFunc + 127) / 128;            // 391
constexpr int kGridAll = kGridS + kGridF;               // 1173

// Scratch (device globals: no allocation allowed)
__device__ float  g_x  [(size_t)kNTot * kC];
__device__ float  g_qa [(size_t)kNTot * kC];   // stmt: qa0, func: qa1
__device__ float  g_qa2[(size_t)kNStmt * kC];  // stmt: qa2
__device__ __half g_kh [(size_t)kNTot * kC];
__device__ __half g_vA [(size_t)kNTot * kC];   // stmt: v@M0, func: v@M2
__device__ __half g_vB [(size_t)kNStmt * kC];  // stmt: v@M1
__device__ float  g_agg[(size_t)kNTot * kC];
__device__ __half g_wth[(size_t)22 * 16384];   // fragment-ordered fp16 weights
__device__ float  g_tb [12 * 128];             // transformed biases
__device__ int    g_tmp[500000];               // cnt[250000] then cur[250000]
__device__ int    g_starts[250003];
__device__ int    g_srt[600000];

__device__ __forceinline__ float gelu_t(float u) {
    return 0.5f * u * (1.f + tanhf(0.7978845608028654f * (u + 0.044715f * u * u * u)));
}

#define MMA_F16(c, a, bv0, bv1) \
    asm volatile("mma.sync.aligned.m16n8k16.row.col.f32.f16.f16.f32 " \
        "{%0,%1,%2,%3}, {%4,%5,%6,%7}, {%8,%9}, {%0,%1,%2,%3};" \
        : "+f"((c)[0]), "+f"((c)[1]), "+f"((c)[2]), "+f"((c)[3]) \
        : "r"((a)[0]), "r"((a)[1]), "r"((a)[2]), "r"((a)[3]), "r"(bv0), "r"(bv1))

// ---------------------------------------------------------------------------
// prep_mats: build fragment-ordered fp16 weights (22 slots of 16384 halves):
//   0,1 = lin; 2-5 = kw(mi); 6-9 = aw(mi);
//   10+l*6+{0:v0,1:v1,2:v2,3:qa0,4:qa2,5:qa1} (relation-folded)
// fp16 frag (half2 idx i): reg=i&1, lane=(i>>1)&31, ks=(i>>6)&7, nt=i>>9;
//   k0 = ks*16+(lane&3)*2+reg*8 (pair k0,k0+1), n = nt*8+(lane>>2)
// v fold:  out[h,j] = sum_d W[.,h*16+d] * M[h,d,j]
// qa fold: out[h,j] = sum_d W[.,h*16+d] * A[h,j,d]   (scaled by p_rel*0.25)
// tb biases: c = l*6+idx, same folds applied to qb/vb.
// ---------------------------------------------------------------------------
__global__ void __launch_bounds__(256) prep_mats(
        const float* __restrict__ lin_w, const float* __restrict__ kw,
        const float* __restrict__ qw, const float* __restrict__ vw,
        const float* __restrict__ aw,
        const float* __restrict__ a_rel, const float* __restrict__ m_rel,
        const float* __restrict__ p_rel,
        const float* __restrict__ qb, const float* __restrict__ vb,
        __half* __restrict__ wth, float* __restrict__ tb)
{
    int b = blockIdx.x, tid = threadIdx.x;
    const int srcT[3] = {0, 0, 1}, dstT[3] = {0, 1, 0};
    __half2* dsth = (__half2*)(wth + (size_t)b * 16384);

    if (b < 10) {   // plain weights
        const float* W = (b < 2) ? lin_w + (size_t)b * 16384
                       : (b < 6) ? kw + (size_t)(b - 2) * 16384
                                 : aw + (size_t)(b - 6) * 16384;
        for (int i = tid; i < 8192; i += 256) {
            int reg = i & 1, lane = (i >> 1) & 31, ks = (i >> 6) & 7, nt = i >> 9;
            int k0 = ks * 16 + (lane & 3) * 2 + reg * 8;
            int n = nt * 8 + (lane >> 2);
            dsth[i] = __floats2half2_rn(__ldg(&W[k0 * 128 + n]),
                                        __ldg(&W[(k0 + 1) * 128 + n]));
        }
        return;
    }
    // folded weights
    int c = b - 10, l = c / 6, idx = c % 6;
    int rel = (idx < 3) ? idx : (idx == 3 ? 0 : (idx == 4 ? 2 : 1));
    bool isQA = (idx >= 3);
    const float* W  = isQA ? qw + (size_t)(l * 2 + dstT[rel]) * 16384
                           : vw + (size_t)(l * 2 + srcT[rel]) * 16384;
    const float* T  = (isQA ? a_rel : m_rel) + (size_t)(l * 3 + rel) * 2048;
    const float* Bi = isQA ? qb + (l * 2 + dstT[rel]) * 128
                           : vb + (l * 2 + srcT[rel]) * 128;
    __shared__ float Ts[2048];
    __shared__ float sc[8];
    for (int i = tid; i < 2048; i += 256) Ts[i] = __ldg(&T[i]);
    if (tid < 8) sc[tid] = isQA ? __ldg(&p_rel[(l * 3 + rel) * 8 + tid]) * 0.25f : 1.f;
    __syncthreads();
    for (int i = tid; i < 8192; i += 256) {
        int reg = i & 1, lane = (i >> 1) & 31, ks = (i >> 6) & 7, nt = i >> 9;
        int k0 = ks * 16 + (lane & 3) * 2 + reg * 8;
        int n = nt * 8 + (lane >> 2);
        int h = n >> 4, j = n & 15;
        float s0 = 0.f, s1 = 0.f;
        if (isQA) {
#pragma unroll
            for (int d = 0; d < 16; ++d) {
                float t = Ts[h * 256 + j * 16 + d];
                s0 += __ldg(&W[k0 * 128 + h * 16 + d]) * t;
                s1 += __ldg(&W[(k0 + 1) * 128 + h * 16 + d]) * t;
            }
        } else {
#pragma unroll
            for (int d = 0; d < 16; ++d) {
                float t = Ts[h * 256 + d * 16 + j];
                s0 += __ldg(&W[k0 * 128 + h * 16 + d]) * t;
                s1 += __ldg(&W[(k0 + 1) * 128 + h * 16 + d]) * t;
            }
        }
        dsth[i] = __floats2half2_rn(s0 * sc[h], s1 * sc[h]);
    }
    if (tid < 128) {
        int h = tid >> 4, j = tid & 15;
        float s = 0.f;
        if (isQA) {
#pragma unroll
            for (int d = 0; d < 16; ++d)
                s += __ldg(&Bi[h * 16 + d]) * Ts[h * 256 + j * 16 + d];
        } else {
#pragma unroll
            for (int d = 0; d < 16; ++d)
                s += __ldg(&Bi[h * 16 + d]) * Ts[h * 256 + d * 16 + j];
        }
        tb[c * 128 + tid] = s * sc[h];
    }
}

// ---------------------------------------------------------------------------
// fp16 GEMM mainloop: 512 threads, 16 warps (4M x 4N), warp tile 32x32.
// A tile in smem as fp16, 136 halves/row (68 uint32 stride).
// ---------------------------------------------------------------------------
constexpr int TG_THR = 512;
constexpr int TG_SMEMH = 128 * 136 * 2;   // 34816 B

__device__ __forceinline__ void gemm_tile_h(
        const uint32_t* AshU, const uint32_t* __restrict__ Bfh,
        int warpM, int warpN, int lane, float acc[2][4][4])
{
#pragma unroll
    for (int mt = 0; mt < 2; ++mt)
#pragma unroll
        for (int nt = 0; nt < 4; ++nt)
#pragma unroll
            for (int i = 0; i < 4; ++i) acc[mt][nt][i] = 0.f;
#pragma unroll
    for (int ks = 0; ks < 8; ++ks) {
        uint2 bv[4];
#pragma unroll
        for (int nt = 0; nt < 4; ++nt) {
            int ntA = warpN * 4 + nt;
            bv[nt] = __ldg((const uint2*)Bfh + ((ntA * 8 + ks) * 32 + lane));
        }
        uint32_t a[2][4];
#pragma unroll
        for (int mt = 0; mt < 2; ++mt) {
            int rb = warpM * 32 + mt * 16 + (lane >> 2);
            int cb = ks * 8 + (lane & 3);
            a[mt][0] = AshU[rb * 68 + cb];
            a[mt][1] = AshU[(rb + 8) * 68 + cb];
            a[mt][2] = AshU[rb * 68 + cb + 4];
            a[mt][3] = AshU[(rb + 8) * 68 + cb + 4];
        }
#pragma unroll
        for (int nt = 0; nt < 4; ++nt)
#pragma unroll
            for (int mt = 0; mt < 2; ++mt)
                MMA_F16(acc[mt][nt], a[mt], bv[nt].x, bv[nt].y);
    }
}

// ---------------------------------------------------------------------------
// tgemm1: single-output fp16 GEMM, merged type grid, fp32 output.
// PRE: 1=tanh-gelu, 2=embed(mean+relu).  POST: 1=relu, 2=skip blend.
// ---------------------------------------------------------------------------
template<int PRE, int POST>
__global__ void __launch_bounds__(TG_THR, 2) tgemm1(
        const float* __restrict__ A,
        const int* __restrict__ tok_s, const int* __restrict__ tok_f,
        const float* __restrict__ emb,
        const uint32_t* __restrict__ B0, const uint32_t* __restrict__ B1,
        const float* __restrict__ b0, const float* __restrict__ b1,
        const float* __restrict__ Xold,
        const float* __restrict__ skip0, const float* __restrict__ skip1,
        float* __restrict__ Out)
{
    extern __shared__ float sm[];
    uint32_t* AshU = (uint32_t*)sm;
    __half2* Ash2 = (__half2*)sm;
    int tid = threadIdx.x, wid = tid >> 5, lane = tid & 31;
    int warpM = wid & 3, warpN = wid >> 2;
    int b = blockIdx.x;
    bool tf = (b >= kGridS);
    int rowBase = tf ? (kNStmt + (b - kGridS) * 128) : b * 128;
    int Nend = tf ? kNTot : kNStmt;
    const uint32_t* Bf = tf ? B1 : B0;
    const float* bs = tf ? b1 : b0;

#pragma unroll 2
    for (int p = 0; p < 8; ++p) {
        int idx = p * TG_THR + tid;
        int r = idx >> 5, c4 = idx & 31;
        int n = rowBase + r;
        float4 v = make_float4(0.f, 0.f, 0.f, 0.f);
        if (n < Nend) {
            if (PRE == 2) {
                const int* tok = tf ? tok_f + (size_t)(n - kNStmt) * 16
                                    : tok_s + (size_t)n * 16;
#pragma unroll
                for (int i = 0; i < 16; ++i) {
                    int t = __ldg(&tok[i]);
                    float4 e4 = __ldg((const float4*)(emb + (size_t)t * 128) + c4);
                    v.x += e4.x; v.y += e4.y; v.z += e4.z; v.w += e4.w;
                }
                v.x = fmaxf(v.x * (1.f / 16.f), 0.f);
                v.y = fmaxf(v.y * (1.f / 16.f), 0.f);
                v.z = fmaxf(v.z * (1.f / 16.f), 0.f);
                v.w = fmaxf(v.w * (1.f / 16.f), 0.f);
            } else {
                v = __ldg((const float4*)(A + (size_t)n * 128 + c4 * 4));
                if (PRE == 1) {
                    v.x = gelu_t(v.x); v.y = gelu_t(v.y);
                    v.z = gelu_t(v.z); v.w = gelu_t(v.w);
                }
            }
        }
        Ash2[r * 68 + c4 * 2]     = __floats2half2_rn(v.x, v.y);
        Ash2[r * 68 + c4 * 2 + 1] = __floats2half2_rn(v.z, v.w);
    }
    __syncthreads();

    float gate = 1.f, og = 0.f;
    if (POST == 2) {
        float sv = __ldg(tf ? skip1 : skip0);
        gate = 1.f / (1.f + expf(-sv));
        og = 1.f - gate;
    }

    float acc[2][4][4];
    gemm_tile_h(AshU, Bf, warpM, warpN, lane, acc);

    int g = lane >> 2, t2 = (lane & 3) * 2;
#pragma unroll
    for (int mt = 0; mt < 2; ++mt) {
        int r0 = rowBase + warpM * 32 + mt * 16 + g;
#pragma unroll
        for (int nt = 0; nt < 4; ++nt) {
            int col = warpN * 32 + nt * 8 + t2;
            float bb0 = __ldg(&bs[col]), bb1 = __ldg(&bs[col + 1]);
            float o0 = acc[mt][nt][0] + bb0, o1 = acc[mt][nt][1] + bb1;
            float o2 = acc[mt][nt][2] + bb0, o3 = acc[mt][nt][3] + bb1;
            if (POST == 1) {
                o0 = fmaxf(o0, 0.f); o1 = fmaxf(o1, 0.f);
                o2 = fmaxf(o2, 0.f); o3 = fmaxf(o3, 0.f);
            }
            if (POST == 2) {
                if (r0 < Nend) {
                    float2 x = *(const float2*)(Xold + (size_t)r0 * 128 + col);
                    o0 = gate * o0 + og * x.x; o1 = gate * o1 + og * x.y;
                }
                if (r0 + 8 < Nend) {
                    float2 x = *(const float2*)(Xold + (size_t)(r0 + 8) * 128 + col);
                    o2 = gate * o2 + og * x.x; o3 = gate * o3 + og * x.y;
                }
            }
            if (r0 < Nend)
                *(float2*)(Out + (size_t)r0 * 128 + col) = make_float2(o0, o1);
            if (r0 + 8 < Nend)
                *(float2*)(Out + (size_t)(r0 + 8) * 128 + col) = make_float2(o2, o3);
        }
    }
}

// ---------------------------------------------------------------------------
// tgemm_kqv: 5 outputs. j: 0=k(h16) 1=vA(h16) 2=vB(h16,stmt) 3=qa(f32) 4=qa2(f32,stmt)
// All fp16 MMA. func blocks skip j=2,4.
// ---------------------------------------------------------------------------
struct KqvP {
    const uint32_t* B[2][5];
    const float*    bs[2][5];
};

__global__ void __launch_bounds__(TG_THR, 2) tgemm_kqv(
        const float* __restrict__ A, KqvP P,
        __half* __restrict__ Ok, __half* __restrict__ OvA, __half* __restrict__ OvB,
        float* __restrict__ Oqa, float* __restrict__ Oqa2)
{
    extern __shared__ float sm[];
    uint32_t* AshU = (uint32_t*)sm;
    __half2* Ash2 = (__half2*)sm;
    int tid = threadIdx.x, wid = tid >> 5, lane = tid & 31;
    int warpM = wid & 3, warpN = wid >> 2;
    int b = blockIdx.x;
    bool tf = (b >= kGridS);
    int rowBase = tf ? (kNStmt + (b - kGridS) * 128) : b * 128;
    int Nend = tf ? kNTot : kNStmt;
    int ti = tf ? 1 : 0;

#pragma unroll 4
    for (int p = 0; p < 8; ++p) {
        int idx = p * TG_THR + tid;
        int r = idx >> 5, c4 = idx & 31;
        int n = rowBase + r;
        float4 v = make_float4(0.f, 0.f, 0.f, 0.f);
        if (n < Nend) v = __ldg((const float4*)(A + (size_t)n * 128 + c4 * 4));
        Ash2[r * 68 + c4 * 2]     = __floats2half2_rn(v.x, v.y);
        Ash2[r * 68 + c4 * 2 + 1] = __floats2half2_rn(v.z, v.w);
    }
    __syncthreads();

    int g = lane >> 2, t2 = (lane & 3) * 2;
#pragma unroll
    for (int j = 0; j < 5; ++j) {
        if (tf && (j == 2 || j == 4)) continue;
        float acc[2][4][4];
        gemm_tile_h(AshU, P.B[ti][j], warpM, warpN, lane, acc);
        const float* bs = P.bs[ti][j];
#pragma unroll
        for (int mt = 0; mt < 2; ++mt) {
            int r0 = rowBase + warpM * 32 + mt * 16 + g;
#pragma unroll
            for (int nt = 0; nt < 4; ++nt) {
                int col = warpN * 32 + nt * 8 + t2;
                float bb0 = __ldg(&bs[col]), bb1 = __ldg(&bs[col + 1]);
                float o0 = acc[mt][nt][0] + bb0, o1 = acc[mt][nt][1] + bb1;
                float o2 = acc[mt][nt][2] + bb0, o3 = acc[mt][nt][3] + bb1;
                if (j < 3) {
                    __half* Oh = (j == 0) ? Ok : (j == 1) ? OvA : OvB;
                    if (r0 < Nend)
                        *(__half2*)(Oh + (size_t)r0 * 128 + col) = __floats2half2_rn(o0, o1);
                    if (r0 + 8 < Nend)
                        *(__half2*)(Oh + (size_t)(r0 + 8) * 128 + col) = __floats2half2_rn(o2, o3);
                } else {
                    float* Of = (j == 3) ? Oqa : Oqa2;
                    if (r0 < Nend)
                        *(float2*)(Of + (size_t)r0 * 128 + col) = make_float2(o0, o1);
                    if (r0 + 8 < Nend)
                        *(float2*)(Of + (size_t)(r0 + 8) * 128 + col) = make_float2(o2, o3);
                }
            }
        }
    }
}

// ---------------------------------------------------------------------------
// CSR build
// ---------------------------------------------------------------------------
__global__ void zero_int(int* __restrict__ p, int n) {
    int i = blockIdx.x * 256 + threadIdx.x;
    if (i < n) p[i] = 0;
}

__global__ void hist3(const int* __restrict__ d0, const int* __restrict__ d1,
                      const int* __restrict__ d2, int* __restrict__ cnt) {
    int r = blockIdx.y;
    const int* dst = (r == 0) ? d0 : (r == 1) ? d1 : d2;
    int off = (r == 0) ? 0 : (r == 1) ? kNStmt : kNStmt + kNFunc;
    int i = blockIdx.x * 256 + threadIdx.x;
    if (i < kE) atomicAdd(&cnt[off + __ldg(&dst[i])], 1);
}

__global__ void __launch_bounds__(1024) exscan3(const int* __restrict__ cnt,
                                                int* __restrict__ starts) {
    __shared__ int wsum[32];
    __shared__ int carry_s;
    const int cntOff[3] = {0, kNStmt, kNStmt + kNFunc};
    const int stOff[3]  = {0, kNStmt + 1, kNStmt + kNFunc + 2};
    const int ns[3]     = {kNStmt, kNFunc, kNStmt};
    int r = blockIdx.x;
    const int* c = cnt + cntOff[r];
    int* st = starts + stOff[r];
    int n = ns[r];
    int tid = threadIdx.x, lane = tid & 31, w = tid >> 5;
    if (tid == 0) carry_s = 0;
    __syncthreads();
    for (int base = 0; base < n; base += 1024) {
        int i = base + tid;
        int v = (i < n) ? c[i] : 0;
        int x = v;
#pragma unroll
        for (int o = 1; o < 32; o <<= 1) {
            int t = __shfl_up_sync(0xffffffffu, x, o);
            if (lane >= o) x += t;
        }
        if (lane == 31) wsum[w] = x;
        __syncthreads();
        if (w == 0) {
            int y = wsum[lane];
#pragma unroll
            for (int o = 1; o < 32; o <<= 1) {
                int t = __shfl_up_sync(0xffffffffu, y, o);
                if (lane >= o) y += t;
            }
            wsum[lane] = y;
        }
        __syncthreads();
        int incl = x + (w > 0 ? wsum[w - 1] : 0);
        int carry = carry_s;
        if (i < n) st[i] = carry + incl - v;
        __syncthreads();
        if (tid == 0) carry_s = carry + wsum[31];
        __syncthreads();
    }
    if (tid == 0) st[n] = carry_s;
}

__global__ void scat3(const int* __restrict__ s0, const int* __restrict__ d0,
                      const int* __restrict__ s1, const int* __restrict__ d1,
                      const int* __restrict__ s2, const int* __restrict__ d2,
                      const int* __restrict__ starts, int* __restrict__ cur,
                      int* __restrict__ out) {
    int r = blockIdx.y;
    const int* src = (r == 0) ? s0 : (r == 1) ? s1 : s2;
    const int* dst = (r == 0) ? d0 : (r == 1) ? d1 : d2;
    int cOff = (r == 0) ? 0 : (r == 1) ? kNStmt : kNStmt + kNFunc;
    int sOff = (r == 0) ? 0 : (r == 1) ? kNStmt + 1 : kNStmt + kNFunc + 2;
    int i = blockIdx.x * 256 + threadIdx.x;
    if (i < kE) {
        int d = __ldg(&dst[i]);
        int pos = __ldg(&starts[sOff + d]) + atomicAdd(&cur[cOff + d], 1);
        out[(size_t)r * kE + pos] = __ldg(&src[i]);
    }
}

// ---------------------------------------------------------------------------
// Attention: pure gather + online softmax. Warp per dst, lane = 4 channels.
// ---------------------------------------------------------------------------
__device__ __forceinline__ float4 attn_edges(
        int e0, int e1, int lane, float4 qa,
        const int* __restrict__ srcs,
        const __half* __restrict__ kb, const __half* __restrict__ vb)
{
    float m = -INFINITY, s = 0.f;
    float4 acc = make_float4(0.f, 0.f, 0.f, 0.f);
    if (e0 < e1) {
        int src = __ldg(&srcs[e0]);
        uint2 uk = __ldg((const uint2*)(kb + (size_t)src * 128) + lane);
        uint2 uv = __ldg((const uint2*)(vb + (size_t)src * 128) + lane);
        for (int e = e0; ; ) {
            int ne = e + 1;
            bool more = ne < e1;
            uint2 nuk, nuv;
            if (more) {
                int nsrc = __ldg(&srcs[ne]);
                nuk = __ldg((const uint2*)(kb + (size_t)nsrc * 128) + lane);
                nuv = __ldg((const uint2*)(vb + (size_t)nsrc * 128) + lane);
            }
            float2 k01 = __half22float2(*(__half2*)&uk.x);
            float2 k23 = __half22float2(*(__half2*)&uk.y);
            float2 v01 = __half22float2(*(__half2*)&uv.x);
            float2 v23 = __half22float2(*(__half2*)&uv.y);
            float lg = qa.x * k01.x + qa.y * k01.y + qa.z * k23.x + qa.w * k23.y;
            lg += __shfl_xor_sync(0xffffffffu, lg, 1);
            lg += __shfl_xor_sync(0xffffffffu, lg, 2);
            float nm = fmaxf(m, lg);
            float corr = __expf(m - nm);
            float p = __expf(lg - nm);
            s = s * corr + p;
            acc.x = acc.x * corr + p * v01.x;
            acc.y = acc.y * corr + p * v01.y;
            acc.z = acc.z * corr + p * v23.x;
            acc.w = acc.w * corr + p * v23.y;
            m = nm;
            if (!more) break;
            e = ne; uk = nuk; uv = nuv;
        }
    }
    float inv = 1.f / (s + 1e-16f);
    return make_float4(acc.x * inv, acc.y * inv, acc.z * inv, acc.w * inv);
}

constexpr int kAttnGridS = kNStmt / 8;   // 12500

__global__ void __launch_bounds__(256) attn_all(
        const float* __restrict__ qa, const float* __restrict__ qa2,
        const __half* __restrict__ kh, const __half* __restrict__ vA,
        const __half* __restrict__ vB,
        const int* __restrict__ st, const int* __restrict__ srt,
        float* __restrict__ agg)
{
    int tid = threadIdx.x, wid = tid >> 5, lane = tid & 31;
    int b = blockIdx.x;
    if (b < kAttnGridS) {
        int dn = b * 8 + wid;
        float4 q0 = __ldg((const float4*)(qa + (size_t)dn * 128) + lane);
        float4 r = attn_edges(__ldg(&st[dn]), __ldg(&st[dn + 1]), lane, q0,
                              srt, kh, vA);
        float4 q2 = __ldg((const float4*)(qa2 + (size_t)dn * 128) + lane);
        const int* st2 = st + (kNStmt + kNFunc + 2);
        float4 r2 = attn_edges(__ldg(&st2[dn]), __ldg(&st2[dn + 1]), lane, q2,
                               srt + 2 * kE,
                               kh + (size_t)kNStmt * 128, vA + (size_t)kNStmt * 128);
        r.x += r2.x; r.y += r2.y; r.z += r2.z; r.w += r2.w;
        ((float4*)(agg + (size_t)dn * 128))[lane] = r;
    } else {
        int dn = (b - kAttnGridS) * 8 + wid;
        const int* st1 = st + (kNStmt + 1);
        float4 q1 = __ldg((const float4*)(qa + (size_t)(kNStmt + dn) * 128) + lane);
        float4 r = attn_edges(__ldg(&st1[dn]), __ldg(&st1[dn + 1]), lane, q1,
                              srt + kE, kh, vB);
        ((float4*)(agg + (size_t)(kNStmt + dn) * 128))[lane] = r;
    }
}

// ---------------------------------------------------------------------------
// Orchestration
// ---------------------------------------------------------------------------
extern "C" void kernel_launch(void* const* d_in, const int* in_sizes, int n_in,
                              void* d_out, int out_size) {
    const int* tok_s = (const int*)d_in[0];
    const int* tok_f = (const int*)d_in[1];
    const int* e0s = (const int*)d_in[2], *e0d = (const int*)d_in[3];
    const int* e1s = (const int*)d_in[4], *e1d = (const int*)d_in[5];
    const int* e2s = (const int*)d_in[6], *e2d = (const int*)d_in[7];
    const float* emb   = (const float*)d_in[8];
    const float* lin_w = (const float*)d_in[9];
    const float* lin_b = (const float*)d_in[10];
    const float* kw = (const float*)d_in[11];
    const float* kb = (const float*)d_in[12];
    const float* qw = (const float*)d_in[13];
    const float* qb = (const float*)d_in[14];
    const float* vw = (const float*)d_in[15];
    const float* vb = (const float*)d_in[16];
    const float* aw = (const float*)d_in[17];
    const float* ab = (const float*)d_in[18];
    const float* skip  = (const float*)d_in[19];
    const float* a_rel = (const float*)d_in[20];
    const float* m_rel = (const float*)d_in[21];
    const float* p_rel = (const float*)d_in[22];
    float* out = (float*)d_out;

    float *px, *pqa, *pqa2, *pagg, *ptb;
    __half *pkh, *pvA, *pvB, *pwth;
    int *ptmp, *pst, *psrt;
    cudaGetSymbolAddress((void**)&px,   g_x);
    cudaGetSymbolAddress((void**)&pqa,  g_qa);
    cudaGetSymbolAddress((void**)&pqa2, g_qa2);
    cudaGetSymbolAddress((void**)&pkh,  g_kh);
    cudaGetSymbolAddress((void**)&pvA,  g_vA);
    cudaGetSymbolAddress((void**)&pvB,  g_vB);
    cudaGetSymbolAddress((void**)&pagg, g_agg);
    cudaGetSymbolAddress((void**)&pwth, g_wth);
    cudaGetSymbolAddress((void**)&ptb,  g_tb);
    cudaGetSymbolAddress((void**)&ptmp, g_tmp);
    cudaGetSymbolAddress((void**)&pst,  g_starts);
    cudaGetSymbolAddress((void**)&psrt, g_srt);

    cudaFuncSetAttribute(tgemm1<2,1>, cudaFuncAttributeMaxDynamicSharedMemorySize, TG_SMEMH);
    cudaFuncSetAttribute(tgemm1<1,2>, cudaFuncAttributeMaxDynamicSharedMemorySize, TG_SMEMH);
    cudaFuncSetAttribute(tgemm_kqv, cudaFuncAttributeMaxDynamicSharedMemorySize, TG_SMEMH);

    int egrid = (kE + 255) / 256;

    // CSR build
    zero_int<<<(500000 + 255) / 256, 256>>>(ptmp, 500000);
    hist3<<<dim3(egrid, 3), 256>>>(e0d, e1d, e2d, ptmp);
    exscan3<<<3, 1024>>>(ptmp, pst);
    scat3<<<dim3(egrid, 3), 256>>>(e0s, e0d, e1s, e1d, e2s, e2d,
                                   pst, ptmp + 250000, psrt);

    // Weight prep, then input linear with fused embed
    prep_mats<<<22, 256>>>(lin_w, kw, qw, vw, aw, a_rel, m_rel, p_rel, qb, vb,
                           pwth, ptb);

    const uint32_t* W = (const uint32_t*)pwth;   // 8192 uint32 per matrix
    tgemm1<2,1><<<kGridAll, TG_THR, TG_SMEMH>>>(
        nullptr, tok_s, tok_f, emb,
        W, W + 8192, lin_b, lin_b + 128,
        nullptr, nullptr, nullptr, px);

    for (int l = 0; l < kL; ++l) {
        int m0 = l * 2, m1 = l * 2 + 1;
        size_t fs = 10 + (size_t)l * 6;   // folded slot base

        KqvP P;
        // stmt: k(2+m0), vA=v0, vB=v1, qa=qa0, qa2
        P.B[0][0] = W + (size_t)(2 + m0) * 8192;
        P.B[0][1] = W + (fs + 0) * 8192;
        P.B[0][2] = W + (fs + 1) * 8192;
        P.B[0][3] = W + (fs + 3) * 8192;
        P.B[0][4] = W + (fs + 4) * 8192;
        P.bs[0][0] = kb + m0 * 128;
        P.bs[0][1] = ptb + (l * 6 + 0) * 128;
        P.bs[0][2] = ptb + (l * 6 + 1) * 128;
        P.bs[0][3] = ptb + (l * 6 + 3) * 128;
        P.bs[0][4] = ptb + (l * 6 + 4) * 128;
        // func: k(2+m1), vA=v2, qa=qa1
        P.B[1][0] = W + (size_t)(2 + m1) * 8192;
        P.B[1][1] = W + (fs + 2) * 8192;
        P.B[1][2] = nullptr;
        P.B[1][3] = W + (fs + 5) * 8192;
        P.B[1][4] = nullptr;
        P.bs[1][0] = kb + m1 * 128;
        P.bs[1][1] = ptb + (l * 6 + 2) * 128;
        P.bs[1][2] = nullptr;
        P.bs[1][3] = ptb + (l * 6 + 5) * 128;
        P.bs[1][4] = nullptr;

        tgemm_kqv<<<kGridAll, TG_THR, TG_SMEMH>>>(px, P, pkh, pvA, pvB, pqa, pqa2);

        attn_all<<<kAttnGridS + kNFunc / 8, 256>>>(pqa, pqa2, pkh, pvA, pvB,
                                                   pst, psrt, pagg);

        float* dst = (l == kL - 1) ? out : px;
        tgemm1<1,2><<<kGridAll, TG_THR, TG_SMEMH>>>(
            pagg, nullptr, nullptr, nullptr,
            W + (size_t)(6 + m0) * 8192, W + (size_t)(6 + m1) * 8192,
            ab + m0 * 128, ab + m1 * 128,
            px, skip + m0, skip + m1, dst);
    }
}